// round 6
// baseline (speedup 1.0000x reference)
#include <cuda_runtime.h>
#include <cuda_bf16.h>
#include <math.h>
#include <stdint.h>

#define T_ 2048
#define DIM_ 2048
#define NH 32
#define HD 64
#define QKVD 6144

// ---------------- scratch ----------------
__device__ float g_qkv[T_ * QKVD];
__device__ float g_tauq[T_ * NH];
__device__ float g_tauv[T_ * NH];
__device__ float g_taupart[8 * T_ * 64];
__device__ __nv_bfloat16 g_Ahi[T_ * DIM_];
__device__ __nv_bfloat16 g_Alo[T_ * DIM_];
__device__ __nv_bfloat16 g_Whi[QKVD * DIM_];
__device__ __nv_bfloat16 g_Wlo[QKVD * DIM_];
__device__ __nv_bfloat16 g_Ghi[T_ * QKVD];
__device__ __nv_bfloat16 g_Glo[T_ * QKVD];
__device__ __nv_bfloat16 g_Twhi[64 * QKVD];
__device__ __nv_bfloat16 g_Twlo[64 * QKVD];
__device__ __nv_bfloat16 g_Qhi[NH * T_ * HD];
__device__ __nv_bfloat16 g_Qlo[NH * T_ * HD];
__device__ __nv_bfloat16 g_Khi[NH * T_ * HD];
__device__ __nv_bfloat16 g_Klo[NH * T_ * HD];
__device__ __nv_bfloat16 g_Vhi[NH * T_ * HD];
__device__ __nv_bfloat16 g_Vlo[NH * T_ * HD];

// ================= helpers =================
__device__ __forceinline__ uint32_t smem_u32(const void* p) {
    uint32_t a;
    asm("{ .reg .u64 t; cvta.to.shared.u64 t, %1; cvt.u32.u64 %0, t; }" : "=r"(a) : "l"(p));
    return a;
}
__device__ __forceinline__ void ldsm4(uint32_t* r, uint32_t addr) {
    asm volatile("ldmatrix.sync.aligned.m8n8.x4.shared.b16 {%0,%1,%2,%3}, [%4];"
        : "=r"(r[0]), "=r"(r[1]), "=r"(r[2]), "=r"(r[3]) : "r"(addr));
}
__device__ __forceinline__ void ldsm4t(uint32_t* r, uint32_t addr) {
    asm volatile("ldmatrix.sync.aligned.m8n8.x4.trans.shared.b16 {%0,%1,%2,%3}, [%4];"
        : "=r"(r[0]), "=r"(r[1]), "=r"(r[2]), "=r"(r[3]) : "r"(addr));
}
__device__ __forceinline__ void mma16816(float* d, const uint32_t* a, const uint32_t* b) {
    asm volatile("mma.sync.aligned.m16n8k16.row.col.f32.bf16.bf16.f32 "
        "{%0,%1,%2,%3}, {%4,%5,%6,%7}, {%8,%9}, {%0,%1,%2,%3};"
        : "+f"(d[0]), "+f"(d[1]), "+f"(d[2]), "+f"(d[3])
        : "r"(a[0]), "r"(a[1]), "r"(a[2]), "r"(a[3]), "r"(b[0]), "r"(b[1]));
}
__device__ __forceinline__ void cp_async16(uint32_t dst, const void* src) {
    asm volatile("cp.async.cg.shared.global [%0], [%1], 16;" :: "r"(dst), "l"(src) : "memory");
}
#define CP_COMMIT() asm volatile("cp.async.commit_group;" ::: "memory")
#define CP_WAIT(n)  asm volatile("cp.async.wait_group %0;" :: "n"(n) : "memory")

__device__ __forceinline__ uint32_t pack_bf2(float lo, float hi) {
    __nv_bfloat162 t = __floats2bfloat162_rn(lo, hi);
    return *reinterpret_cast<uint32_t*>(&t);
}

// ================= split-bf16 decomposition =================
__global__ __launch_bounds__(256)
void decomp_kernel(const float* __restrict__ in, __nv_bfloat16* __restrict__ hi,
                   __nv_bfloat16* __restrict__ lo, int n4) {
    int i = blockIdx.x * 256 + threadIdx.x;
    if (i >= n4) return;
    float4 v = ((const float4*)in)[i];
    __nv_bfloat16 h0 = __float2bfloat16_rn(v.x);
    __nv_bfloat16 h1 = __float2bfloat16_rn(v.y);
    __nv_bfloat16 h2 = __float2bfloat16_rn(v.z);
    __nv_bfloat16 h3 = __float2bfloat16_rn(v.w);
    __nv_bfloat16 l0 = __float2bfloat16_rn(v.x - __bfloat162float(h0));
    __nv_bfloat16 l1 = __float2bfloat16_rn(v.y - __bfloat162float(h1));
    __nv_bfloat16 l2 = __float2bfloat16_rn(v.z - __bfloat162float(h2));
    __nv_bfloat16 l3 = __float2bfloat16_rn(v.w - __bfloat162float(h3));
    ((__nv_bfloat162*)hi)[i * 2 + 0] = __halves2bfloat162(h0, h1);
    ((__nv_bfloat162*)hi)[i * 2 + 1] = __halves2bfloat162(h2, h3);
    ((__nv_bfloat162*)lo)[i * 2 + 0] = __halves2bfloat162(l0, l1);
    ((__nv_bfloat162*)lo)[i * 2 + 1] = __halves2bfloat162(l2, l3);
}

// ================= HMMA split-bf16 GEMM, 64x32 warp tiles, 4-stage =================
#define MAT_BYTES  (128 * 80)
#define STAGE_BYTES (4 * MAT_BYTES)
#define GSMEM (4 * STAGE_BYTES)

__global__ __launch_bounds__(256)
void gemm_hmma_kernel(const __nv_bfloat16* __restrict__ Ahi, const __nv_bfloat16* __restrict__ Alo,
                      const __nv_bfloat16* __restrict__ Bhi, const __nv_bfloat16* __restrict__ Blo,
                      const float* __restrict__ bias, float* __restrict__ C,
                      __nv_bfloat16* __restrict__ Ghi, __nv_bfloat16* __restrict__ Glo,
                      int N, int K) {
    extern __shared__ char smem[];
    const uint32_t sbase = smem_u32(smem);
    const int tid = threadIdx.x;
    const int wid = tid >> 5;
    const int lane = tid & 31;
    const int wm = wid >> 2;
    const int wn = wid & 3;
    const int bx = blockIdx.x, by = blockIdx.y;
    const int nch = K / 32;

    const int lrow0 = tid >> 2;
    const int lc0 = tid & 3;

    float acc[4][4][4];
#pragma unroll
    for (int mt = 0; mt < 4; mt++)
#pragma unroll
        for (int nt = 0; nt < 4; nt++)
#pragma unroll
            for (int r = 0; r < 4; r++) acc[mt][nt][r] = 0.f;

    // load stage ci into buffer ci%4; always commits (empty group when oob)
    auto load_stage = [&](int ci) {
        if (ci < nch) {
            uint32_t st = sbase + (ci & 3) * STAGE_BYTES;
            int k0 = ci * 32;
#pragma unroll
            for (int it = 0; it < 2; it++) {
                int row = lrow0 + it * 64;
                uint32_t so = (uint32_t)row * 80 + lc0 * 16;
                size_t ga = ((size_t)(by * 128 + row) * K + k0 + lc0 * 8);
                size_t gb = ((size_t)(bx * 128 + row) * K + k0 + lc0 * 8);
                cp_async16(st + so,                 Ahi + ga);
                cp_async16(st + MAT_BYTES + so,     Alo + ga);
                cp_async16(st + 2 * MAT_BYTES + so, Bhi + gb);
                cp_async16(st + 3 * MAT_BYTES + so, Blo + gb);
            }
        }
        CP_COMMIT();
    };

    load_stage(0); load_stage(1); load_stage(2);

    for (int ci = 0; ci < nch; ci++) {
        CP_WAIT(2);                 // stage ci complete
        __syncthreads();            // all warps done with stage ci-1 (== buffer (ci+3)%4)
        load_stage(ci + 3);         // overlaps with compute below

        uint32_t st = sbase + (ci & 3) * STAGE_BYTES;
        uint32_t aHi = st, aLo = st + MAT_BYTES;
        uint32_t bHi = st + 2 * MAT_BYTES, bLo = st + 3 * MAT_BYTES;
        const int g = lane >> 3;

#pragma unroll
        for (int ks = 0; ks < 2; ks++) {
            uint32_t ah[4][4], al[4][4];
#pragma unroll
            for (int mt = 0; mt < 4; mt++) {
                uint32_t aoff = (uint32_t)(wm * 64 + mt * 16 + (lane & 15)) * 80
                                + ks * 32 + (lane >> 4) * 16;
                ldsm4(ah[mt], aHi + aoff);
                ldsm4(al[mt], aLo + aoff);
            }
            uint32_t bh[2][4], bl[2][4];
#pragma unroll
            for (int p = 0; p < 2; p++) {
                int row = wn * 32 + p * 16 + (g >> 1) * 8 + (lane & 7);
                uint32_t boff = (uint32_t)row * 80 + ks * 32 + (g & 1) * 16;
                ldsm4(bh[p], bHi + boff);
                ldsm4(bl[p], bLo + boff);
            }
#pragma unroll
            for (int mt = 0; mt < 4; mt++)
#pragma unroll
                for (int p = 0; p < 2; p++)
#pragma unroll
                    for (int pt = 0; pt < 2; pt++) {
                        int nt = p * 2 + pt;
                        mma16816(acc[mt][nt], ah[mt], &bh[p][pt * 2]);
                        mma16816(acc[mt][nt], al[mt], &bh[p][pt * 2]);
                        mma16816(acc[mt][nt], ah[mt], &bl[p][pt * 2]);
                    }
        }
    }

    const bool do_gelu = (Ghi != nullptr);
#pragma unroll
    for (int mt = 0; mt < 4; mt++) {
        int r0 = by * 128 + wm * 64 + mt * 16 + (lane >> 2);
#pragma unroll
        for (int nt = 0; nt < 4; nt++) {
            int c0 = bx * 128 + wn * 32 + nt * 8 + (lane & 3) * 2;
            float b0 = bias[c0], b1 = bias[c0 + 1];
#pragma unroll
            for (int rr = 0; rr < 2; rr++) {
                int r = r0 + rr * 8;
                float v0 = acc[mt][nt][rr * 2 + 0] + b0;
                float v1 = acc[mt][nt][rr * 2 + 1] + b1;
                *(float2*)&C[(size_t)r * N + c0] = make_float2(v0, v1);
                if (do_gelu) {
                    float g0 = 0.5f * v0 * (1.0f + erff(v0 * 0.70710678118654752f));
                    float g1 = 0.5f * v1 * (1.0f + erff(v1 * 0.70710678118654752f));
                    float h0 = __bfloat162float(__float2bfloat16_rn(g0));
                    float h1 = __bfloat162float(__float2bfloat16_rn(g1));
                    *(uint32_t*)&Ghi[(size_t)r * N + c0] = pack_bf2(h0, h1);
                    *(uint32_t*)&Glo[(size_t)r * N + c0] = pack_bf2(g0 - h0, g1 - h1);
                }
            }
        }
    }
}

// ================= tau: HMMA split-K GEMM, 4-stage =================
#define TAPL 10240
#define TBPL 5120
#define TSTAGE (2 * TAPL + 2 * TBPL)
#define TSMEM (4 * TSTAGE)

__global__ __launch_bounds__(256)
void tau_hmma_kernel(const __nv_bfloat16* __restrict__ Ghi, const __nv_bfloat16* __restrict__ Glo,
                     const __nv_bfloat16* __restrict__ Twhi, const __nv_bfloat16* __restrict__ Twlo,
                     float* __restrict__ part) {
    extern __shared__ char smem[];
    const uint32_t sbase = smem_u32(smem);
    const int tid = threadIdx.x;
    const int wid = tid >> 5;
    const int lane = tid & 31;
    const int wm = wid >> 1;
    const int wn = wid & 1;
    const int t0 = blockIdx.x * 128;
    const int kbase = blockIdx.y * 768;

    float acc[2][4][4];
#pragma unroll
    for (int mt = 0; mt < 2; mt++)
#pragma unroll
        for (int nt = 0; nt < 4; nt++)
#pragma unroll
            for (int r = 0; r < 4; r++) acc[mt][nt][r] = 0.f;

    auto load_stage = [&](int ci) {
        if (ci < 24) {
            uint32_t st = sbase + (ci & 3) * TSTAGE;
            int k0 = kbase + ci * 32;
#pragma unroll
            for (int i = 0; i < 6; i++) {
                int c = tid + i * 256;
                if (c < 1024) {
                    int pl = c >> 9, r = (c >> 2) & 127, k4 = c & 3;
                    cp_async16(st + pl * TAPL + (uint32_t)r * 80 + k4 * 16,
                               (pl ? Glo : Ghi) + (size_t)(t0 + r) * QKVD + k0 + k4 * 8);
                } else {
                    int c2 = c - 1024;
                    int pl = c2 >> 8, r = (c2 >> 2) & 63, k4 = c2 & 3;
                    cp_async16(st + 2 * TAPL + pl * TBPL + (uint32_t)r * 80 + k4 * 16,
                               (pl ? Twlo : Twhi) + (size_t)r * QKVD + k0 + k4 * 8);
                }
            }
        }
        CP_COMMIT();
    };

    load_stage(0); load_stage(1); load_stage(2);

    for (int ci = 0; ci < 24; ci++) {
        CP_WAIT(2);
        __syncthreads();
        load_stage(ci + 3);

        uint32_t st = sbase + (ci & 3) * TSTAGE;
        const int g = lane >> 3;
#pragma unroll
        for (int ks = 0; ks < 2; ks++) {
            uint32_t ah[2][4], al[2][4];
#pragma unroll
            for (int mt = 0; mt < 2; mt++) {
                uint32_t aoff = (uint32_t)(wm * 32 + mt * 16 + (lane & 15)) * 80
                                + ks * 32 + (lane >> 4) * 16;
                ldsm4(ah[mt], st + aoff);
                ldsm4(al[mt], st + TAPL + aoff);
            }
            uint32_t bh[2][4], bl[2][4];
#pragma unroll
            for (int p = 0; p < 2; p++) {
                int row = wn * 32 + p * 16 + (g >> 1) * 8 + (lane & 7);
                uint32_t boff = (uint32_t)row * 80 + ks * 32 + (g & 1) * 16;
                ldsm4(bh[p], st + 2 * TAPL + boff);
                ldsm4(bl[p], st + 2 * TAPL + TBPL + boff);
            }
#pragma unroll
            for (int mt = 0; mt < 2; mt++)
#pragma unroll
                for (int p = 0; p < 2; p++)
#pragma unroll
                    for (int pt = 0; pt < 2; pt++) {
                        int nt = p * 2 + pt;
                        mma16816(acc[mt][nt], ah[mt], &bh[p][pt * 2]);
                        mma16816(acc[mt][nt], al[mt], &bh[p][pt * 2]);
                        mma16816(acc[mt][nt], ah[mt], &bl[p][pt * 2]);
                    }
        }
    }

    float* pb = part + (size_t)blockIdx.y * T_ * 64;
#pragma unroll
    for (int mt = 0; mt < 2; mt++) {
        int r0 = t0 + wm * 32 + mt * 16 + (lane >> 2);
#pragma unroll
        for (int nt = 0; nt < 4; nt++) {
            int c0 = wn * 32 + nt * 8 + (lane & 3) * 2;
            *(float2*)&pb[(size_t)r0 * 64 + c0]       = make_float2(acc[mt][nt][0], acc[mt][nt][1]);
            *(float2*)&pb[(size_t)(r0 + 8) * 64 + c0] = make_float2(acc[mt][nt][2], acc[mt][nt][3]);
        }
    }
}

__global__ __launch_bounds__(256)
void tau_finish_kernel(const float* __restrict__ part, const float* __restrict__ alpha,
                       const int* __restrict__ positions,
                       float* __restrict__ tauq, float* __restrict__ tauv) {
    int idx = blockIdx.x * 256 + threadIdx.x;
    if (idx >= T_ * 64) return;
    int t = idx >> 6, o = idx & 63;
    float s = 0.f;
#pragma unroll
    for (int ks = 0; ks < 8; ks++) s += part[(size_t)ks * T_ * 64 + idx];
    int h = o & 31;
    float pl = logf(fmaxf((float)positions[t] + 1.0f, 1e-6f));
    float tp = 0.5f + 1.0f / (1.0f + expf(-alpha[h] * pl));
    float v = tanhf(s) + tp;
    if (o < 32) tauq[t * NH + h] = v;
    else        tauv[t * NH + h] = v;
}

// ================= prep =================
__global__ __launch_bounds__(256)
void prep_kernel(const float* __restrict__ qkv, const int* __restrict__ positions,
                 const float* __restrict__ tauq, const float* __restrict__ tauv,
                 __nv_bfloat16* __restrict__ Qhi, __nv_bfloat16* __restrict__ Qlo,
                 __nv_bfloat16* __restrict__ Khi, __nv_bfloat16* __restrict__ Klo,
                 __nv_bfloat16* __restrict__ Vhi, __nv_bfloat16* __restrict__ Vlo) {
    const int t = blockIdx.x;
    const float p = (float)positions[t];
    const float* row = qkv + (size_t)t * QKVD;

    for (int e = threadIdx.x; e < DIM_; e += 256) {
        int h = e >> 6;
        int d = e & 63;
        float tq = tauq[t * NH + h];
        float tv = tauv[t * NH + h];

        float qo = row[e] * tq;
        float ko = row[DIM_ + e];
        float vo = row[2 * DIM_ + e] * tv;

        if (d < 32) {
            int i = (d < 16) ? d : (d - 16);
            float ang = p * exp2f(-(float)i * 1.2457230355827609f);
            float s, c;
            sincosf(ang, &s, &c);
            if (d < 16) {
                float q2 = row[e + 16] * tq;
                float k2 = row[DIM_ + e + 16];
                qo = qo * c - q2 * s;
                ko = ko * c - k2 * s;
            } else {
                float q1 = row[e - 16] * tq;
                float k1 = row[DIM_ + e - 16];
                qo = qo * c + q1 * s;
                ko = ko * c + k1 * s;
            }
        }
        qo *= 0.125f;
        size_t o = (size_t)h * T_ * HD + (size_t)t * HD + d;
        __nv_bfloat16 qh = __float2bfloat16_rn(qo);
        __nv_bfloat16 kh = __float2bfloat16_rn(ko);
        __nv_bfloat16 vh = __float2bfloat16_rn(vo);
        Qhi[o] = qh; Qlo[o] = __float2bfloat16_rn(qo - __bfloat162float(qh));
        Khi[o] = kh; Klo[o] = __float2bfloat16_rn(ko - __bfloat162float(kh));
        Vhi[o] = vh; Vlo[o] = __float2bfloat16_rn(vo - __bfloat162float(vh));
    }
}

// ================= HMMA flash attention, 4-stage KV pipeline =================
#define FROW 144
#define FQL_OFF (128 * FROW)
#define FSTG0   (2 * 128 * FROW)
#define FSTG_BYTES (4 * 64 * FROW)
#define FKH 0
#define FKL (64 * FROW)
#define FVH (2 * 64 * FROW)
#define FVL (3 * 64 * FROW)
#define FLASH2_SMEM (FSTG0 + 4 * FSTG_BYTES)   // 184320

__global__ __launch_bounds__(256, 1)
void flash_hmma_kernel(const __nv_bfloat16* __restrict__ Qhi, const __nv_bfloat16* __restrict__ Qlo,
                       const __nv_bfloat16* __restrict__ Khi, const __nv_bfloat16* __restrict__ Klo,
                       const __nv_bfloat16* __restrict__ Vhi, const __nv_bfloat16* __restrict__ Vlo,
                       __nv_bfloat16* __restrict__ Ahi, __nv_bfloat16* __restrict__ Alo) {
    extern __shared__ char smem[];
    const uint32_t sb = smem_u32(smem);
    const int tid = threadIdx.x;
    const int wid = tid >> 5;
    const int lane = tid & 31;
    const int h = blockIdx.y;
    const int qt = (int)gridDim.x - 1 - (int)blockIdx.x;
    const int q0 = qt * 128;
    const size_t hb = (size_t)h * T_ * HD;
    const int nkt = 2 * qt + 2;

#pragma unroll
    for (int i = 0; i < 8; i++) {
        int c = tid + i * 256;
        int pl = c >> 10;
        int r = (c >> 3) & 127;
        int k8 = c & 7;
        const __nv_bfloat16* src = (pl ? Qlo : Qhi) + hb + (size_t)(q0 + r) * HD + k8 * 8;
        cp_async16(sb + pl * FQL_OFF + (uint32_t)r * FROW + k8 * 16, src);
    }
    CP_COMMIT();

    auto load_kv = [&](int kt) {
        if (kt < nkt) {
            uint32_t stg = sb + FSTG0 + (kt & 3) * FSTG_BYTES;
#pragma unroll
            for (int i = 0; i < 8; i++) {
                int c = tid + i * 256;
                int pl = c >> 9;
                int r = (c >> 3) & 63;
                int k8 = c & 7;
                const __nv_bfloat16* base =
                    (pl == 0) ? Khi : (pl == 1) ? Klo : (pl == 2) ? Vhi : Vlo;
                cp_async16(stg + pl * (64 * FROW) + (uint32_t)r * FROW + k8 * 16,
                           base + hb + (size_t)(kt * 64 + r) * HD + k8 * 8);
            }
        }
        CP_COMMIT();
    };
    load_kv(0); load_kv(1); load_kv(2);

    CP_WAIT(3);                // Q complete
    __syncthreads();

    uint32_t aqh[4][4], aql[4][4];
#pragma unroll
    for (int ks = 0; ks < 4; ks++) {
        uint32_t addr = sb + (uint32_t)(wid * 16 + (lane & 15)) * FROW + ks * 32 + (lane >> 4) * 16;
        ldsm4(aqh[ks], addr);
        ldsm4(aql[ks], addr + FQL_OFF);
    }

    float m0 = -1e30f, m1 = -1e30f, l0 = 0.f, l1 = 0.f;
    float O[8][4];
#pragma unroll
    for (int nf = 0; nf < 8; nf++)
#pragma unroll
        for (int c = 0; c < 4; c++) O[nf][c] = 0.f;

    for (int kt = 0; kt < nkt; kt++) {
        CP_WAIT(2);            // stage kt complete
        __syncthreads();       // all warps done with stage kt-1 (== buffer (kt+3)%4)
        load_kv(kt + 3);       // overlaps with compute

        const bool active = (kt * 64 <= q0 + wid * 16 + 15);
        const uint32_t stg = sb + FSTG0 + (kt & 3) * FSTG_BYTES;

        if (active) {
            float S[8][4];
#pragma unroll
            for (int nf = 0; nf < 8; nf++)
#pragma unroll
                for (int c = 0; c < 4; c++) S[nf][c] = 0.f;

#pragma unroll
            for (int ks = 0; ks < 4; ks++) {
                uint32_t bh[4][4], bl[4][4];
#pragma unroll
                for (int kp = 0; kp < 4; kp++) {
                    uint32_t ka = stg + (uint32_t)(kp * 16 + ((lane >> 4) << 3) + (lane & 7)) * FROW
                                  + ks * 32 + ((lane >> 3) & 1) * 16;
                    ldsm4(bh[kp], ka + FKH);
                    ldsm4(bl[kp], ka + FKL);
                }
#pragma unroll
                for (int kp = 0; kp < 4; kp++)
#pragma unroll
                    for (int half = 0; half < 2; half++) {
                        int nf = kp * 2 + half;
                        mma16816(S[nf], aqh[ks], &bh[kp][half * 2]);
                        mma16816(S[nf], aql[ks], &bh[kp][half * 2]);
                        mma16816(S[nf], aqh[ks], &bl[kp][half * 2]);
                    }
            }

            if (kt >= 2 * qt) {
                int rbase = q0 + wid * 16 + (lane >> 2);
                int cbase = kt * 64 + (lane & 3) * 2;
#pragma unroll
                for (int nf = 0; nf < 8; nf++)
#pragma unroll
                    for (int c = 0; c < 4; c++) {
                        int row = rbase + ((c >> 1) & 1) * 8;
                        int col = cbase + nf * 8 + (c & 1);
                        if (col > row) S[nf][c] = -1e30f;
                    }
            }

#pragma unroll
            for (int j = 0; j < 2; j++) {
                float& mj = j ? m1 : m0;
                float& lj = j ? l1 : l0;
                float rm = -1e30f;
#pragma unroll
                for (int nf = 0; nf < 8; nf++) {
                    rm = fmaxf(rm, S[nf][2 * j]);
                    rm = fmaxf(rm, S[nf][2 * j + 1]);
                }
                rm = fmaxf(rm, __shfl_xor_sync(0xffffffffu, rm, 1));
                rm = fmaxf(rm, __shfl_xor_sync(0xffffffffu, rm, 2));
                float mn = fmaxf(mj, rm);
                float alpha = __expf(mj - mn);
                float rs = 0.f;
#pragma unroll
                for (int nf = 0; nf < 8; nf++) {
                    float p0 = __expf(S[nf][2 * j] - mn);
                    float p1 = __expf(S[nf][2 * j + 1] - mn);
                    S[nf][2 * j] = p0; S[nf][2 * j + 1] = p1;
                    rs += p0 + p1;
                }
                rs += __shfl_xor_sync(0xffffffffu, rs, 1);
                rs += __shfl_xor_sync(0xffffffffu, rs, 2);
                lj = lj * alpha + rs;
                mj = mn;
#pragma unroll
                for (int nf = 0; nf < 8; nf++) {
                    O[nf][2 * j] *= alpha;
                    O[nf][2 * j + 1] *= alpha;
                }
            }

#pragma unroll
            for (int ks = 0; ks < 4; ks++) {
                uint32_t ah[4], al[4];
#pragma unroll
                for (int q = 0; q < 4; q++) {
                    int sf = 2 * ks + (q >> 1);
                    int c0 = (q & 1) * 2;
                    float p0 = S[sf][c0], p1 = S[sf][c0 + 1];
                    float h0 = __bfloat162float(__float2bfloat16_rn(p0));
                    float h1 = __bfloat162float(__float2bfloat16_rn(p1));
                    ah[q] = pack_bf2(h0, h1);
                    al[q] = pack_bf2(p0 - h0, p1 - h1);
                }
#pragma unroll
                for (int dp = 0; dp < 4; dp++) {
                    uint32_t va = stg + (uint32_t)(ks * 16 + ((lane >> 3) & 1) * 8 + (lane & 7)) * FROW
                                  + dp * 32 + (lane >> 4) * 16;
                    uint32_t vh[4], vl[4];
                    ldsm4t(vh, va + FVH);
                    ldsm4t(vl, va + FVL);
                    mma16816(O[2 * dp],     ah, &vh[0]);
                    mma16816(O[2 * dp],     al, &vh[0]);
                    mma16816(O[2 * dp],     ah, &vl[0]);
                    mma16816(O[2 * dp + 1], ah, &vh[2]);
                    mma16816(O[2 * dp + 1], al, &vh[2]);
                    mma16816(O[2 * dp + 1], ah, &vl[2]);
                }
            }
        }
    }

    float inv0 = 1.0f / l0;
    float inv1 = 1.0f / l1;
    int r0 = q0 + wid * 16 + (lane >> 2);
#pragma unroll
    for (int nf = 0; nf < 8; nf++)
#pragma unroll
        for (int j = 0; j < 2; j++) {
            float inv = j ? inv1 : inv0;
            float v0 = O[nf][2 * j] * inv;
            float v1 = O[nf][2 * j + 1] * inv;
            int t = r0 + j * 8;
            int col = h * 64 + nf * 8 + (lane & 3) * 2;
            float h0 = __bfloat162float(__float2bfloat16_rn(v0));
            float h1 = __bfloat162float(__float2bfloat16_rn(v1));
            *(uint32_t*)&Ahi[(size_t)t * DIM_ + col] = pack_bf2(h0, h1);
            *(uint32_t*)&Alo[(size_t)t * DIM_ + col] = pack_bf2(v0 - h0, v1 - h1);
        }
}

// ================= host launch =================
extern "C" void kernel_launch(void* const* d_in, const int* in_sizes, int n_in,
                              void* d_out, int out_size) {
    const int*   positions = (const int*)d_in[0];
    const float* hidden    = (const float*)d_in[1];
    const float* Wqkv      = (const float*)d_in[2];
    const float* bqkv      = (const float*)d_in[3];
    const float* Wout      = (const float*)d_in[4];
    const float* bout      = (const float*)d_in[5];
    const float* tau_alpha = (const float*)d_in[6];
    const float* tau_wq    = (const float*)d_in[7];
    const float* tau_wv    = (const float*)d_in[8];
    float* out = (float*)d_out;

    float *qkv, *tauq, *tauv, *taupart;
    __nv_bfloat16 *Ahi, *Alo, *Whi, *Wlo, *Ghi, *Glo, *Twhi, *Twlo;
    __nv_bfloat16 *Qhi, *Qlo, *Khi, *Klo, *Vhi, *Vlo;
    cudaGetSymbolAddress((void**)&qkv,     g_qkv);
    cudaGetSymbolAddress((void**)&tauq,    g_tauq);
    cudaGetSymbolAddress((void**)&tauv,    g_tauv);
    cudaGetSymbolAddress((void**)&taupart, g_taupart);
    cudaGetSymbolAddress((void**)&Ahi,     g_Ahi);
    cudaGetSymbolAddress((void**)&Alo,     g_Alo);
    cudaGetSymbolAddress((void**)&Whi,     g_Whi);
    cudaGetSymbolAddress((void**)&Wlo,     g_Wlo);
    cudaGetSymbolAddress((void**)&Ghi,     g_Ghi);
    cudaGetSymbolAddress((void**)&Glo,     g_Glo);
    cudaGetSymbolAddress((void**)&Twhi,    g_Twhi);
    cudaGetSymbolAddress((void**)&Twlo,    g_Twlo);
    cudaGetSymbolAddress((void**)&Qhi,     g_Qhi);
    cudaGetSymbolAddress((void**)&Qlo,     g_Qlo);
    cudaGetSymbolAddress((void**)&Khi,     g_Khi);
    cudaGetSymbolAddress((void**)&Klo,     g_Klo);
    cudaGetSymbolAddress((void**)&Vhi,     g_Vhi);
    cudaGetSymbolAddress((void**)&Vlo,     g_Vlo);

    cudaFuncSetAttribute(gemm_hmma_kernel, cudaFuncAttributeMaxDynamicSharedMemorySize, GSMEM);
    cudaFuncSetAttribute(tau_hmma_kernel, cudaFuncAttributeMaxDynamicSharedMemorySize, TSMEM);
    cudaFuncSetAttribute(flash_hmma_kernel, cudaFuncAttributeMaxDynamicSharedMemorySize, FLASH2_SMEM);

    decomp_kernel<<<(T_ * DIM_ / 4 + 255) / 256, 256>>>(hidden, Ahi, Alo, T_ * DIM_ / 4);
    decomp_kernel<<<(QKVD * DIM_ / 4 + 255) / 256, 256>>>(Wqkv, Whi, Wlo, QKVD * DIM_ / 4);
    decomp_kernel<<<(32 * QKVD / 4 + 255) / 256, 256>>>(tau_wq, Twhi, Twlo, 32 * QKVD / 4);
    decomp_kernel<<<(32 * QKVD / 4 + 255) / 256, 256>>>(tau_wv, Twhi + 32 * QKVD, Twlo + 32 * QKVD, 32 * QKVD / 4);
    gemm_hmma_kernel<<<dim3(QKVD / 128, T_ / 128), 256, GSMEM>>>(
        Ahi, Alo, Whi, Wlo, bqkv, qkv, Ghi, Glo, QKVD, DIM_);
    tau_hmma_kernel<<<dim3(T_ / 128, 8), 256, TSMEM>>>(Ghi, Glo, Twhi, Twlo, taupart);
    tau_finish_kernel<<<(T_ * 64 + 255) / 256, 256>>>(taupart, tau_alpha, positions, tauq, tauv);
    prep_kernel<<<T_, 256>>>(qkv, positions, tauq, tauv, Qhi, Qlo, Khi, Klo, Vhi, Vlo);
    flash_hmma_kernel<<<dim3(T_ / 128, NH), 256, FLASH2_SMEM>>>(
        Qhi, Qlo, Khi, Klo, Vhi, Vlo, Ahi, Alo);
    decomp_kernel<<<(DIM_ * DIM_ / 4 + 255) / 256, 256>>>(Wout, Whi, Wlo, DIM_ * DIM_ / 4);
    gemm_hmma_kernel<<<dim3(DIM_ / 128, T_ / 128), 256, GSMEM>>>(
        Ahi, Alo, Whi, Wlo, bout, out, nullptr, nullptr, DIM_, DIM_);
}

// round 7
// speedup vs baseline: 1.0033x; 1.0033x over previous
#include <cuda_runtime.h>
#include <cuda_bf16.h>
#include <math.h>
#include <stdint.h>

#define T_ 2048
#define DIM_ 2048
#define NH 32
#define HD 64
#define QKVD 6144

// ---------------- scratch ----------------
__device__ float g_qkv[T_ * QKVD];
__device__ float g_tauq[T_ * NH];
__device__ float g_tauv[T_ * NH];
__device__ float g_taupart[8 * T_ * 64];
__device__ __nv_bfloat16 g_Ahi[T_ * DIM_];
__device__ __nv_bfloat16 g_Alo[T_ * DIM_];
__device__ __nv_bfloat16 g_Whi[QKVD * DIM_];
__device__ __nv_bfloat16 g_Wlo[QKVD * DIM_];
__device__ __nv_bfloat16 g_Ghi[T_ * QKVD];
__device__ __nv_bfloat16 g_Glo[T_ * QKVD];
__device__ __nv_bfloat16 g_Twhi[64 * QKVD];
__device__ __nv_bfloat16 g_Twlo[64 * QKVD];
__device__ __nv_bfloat16 g_Qhi[NH * T_ * HD];
__device__ __nv_bfloat16 g_Qlo[NH * T_ * HD];
__device__ __nv_bfloat16 g_Khi[NH * T_ * HD];
__device__ __nv_bfloat16 g_Klo[NH * T_ * HD];
__device__ __nv_bfloat16 g_Vhi[NH * T_ * HD];
__device__ __nv_bfloat16 g_Vlo[NH * T_ * HD];

// ================= helpers =================
__device__ __forceinline__ uint32_t smem_u32(const void* p) {
    uint32_t a;
    asm("{ .reg .u64 t; cvta.to.shared.u64 t, %1; cvt.u32.u64 %0, t; }" : "=r"(a) : "l"(p));
    return a;
}
__device__ __forceinline__ void ldsm4(uint32_t* r, uint32_t addr) {
    asm volatile("ldmatrix.sync.aligned.m8n8.x4.shared.b16 {%0,%1,%2,%3}, [%4];"
        : "=r"(r[0]), "=r"(r[1]), "=r"(r[2]), "=r"(r[3]) : "r"(addr));
}
__device__ __forceinline__ void ldsm4t(uint32_t* r, uint32_t addr) {
    asm volatile("ldmatrix.sync.aligned.m8n8.x4.trans.shared.b16 {%0,%1,%2,%3}, [%4];"
        : "=r"(r[0]), "=r"(r[1]), "=r"(r[2]), "=r"(r[3]) : "r"(addr));
}
__device__ __forceinline__ void mma16816(float* d, const uint32_t* a, const uint32_t* b) {
    asm volatile("mma.sync.aligned.m16n8k16.row.col.f32.bf16.bf16.f32 "
        "{%0,%1,%2,%3}, {%4,%5,%6,%7}, {%8,%9}, {%0,%1,%2,%3};"
        : "+f"(d[0]), "+f"(d[1]), "+f"(d[2]), "+f"(d[3])
        : "r"(a[0]), "r"(a[1]), "r"(a[2]), "r"(a[3]), "r"(b[0]), "r"(b[1]));
}
__device__ __forceinline__ void cp_async16(uint32_t dst, const void* src) {
    asm volatile("cp.async.cg.shared.global [%0], [%1], 16;" :: "r"(dst), "l"(src) : "memory");
}
#define CP_COMMIT() asm volatile("cp.async.commit_group;" ::: "memory")
#define CP_WAIT(n)  asm volatile("cp.async.wait_group %0;" :: "n"(n) : "memory")

__device__ __forceinline__ uint32_t pack_bf2(float lo, float hi) {
    __nv_bfloat162 t = __floats2bfloat162_rn(lo, hi);
    return *reinterpret_cast<uint32_t*>(&t);
}

// ================= split-bf16 decomposition =================
__global__ __launch_bounds__(256)
void decomp_kernel(const float* __restrict__ in, __nv_bfloat16* __restrict__ hi,
                   __nv_bfloat16* __restrict__ lo, int n4) {
    int i = blockIdx.x * 256 + threadIdx.x;
    if (i >= n4) return;
    float4 v = ((const float4*)in)[i];
    __nv_bfloat16 h0 = __float2bfloat16_rn(v.x);
    __nv_bfloat16 h1 = __float2bfloat16_rn(v.y);
    __nv_bfloat16 h2 = __float2bfloat16_rn(v.z);
    __nv_bfloat16 h3 = __float2bfloat16_rn(v.w);
    __nv_bfloat16 l0 = __float2bfloat16_rn(v.x - __bfloat162float(h0));
    __nv_bfloat16 l1 = __float2bfloat16_rn(v.y - __bfloat162float(h1));
    __nv_bfloat16 l2 = __float2bfloat16_rn(v.z - __bfloat162float(h2));
    __nv_bfloat16 l3 = __float2bfloat16_rn(v.w - __bfloat162float(h3));
    ((__nv_bfloat162*)hi)[i * 2 + 0] = __halves2bfloat162(h0, h1);
    ((__nv_bfloat162*)hi)[i * 2 + 1] = __halves2bfloat162(h2, h3);
    ((__nv_bfloat162*)lo)[i * 2 + 0] = __halves2bfloat162(l0, l1);
    ((__nv_bfloat162*)lo)[i * 2 + 1] = __halves2bfloat162(l2, l3);
}

// ================= HMMA split-bf16 GEMM, 64x32 warp tiles, term-major MMA order =================
#define MAT_BYTES  (128 * 80)
#define STAGE_BYTES (4 * MAT_BYTES)
#define GSMEM (4 * STAGE_BYTES)

__global__ __launch_bounds__(256)
void gemm_hmma_kernel(const __nv_bfloat16* __restrict__ Ahi, const __nv_bfloat16* __restrict__ Alo,
                      const __nv_bfloat16* __restrict__ Bhi, const __nv_bfloat16* __restrict__ Blo,
                      const float* __restrict__ bias, float* __restrict__ C,
                      __nv_bfloat16* __restrict__ Ghi, __nv_bfloat16* __restrict__ Glo,
                      int N, int K) {
    extern __shared__ char smem[];
    const uint32_t sbase = smem_u32(smem);
    const int tid = threadIdx.x;
    const int wid = tid >> 5;
    const int lane = tid & 31;
    const int wm = wid >> 2;
    const int wn = wid & 3;
    const int bx = blockIdx.x, by = blockIdx.y;
    const int nch = K / 32;

    const int lrow0 = tid >> 2;
    const int lc0 = tid & 3;

    float acc[4][4][4];
#pragma unroll
    for (int mt = 0; mt < 4; mt++)
#pragma unroll
        for (int nt = 0; nt < 4; nt++)
#pragma unroll
            for (int r = 0; r < 4; r++) acc[mt][nt][r] = 0.f;

    auto load_stage = [&](int ci) {
        if (ci < nch) {
            uint32_t st = sbase + (ci & 3) * STAGE_BYTES;
            int k0 = ci * 32;
#pragma unroll
            for (int it = 0; it < 2; it++) {
                int row = lrow0 + it * 64;
                uint32_t so = (uint32_t)row * 80 + lc0 * 16;
                size_t ga = ((size_t)(by * 128 + row) * K + k0 + lc0 * 8);
                size_t gb = ((size_t)(bx * 128 + row) * K + k0 + lc0 * 8);
                cp_async16(st + so,                 Ahi + ga);
                cp_async16(st + MAT_BYTES + so,     Alo + ga);
                cp_async16(st + 2 * MAT_BYTES + so, Bhi + gb);
                cp_async16(st + 3 * MAT_BYTES + so, Blo + gb);
            }
        }
        CP_COMMIT();
    };

    load_stage(0); load_stage(1); load_stage(2);

    for (int ci = 0; ci < nch; ci++) {
        CP_WAIT(2);
        __syncthreads();
        load_stage(ci + 3);

        uint32_t st = sbase + (ci & 3) * STAGE_BYTES;
        uint32_t aHi = st, aLo = st + MAT_BYTES;
        uint32_t bHi = st + 2 * MAT_BYTES, bLo = st + 3 * MAT_BYTES;
        const int g = lane >> 3;

#pragma unroll
        for (int ks = 0; ks < 2; ks++) {
            uint32_t ah[4][4], al[4][4];
#pragma unroll
            for (int mt = 0; mt < 4; mt++) {
                uint32_t aoff = (uint32_t)(wm * 64 + mt * 16 + (lane & 15)) * 80
                                + ks * 32 + (lane >> 4) * 16;
                ldsm4(ah[mt], aHi + aoff);
                ldsm4(al[mt], aLo + aoff);
            }
            uint32_t bh[2][4], bl[2][4];
#pragma unroll
            for (int p = 0; p < 2; p++) {
                int row = wn * 32 + p * 16 + (g >> 1) * 8 + (lane & 7);
                uint32_t boff = (uint32_t)row * 80 + ks * 32 + (g & 1) * 16;
                ldsm4(bh[p], bHi + boff);
                ldsm4(bl[p], bLo + boff);
            }
            // term-major: 16 independent MMAs per term (no acc RAW chains)
#pragma unroll
            for (int mt = 0; mt < 4; mt++)
#pragma unroll
                for (int p = 0; p < 2; p++)
#pragma unroll
                    for (int pt = 0; pt < 2; pt++)
                        mma16816(acc[mt][p * 2 + pt], ah[mt], &bh[p][pt * 2]);
#pragma unroll
            for (int mt = 0; mt < 4; mt++)
#pragma unroll
                for (int p = 0; p < 2; p++)
#pragma unroll
                    for (int pt = 0; pt < 2; pt++)
                        mma16816(acc[mt][p * 2 + pt], al[mt], &bh[p][pt * 2]);
#pragma unroll
            for (int mt = 0; mt < 4; mt++)
#pragma unroll
                for (int p = 0; p < 2; p++)
#pragma unroll
                    for (int pt = 0; pt < 2; pt++)
                        mma16816(acc[mt][p * 2 + pt], ah[mt], &bl[p][pt * 2]);
        }
    }

    const bool do_gelu = (Ghi != nullptr);
#pragma unroll
    for (int mt = 0; mt < 4; mt++) {
        int r0 = by * 128 + wm * 64 + mt * 16 + (lane >> 2);
#pragma unroll
        for (int nt = 0; nt < 4; nt++) {
            int c0 = bx * 128 + wn * 32 + nt * 8 + (lane & 3) * 2;
            float b0 = bias[c0], b1 = bias[c0 + 1];
#pragma unroll
            for (int rr = 0; rr < 2; rr++) {
                int r = r0 + rr * 8;
                float v0 = acc[mt][nt][rr * 2 + 0] + b0;
                float v1 = acc[mt][nt][rr * 2 + 1] + b1;
                *(float2*)&C[(size_t)r * N + c0] = make_float2(v0, v1);
                if (do_gelu) {
                    float g0 = 0.5f * v0 * (1.0f + erff(v0 * 0.70710678118654752f));
                    float g1 = 0.5f * v1 * (1.0f + erff(v1 * 0.70710678118654752f));
                    float h0 = __bfloat162float(__float2bfloat16_rn(g0));
                    float h1 = __bfloat162float(__float2bfloat16_rn(g1));
                    *(uint32_t*)&Ghi[(size_t)r * N + c0] = pack_bf2(h0, h1);
                    *(uint32_t*)&Glo[(size_t)r * N + c0] = pack_bf2(g0 - h0, g1 - h1);
                }
            }
        }
    }
}

// ================= tau: HMMA split-K GEMM, term-major =================
#define TAPL 10240
#define TBPL 5120
#define TSTAGE (2 * TAPL + 2 * TBPL)
#define TSMEM (4 * TSTAGE)

__global__ __launch_bounds__(256)
void tau_hmma_kernel(const __nv_bfloat16* __restrict__ Ghi, const __nv_bfloat16* __restrict__ Glo,
                     const __nv_bfloat16* __restrict__ Twhi, const __nv_bfloat16* __restrict__ Twlo,
                     float* __restrict__ part) {
    extern __shared__ char smem[];
    const uint32_t sbase = smem_u32(smem);
    const int tid = threadIdx.x;
    const int wid = tid >> 5;
    const int lane = tid & 31;
    const int wm = wid >> 1;
    const int wn = wid & 1;
    const int t0 = blockIdx.x * 128;
    const int kbase = blockIdx.y * 768;

    float acc[2][4][4];
#pragma unroll
    for (int mt = 0; mt < 2; mt++)
#pragma unroll
        for (int nt = 0; nt < 4; nt++)
#pragma unroll
            for (int r = 0; r < 4; r++) acc[mt][nt][r] = 0.f;

    auto load_stage = [&](int ci) {
        if (ci < 24) {
            uint32_t st = sbase + (ci & 3) * TSTAGE;
            int k0 = kbase + ci * 32;
#pragma unroll
            for (int i = 0; i < 6; i++) {
                int c = tid + i * 256;
                if (c < 1024) {
                    int pl = c >> 9, r = (c >> 2) & 127, k4 = c & 3;
                    cp_async16(st + pl * TAPL + (uint32_t)r * 80 + k4 * 16,
                               (pl ? Glo : Ghi) + (size_t)(t0 + r) * QKVD + k0 + k4 * 8);
                } else {
                    int c2 = c - 1024;
                    int pl = c2 >> 8, r = (c2 >> 2) & 63, k4 = c2 & 3;
                    cp_async16(st + 2 * TAPL + pl * TBPL + (uint32_t)r * 80 + k4 * 16,
                               (pl ? Twlo : Twhi) + (size_t)r * QKVD + k0 + k4 * 8);
                }
            }
        }
        CP_COMMIT();
    };

    load_stage(0); load_stage(1); load_stage(2);

    for (int ci = 0; ci < 24; ci++) {
        CP_WAIT(2);
        __syncthreads();
        load_stage(ci + 3);

        uint32_t st = sbase + (ci & 3) * TSTAGE;
        const int g = lane >> 3;
#pragma unroll
        for (int ks = 0; ks < 2; ks++) {
            uint32_t ah[2][4], al[2][4];
#pragma unroll
            for (int mt = 0; mt < 2; mt++) {
                uint32_t aoff = (uint32_t)(wm * 32 + mt * 16 + (lane & 15)) * 80
                                + ks * 32 + (lane >> 4) * 16;
                ldsm4(ah[mt], st + aoff);
                ldsm4(al[mt], st + TAPL + aoff);
            }
            uint32_t bh[2][4], bl[2][4];
#pragma unroll
            for (int p = 0; p < 2; p++) {
                int row = wn * 32 + p * 16 + (g >> 1) * 8 + (lane & 7);
                uint32_t boff = (uint32_t)row * 80 + ks * 32 + (g & 1) * 16;
                ldsm4(bh[p], st + 2 * TAPL + boff);
                ldsm4(bl[p], st + 2 * TAPL + TBPL + boff);
            }
#pragma unroll
            for (int mt = 0; mt < 2; mt++)
#pragma unroll
                for (int p = 0; p < 2; p++)
#pragma unroll
                    for (int pt = 0; pt < 2; pt++)
                        mma16816(acc[mt][p * 2 + pt], ah[mt], &bh[p][pt * 2]);
#pragma unroll
            for (int mt = 0; mt < 2; mt++)
#pragma unroll
                for (int p = 0; p < 2; p++)
#pragma unroll
                    for (int pt = 0; pt < 2; pt++)
                        mma16816(acc[mt][p * 2 + pt], al[mt], &bh[p][pt * 2]);
#pragma unroll
            for (int mt = 0; mt < 2; mt++)
#pragma unroll
                for (int p = 0; p < 2; p++)
#pragma unroll
                    for (int pt = 0; pt < 2; pt++)
                        mma16816(acc[mt][p * 2 + pt], ah[mt], &bl[p][pt * 2]);
        }
    }

    float* pb = part + (size_t)blockIdx.y * T_ * 64;
#pragma unroll
    for (int mt = 0; mt < 2; mt++) {
        int r0 = t0 + wm * 32 + mt * 16 + (lane >> 2);
#pragma unroll
        for (int nt = 0; nt < 4; nt++) {
            int c0 = wn * 32 + nt * 8 + (lane & 3) * 2;
            *(float2*)&pb[(size_t)r0 * 64 + c0]       = make_float2(acc[mt][nt][0], acc[mt][nt][1]);
            *(float2*)&pb[(size_t)(r0 + 8) * 64 + c0] = make_float2(acc[mt][nt][2], acc[mt][nt][3]);
        }
    }
}

__global__ __launch_bounds__(256)
void tau_finish_kernel(const float* __restrict__ part, const float* __restrict__ alpha,
                       const int* __restrict__ positions,
                       float* __restrict__ tauq, float* __restrict__ tauv) {
    int idx = blockIdx.x * 256 + threadIdx.x;
    if (idx >= T_ * 64) return;
    int t = idx >> 6, o = idx & 63;
    float s = 0.f;
#pragma unroll
    for (int ks = 0; ks < 8; ks++) s += part[(size_t)ks * T_ * 64 + idx];
    int h = o & 31;
    float pl = logf(fmaxf((float)positions[t] + 1.0f, 1e-6f));
    float tp = 0.5f + 1.0f / (1.0f + expf(-alpha[h] * pl));
    float v = tanhf(s) + tp;
    if (o < 32) tauq[t * NH + h] = v;
    else        tauv[t * NH + h] = v;
}

// ================= prep =================
__global__ __launch_bounds__(256)
void prep_kernel(const float* __restrict__ qkv, const int* __restrict__ positions,
                 const float* __restrict__ tauq, const float* __restrict__ tauv,
                 __nv_bfloat16* __restrict__ Qhi, __nv_bfloat16* __restrict__ Qlo,
                 __nv_bfloat16* __restrict__ Khi, __nv_bfloat16* __restrict__ Klo,
                 __nv_bfloat16* __restrict__ Vhi, __nv_bfloat16* __restrict__ Vlo) {
    const int t = blockIdx.x;
    const float p = (float)positions[t];
    const float* row = qkv + (size_t)t * QKVD;

    for (int e = threadIdx.x; e < DIM_; e += 256) {
        int h = e >> 6;
        int d = e & 63;
        float tq = tauq[t * NH + h];
        float tv = tauv[t * NH + h];

        float qo = row[e] * tq;
        float ko = row[DIM_ + e];
        float vo = row[2 * DIM_ + e] * tv;

        if (d < 32) {
            int i = (d < 16) ? d : (d - 16);
            float ang = p * exp2f(-(float)i * 1.2457230355827609f);
            float s, c;
            sincosf(ang, &s, &c);
            if (d < 16) {
                float q2 = row[e + 16] * tq;
                float k2 = row[DIM_ + e + 16];
                qo = qo * c - q2 * s;
                ko = ko * c - k2 * s;
            } else {
                float q1 = row[e - 16] * tq;
                float k1 = row[DIM_ + e - 16];
                qo = qo * c + q1 * s;
                ko = ko * c + k1 * s;
            }
        }
        qo *= 0.125f;
        size_t o = (size_t)h * T_ * HD + (size_t)t * HD + d;
        __nv_bfloat16 qh = __float2bfloat16_rn(qo);
        __nv_bfloat16 kh = __float2bfloat16_rn(ko);
        __nv_bfloat16 vh = __float2bfloat16_rn(vo);
        Qhi[o] = qh; Qlo[o] = __float2bfloat16_rn(qo - __bfloat162float(qh));
        Khi[o] = kh; Klo[o] = __float2bfloat16_rn(ko - __bfloat162float(kh));
        Vhi[o] = vh; Vlo[o] = __float2bfloat16_rn(vo - __bfloat162float(vh));
    }
}

// ================= HMMA flash attention, term-major MMA order =================
#define FROW 144
#define FQL_OFF (128 * FROW)
#define FSTG0   (2 * 128 * FROW)
#define FSTG_BYTES (4 * 64 * FROW)
#define FKH 0
#define FKL (64 * FROW)
#define FVH (2 * 64 * FROW)
#define FVL (3 * 64 * FROW)
#define FLASH2_SMEM (FSTG0 + 4 * FSTG_BYTES)

__global__ __launch_bounds__(256, 1)
void flash_hmma_kernel(const __nv_bfloat16* __restrict__ Qhi, const __nv_bfloat16* __restrict__ Qlo,
                       const __nv_bfloat16* __restrict__ Khi, const __nv_bfloat16* __restrict__ Klo,
                       const __nv_bfloat16* __restrict__ Vhi, const __nv_bfloat16* __restrict__ Vlo,
                       __nv_bfloat16* __restrict__ Ahi, __nv_bfloat16* __restrict__ Alo) {
    extern __shared__ char smem[];
    const uint32_t sb = smem_u32(smem);
    const int tid = threadIdx.x;
    const int wid = tid >> 5;
    const int lane = tid & 31;
    const int h = blockIdx.y;
    const int qt = (int)gridDim.x - 1 - (int)blockIdx.x;
    const int q0 = qt * 128;
    const size_t hb = (size_t)h * T_ * HD;
    const int nkt = 2 * qt + 2;

#pragma unroll
    for (int i = 0; i < 8; i++) {
        int c = tid + i * 256;
        int pl = c >> 10;
        int r = (c >> 3) & 127;
        int k8 = c & 7;
        const __nv_bfloat16* src = (pl ? Qlo : Qhi) + hb + (size_t)(q0 + r) * HD + k8 * 8;
        cp_async16(sb + pl * FQL_OFF + (uint32_t)r * FROW + k8 * 16, src);
    }
    CP_COMMIT();

    auto load_kv = [&](int kt) {
        if (kt < nkt) {
            uint32_t stg = sb + FSTG0 + (kt & 3) * FSTG_BYTES;
#pragma unroll
            for (int i = 0; i < 8; i++) {
                int c = tid + i * 256;
                int pl = c >> 9;
                int r = (c >> 3) & 63;
                int k8 = c & 7;
                const __nv_bfloat16* base =
                    (pl == 0) ? Khi : (pl == 1) ? Klo : (pl == 2) ? Vhi : Vlo;
                cp_async16(stg + pl * (64 * FROW) + (uint32_t)r * FROW + k8 * 16,
                           base + hb + (size_t)(kt * 64 + r) * HD + k8 * 8);
            }
        }
        CP_COMMIT();
    };
    load_kv(0); load_kv(1); load_kv(2);

    CP_WAIT(3);
    __syncthreads();

    uint32_t aqh[4][4], aql[4][4];
#pragma unroll
    for (int ks = 0; ks < 4; ks++) {
        uint32_t addr = sb + (uint32_t)(wid * 16 + (lane & 15)) * FROW + ks * 32 + (lane >> 4) * 16;
        ldsm4(aqh[ks], addr);
        ldsm4(aql[ks], addr + FQL_OFF);
    }

    float m0 = -1e30f, m1 = -1e30f, l0 = 0.f, l1 = 0.f;
    float O[8][4];
#pragma unroll
    for (int nf = 0; nf < 8; nf++)
#pragma unroll
        for (int c = 0; c < 4; c++) O[nf][c] = 0.f;

    for (int kt = 0; kt < nkt; kt++) {
        CP_WAIT(2);
        __syncthreads();
        load_kv(kt + 3);

        const bool active = (kt * 64 <= q0 + wid * 16 + 15);
        const uint32_t stg = sb + FSTG0 + (kt & 3) * FSTG_BYTES;

        if (active) {
            float S[8][4];
#pragma unroll
            for (int nf = 0; nf < 8; nf++)
#pragma unroll
                for (int c = 0; c < 4; c++) S[nf][c] = 0.f;

            // ---- S = Q K^T, term-major (8 independent MMAs per term) ----
#pragma unroll
            for (int ks = 0; ks < 4; ks++) {
                uint32_t bh[4][4], bl[4][4];
#pragma unroll
                for (int kp = 0; kp < 4; kp++) {
                    uint32_t ka = stg + (uint32_t)(kp * 16 + ((lane >> 4) << 3) + (lane & 7)) * FROW
                                  + ks * 32 + ((lane >> 3) & 1) * 16;
                    ldsm4(bh[kp], ka + FKH);
                    ldsm4(bl[kp], ka + FKL);
                }
#pragma unroll
                for (int kp = 0; kp < 4; kp++)
#pragma unroll
                    for (int half = 0; half < 2; half++)
                        mma16816(S[kp * 2 + half], aqh[ks], &bh[kp][half * 2]);
#pragma unroll
                for (int kp = 0; kp < 4; kp++)
#pragma unroll
                    for (int half = 0; half < 2; half++)
                        mma16816(S[kp * 2 + half], aql[ks], &bh[kp][half * 2]);
#pragma unroll
                for (int kp = 0; kp < 4; kp++)
#pragma unroll
                    for (int half = 0; half < 2; half++)
                        mma16816(S[kp * 2 + half], aqh[ks], &bl[kp][half * 2]);
            }

            if (kt >= 2 * qt) {
                int rbase = q0 + wid * 16 + (lane >> 2);
                int cbase = kt * 64 + (lane & 3) * 2;
#pragma unroll
                for (int nf = 0; nf < 8; nf++)
#pragma unroll
                    for (int c = 0; c < 4; c++) {
                        int row = rbase + ((c >> 1) & 1) * 8;
                        int col = cbase + nf * 8 + (c & 1);
                        if (col > row) S[nf][c] = -1e30f;
                    }
            }

#pragma unroll
            for (int j = 0; j < 2; j++) {
                float& mj = j ? m1 : m0;
                float& lj = j ? l1 : l0;
                float rm = -1e30f;
#pragma unroll
                for (int nf = 0; nf < 8; nf++) {
                    rm = fmaxf(rm, S[nf][2 * j]);
                    rm = fmaxf(rm, S[nf][2 * j + 1]);
                }
                rm = fmaxf(rm, __shfl_xor_sync(0xffffffffu, rm, 1));
                rm = fmaxf(rm, __shfl_xor_sync(0xffffffffu, rm, 2));
                float mn = fmaxf(mj, rm);
                float alpha = __expf(mj - mn);
                float rs = 0.f;
#pragma unroll
                for (int nf = 0; nf < 8; nf++) {
                    float p0 = __expf(S[nf][2 * j] - mn);
                    float p1 = __expf(S[nf][2 * j + 1] - mn);
                    S[nf][2 * j] = p0; S[nf][2 * j + 1] = p1;
                    rs += p0 + p1;
                }
                rs += __shfl_xor_sync(0xffffffffu, rs, 1);
                rs += __shfl_xor_sync(0xffffffffu, rs, 2);
                lj = lj * alpha + rs;
                mj = mn;
#pragma unroll
                for (int nf = 0; nf < 8; nf++) {
                    O[nf][2 * j] *= alpha;
                    O[nf][2 * j + 1] *= alpha;
                }
            }

            // ---- O += P V, term-major per ks (8 independent MMAs per term) ----
#pragma unroll
            for (int ks = 0; ks < 4; ks++) {
                uint32_t ah[4], al[4];
#pragma unroll
                for (int q = 0; q < 4; q++) {
                    int sf = 2 * ks + (q >> 1);
                    int c0 = (q & 1) * 2;
                    float p0 = S[sf][c0], p1 = S[sf][c0 + 1];
                    float h0 = __bfloat162float(__float2bfloat16_rn(p0));
                    float h1 = __bfloat162float(__float2bfloat16_rn(p1));
                    ah[q] = pack_bf2(h0, h1);
                    al[q] = pack_bf2(p0 - h0, p1 - h1);
                }
                uint32_t vh[4][4], vl[4][4];
#pragma unroll
                for (int dp = 0; dp < 4; dp++) {
                    uint32_t va = stg + (uint32_t)(ks * 16 + ((lane >> 3) & 1) * 8 + (lane & 7)) * FROW
                                  + dp * 32 + (lane >> 4) * 16;
                    ldsm4t(vh[dp], va + FVH);
                    ldsm4t(vl[dp], va + FVL);
                }
#pragma unroll
                for (int dp = 0; dp < 4; dp++) {
                    mma16816(O[2 * dp],     ah, &vh[dp][0]);
                    mma16816(O[2 * dp + 1], ah, &vh[dp][2]);
                }
#pragma unroll
                for (int dp = 0; dp < 4; dp++) {
                    mma16816(O[2 * dp],     al, &vh[dp][0]);
                    mma16816(O[2 * dp + 1], al, &vh[dp][2]);
                }
#pragma unroll
                for (int dp = 0; dp < 4; dp++) {
                    mma16816(O[2 * dp],     ah, &vl[dp][0]);
                    mma16816(O[2 * dp + 1], ah, &vl[dp][2]);
                }
            }
        }
    }

    float inv0 = 1.0f / l0;
    float inv1 = 1.0f / l1;
    int r0 = q0 + wid * 16 + (lane >> 2);
#pragma unroll
    for (int nf = 0; nf < 8; nf++)
#pragma unroll
        for (int j = 0; j < 2; j++) {
            float inv = j ? inv1 : inv0;
            float v0 = O[nf][2 * j] * inv;
            float v1 = O[nf][2 * j + 1] * inv;
            int t = r0 + j * 8;
            int col = h * 64 + nf * 8 + (lane & 3) * 2;
            float h0 = __bfloat162float(__float2bfloat16_rn(v0));
            float h1 = __bfloat162float(__float2bfloat16_rn(v1));
            *(uint32_t*)&Ahi[(size_t)t * DIM_ + col] = pack_bf2(h0, h1);
            *(uint32_t*)&Alo[(size_t)t * DIM_ + col] = pack_bf2(v0 - h0, v1 - h1);
        }
}

// ================= host launch =================
extern "C" void kernel_launch(void* const* d_in, const int* in_sizes, int n_in,
                              void* d_out, int out_size) {
    const int*   positions = (const int*)d_in[0];
    const float* hidden    = (const float*)d_in[1];
    const float* Wqkv      = (const float*)d_in[2];
    const float* bqkv      = (const float*)d_in[3];
    const float* Wout      = (const float*)d_in[4];
    const float* bout      = (const float*)d_in[5];
    const float* tau_alpha = (const float*)d_in[6];
    const float* tau_wq    = (const float*)d_in[7];
    const float* tau_wv    = (const float*)d_in[8];
    float* out = (float*)d_out;

    float *qkv, *tauq, *tauv, *taupart;
    __nv_bfloat16 *Ahi, *Alo, *Whi, *Wlo, *Ghi, *Glo, *Twhi, *Twlo;
    __nv_bfloat16 *Qhi, *Qlo, *Khi, *Klo, *Vhi, *Vlo;
    cudaGetSymbolAddress((void**)&qkv,     g_qkv);
    cudaGetSymbolAddress((void**)&tauq,    g_tauq);
    cudaGetSymbolAddress((void**)&tauv,    g_tauv);
    cudaGetSymbolAddress((void**)&taupart, g_taupart);
    cudaGetSymbolAddress((void**)&Ahi,     g_Ahi);
    cudaGetSymbolAddress((void**)&Alo,     g_Alo);
    cudaGetSymbolAddress((void**)&Whi,     g_Whi);
    cudaGetSymbolAddress((void**)&Wlo,     g_Wlo);
    cudaGetSymbolAddress((void**)&Ghi,     g_Ghi);
    cudaGetSymbolAddress((void**)&Glo,     g_Glo);
    cudaGetSymbolAddress((void**)&Twhi,    g_Twhi);
    cudaGetSymbolAddress((void**)&Twlo,    g_Twlo);
    cudaGetSymbolAddress((void**)&Qhi,     g_Qhi);
    cudaGetSymbolAddress((void**)&Qlo,     g_Qlo);
    cudaGetSymbolAddress((void**)&Khi,     g_Khi);
    cudaGetSymbolAddress((void**)&Klo,     g_Klo);
    cudaGetSymbolAddress((void**)&Vhi,     g_Vhi);
    cudaGetSymbolAddress((void**)&Vlo,     g_Vlo);

    cudaFuncSetAttribute(gemm_hmma_kernel, cudaFuncAttributeMaxDynamicSharedMemorySize, GSMEM);
    cudaFuncSetAttribute(tau_hmma_kernel, cudaFuncAttributeMaxDynamicSharedMemorySize, TSMEM);
    cudaFuncSetAttribute(flash_hmma_kernel, cudaFuncAttributeMaxDynamicSharedMemorySize, FLASH2_SMEM);

    decomp_kernel<<<(T_ * DIM_ / 4 + 255) / 256, 256>>>(hidden, Ahi, Alo, T_ * DIM_ / 4);
    decomp_kernel<<<(QKVD * DIM_ / 4 + 255) / 256, 256>>>(Wqkv, Whi, Wlo, QKVD * DIM_ / 4);
    decomp_kernel<<<(32 * QKVD / 4 + 255) / 256, 256>>>(tau_wq, Twhi, Twlo, 32 * QKVD / 4);
    decomp_kernel<<<(32 * QKVD / 4 + 255) / 256, 256>>>(tau_wv, Twhi + 32 * QKVD, Twlo + 32 * QKVD, 32 * QKVD / 4);
    gemm_hmma_kernel<<<dim3(QKVD / 128, T_ / 128), 256, GSMEM>>>(
        Ahi, Alo, Whi, Wlo, bqkv, qkv, Ghi, Glo, QKVD, DIM_);
    tau_hmma_kernel<<<dim3(T_ / 128, 8), 256, TSMEM>>>(Ghi, Glo, Twhi, Twlo, taupart);
    tau_finish_kernel<<<(T_ * 64 + 255) / 256, 256>>>(taupart, tau_alpha, positions, tauq, tauv);
    prep_kernel<<<T_, 256>>>(qkv, positions, tauq, tauv, Qhi, Qlo, Khi, Klo, Vhi, Vlo);
    flash_hmma_kernel<<<dim3(T_ / 128, NH), 256, FLASH2_SMEM>>>(
        Qhi, Qlo, Khi, Klo, Vhi, Vlo, Ahi, Alo);
    decomp_kernel<<<(DIM_ * DIM_ / 4 + 255) / 256, 256>>>(Wout, Whi, Wlo, DIM_ * DIM_ / 4);
    gemm_hmma_kernel<<<dim3(DIM_ / 128, T_ / 128), 256, GSMEM>>>(
        Ahi, Alo, Whi, Wlo, bout, out, nullptr, nullptr, DIM_, DIM_);
}

// round 9
// speedup vs baseline: 1.3713x; 1.3668x over previous
#include <cuda_runtime.h>
#include <cuda_fp16.h>
#include <math.h>
#include <stdint.h>

#define T_ 2048
#define DIM_ 2048
#define NH 32
#define HD 64
#define QKVD 6144

// ---------------- scratch ----------------
__device__ float g_qkv[T_ * QKVD];
__device__ float g_tauq[T_ * NH];
__device__ float g_tauv[T_ * NH];
__device__ float g_taupart[8 * T_ * 64];
__device__ __half g_Ahi[T_ * DIM_];      // hidden / attn hi plane (A operand)
__device__ __half g_Alo[T_ * DIM_];
__device__ __half g_Whi[QKVD * DIM_];    // Wqkv / Wout hi plane (B operand, lo dropped)
__device__ __half g_Ghi[T_ * QKVD];      // gelu(qkv) hi/lo (A operand of tau)
__device__ __half g_Glo[T_ * QKVD];
__device__ __half g_Twhi[64 * QKVD];     // stacked tau_wq/tau_wv hi plane
__device__ __half g_Qhi[NH * T_ * HD];
__device__ __half g_Qlo[NH * T_ * HD];
__device__ __half g_Khi[NH * T_ * HD];   // K hi only (B operand)
__device__ __half g_Vhi[NH * T_ * HD];   // V hi only (B operand)

// ================= helpers =================
__device__ __forceinline__ uint32_t smem_u32(const void* p) {
    uint32_t a;
    asm("{ .reg .u64 t; cvta.to.shared.u64 t, %1; cvt.u32.u64 %0, t; }" : "=r"(a) : "l"(p));
    return a;
}
__device__ __forceinline__ void ldsm4(uint32_t* r, uint32_t addr) {
    asm volatile("ldmatrix.sync.aligned.m8n8.x4.shared.b16 {%0,%1,%2,%3}, [%4];"
        : "=r"(r[0]), "=r"(r[1]), "=r"(r[2]), "=r"(r[3]) : "r"(addr));
}
__device__ __forceinline__ void ldsm4t(uint32_t* r, uint32_t addr) {
    asm volatile("ldmatrix.sync.aligned.m8n8.x4.trans.shared.b16 {%0,%1,%2,%3}, [%4];"
        : "=r"(r[0]), "=r"(r[1]), "=r"(r[2]), "=r"(r[3]) : "r"(addr));
}
__device__ __forceinline__ void mma16816(float* d, const uint32_t* a, const uint32_t* b) {
    asm volatile("mma.sync.aligned.m16n8k16.row.col.f32.f16.f16.f32 "
        "{%0,%1,%2,%3}, {%4,%5,%6,%7}, {%8,%9}, {%0,%1,%2,%3};"
        : "+f"(d[0]), "+f"(d[1]), "+f"(d[2]), "+f"(d[3])
        : "r"(a[0]), "r"(a[1]), "r"(a[2]), "r"(a[3]), "r"(b[0]), "r"(b[1]));
}
__device__ __forceinline__ void cp_async16(uint32_t dst, const void* src) {
    asm volatile("cp.async.cg.shared.global [%0], [%1], 16;" :: "r"(dst), "l"(src) : "memory");
}
#define CP_COMMIT() asm volatile("cp.async.commit_group;" ::: "memory")
#define CP_WAIT(n)  asm volatile("cp.async.wait_group %0;" :: "n"(n) : "memory")

__device__ __forceinline__ uint32_t pack_h2(float lo, float hi) {
    __half2 t = __floats2half2_rn(lo, hi);
    return *reinterpret_cast<uint32_t*>(&t);
}

// ================= split-fp16 decomposition (hi + lo) =================
__global__ __launch_bounds__(256)
void decomp_kernel(const float* __restrict__ in, __half* __restrict__ hi,
                   __half* __restrict__ lo, int n4) {
    int i = blockIdx.x * 256 + threadIdx.x;
    if (i >= n4) return;
    float4 v = ((const float4*)in)[i];
    __half h0 = __float2half_rn(v.x);
    __half h1 = __float2half_rn(v.y);
    __half h2 = __float2half_rn(v.z);
    __half h3 = __float2half_rn(v.w);
    ((__half2*)hi)[i * 2 + 0] = __halves2half2(h0, h1);
    ((__half2*)hi)[i * 2 + 1] = __halves2half2(h2, h3);
    ((__half2*)lo)[i * 2 + 0] = __floats2half2_rn(v.x - __half2float(h0), v.y - __half2float(h1));
    ((__half2*)lo)[i * 2 + 1] = __floats2half2_rn(v.z - __half2float(h2), v.w - __half2float(h3));
}

// hi-only decomposition (for B operands whose lo term is dropped)
__global__ __launch_bounds__(256)
void decomp1_kernel(const float* __restrict__ in, __half* __restrict__ hi, int n4) {
    int i = blockIdx.x * 256 + threadIdx.x;
    if (i >= n4) return;
    float4 v = ((const float4*)in)[i];
    ((__half2*)hi)[i * 2 + 0] = __floats2half2_rn(v.x, v.y);
    ((__half2*)hi)[i * 2 + 1] = __floats2half2_rn(v.z, v.w);
}

// ================= HMMA fp16 2-term GEMM, 64x32 warp tiles =================
// C = A@B^T + bias ; A = Ahi+Alo (2 planes), B = Bhi only.
#define MAT_BYTES  (128 * 80)
#define STAGE_BYTES (3 * MAT_BYTES)   // Ahi, Alo, Bhi
#define GSMEM (4 * STAGE_BYTES)       // 122880

__global__ __launch_bounds__(256)
void gemm_hmma_kernel(const __half* __restrict__ Ahi, const __half* __restrict__ Alo,
                      const __half* __restrict__ Bhi,
                      const float* __restrict__ bias, float* __restrict__ C,
                      __half* __restrict__ Ghi, __half* __restrict__ Glo,
                      int N, int K) {
    extern __shared__ char smem[];
    const uint32_t sbase = smem_u32(smem);
    const int tid = threadIdx.x;
    const int wid = tid >> 5;
    const int lane = tid & 31;
    const int wm = wid >> 2;
    const int wn = wid & 3;
    const int bx = blockIdx.x, by = blockIdx.y;
    const int nch = K / 32;

    float acc[4][4][4];
#pragma unroll
    for (int mt = 0; mt < 4; mt++)
#pragma unroll
        for (int nt = 0; nt < 4; nt++)
#pragma unroll
            for (int r = 0; r < 4; r++) acc[mt][nt][r] = 0.f;

    // 3 planes x 512 chunks = 1536 chunks, 6 per thread
    auto load_stage = [&](int ci) {
        if (ci < nch) {
            uint32_t st = sbase + (ci & 3) * STAGE_BYTES;
            int k0 = ci * 32;
#pragma unroll
            for (int i = 0; i < 6; i++) {
                int c = tid + i * 256;
                int pl = c / 512;            // 0=Ahi 1=Alo 2=Bhi
                int idx = c & 511;
                int row = idx >> 2, k4 = idx & 3;
                uint32_t so = (uint32_t)row * 80 + k4 * 16;
                if (pl == 0)
                    cp_async16(st + so, Ahi + (size_t)(by * 128 + row) * K + k0 + k4 * 8);
                else if (pl == 1)
                    cp_async16(st + MAT_BYTES + so, Alo + (size_t)(by * 128 + row) * K + k0 + k4 * 8);
                else
                    cp_async16(st + 2 * MAT_BYTES + so, Bhi + (size_t)(bx * 128 + row) * K + k0 + k4 * 8);
            }
        }
        CP_COMMIT();
    };

    load_stage(0); load_stage(1); load_stage(2);

    for (int ci = 0; ci < nch; ci++) {
        CP_WAIT(2);
        __syncthreads();
        load_stage(ci + 3);

        uint32_t st = sbase + (ci & 3) * STAGE_BYTES;
        uint32_t aHi = st, aLo = st + MAT_BYTES, bHi = st + 2 * MAT_BYTES;
        const int g = lane >> 3;

#pragma unroll
        for (int ks = 0; ks < 2; ks++) {
            uint32_t ah[4][4], al[4][4];
#pragma unroll
            for (int mt = 0; mt < 4; mt++) {
                uint32_t aoff = (uint32_t)(wm * 64 + mt * 16 + (lane & 15)) * 80
                                + ks * 32 + (lane >> 4) * 16;
                ldsm4(ah[mt], aHi + aoff);
                ldsm4(al[mt], aLo + aoff);
            }
            uint32_t bh[2][4];
#pragma unroll
            for (int p = 0; p < 2; p++) {
                int row = wn * 32 + p * 16 + (g >> 1) * 8 + (lane & 7);
                uint32_t boff = (uint32_t)row * 80 + ks * 32 + (g & 1) * 16;
                ldsm4(bh[p], bHi + boff);
            }
#pragma unroll
            for (int mt = 0; mt < 4; mt++)
#pragma unroll
                for (int p = 0; p < 2; p++)
#pragma unroll
                    for (int pt = 0; pt < 2; pt++)
                        mma16816(acc[mt][p * 2 + pt], ah[mt], &bh[p][pt * 2]);
#pragma unroll
            for (int mt = 0; mt < 4; mt++)
#pragma unroll
                for (int p = 0; p < 2; p++)
#pragma unroll
                    for (int pt = 0; pt < 2; pt++)
                        mma16816(acc[mt][p * 2 + pt], al[mt], &bh[p][pt * 2]);
        }
    }

    const bool do_gelu = (Ghi != nullptr);
#pragma unroll
    for (int mt = 0; mt < 4; mt++) {
        int r0 = by * 128 + wm * 64 + mt * 16 + (lane >> 2);
#pragma unroll
        for (int nt = 0; nt < 4; nt++) {
            int c0 = bx * 128 + wn * 32 + nt * 8 + (lane & 3) * 2;
            float b0 = bias[c0], b1 = bias[c0 + 1];
#pragma unroll
            for (int rr = 0; rr < 2; rr++) {
                int r = r0 + rr * 8;
                float v0 = acc[mt][nt][rr * 2 + 0] + b0;
                float v1 = acc[mt][nt][rr * 2 + 1] + b1;
                *(float2*)&C[(size_t)r * N + c0] = make_float2(v0, v1);
                if (do_gelu) {
                    float g0 = 0.5f * v0 * (1.0f + erff(v0 * 0.70710678118654752f));
                    float g1 = 0.5f * v1 * (1.0f + erff(v1 * 0.70710678118654752f));
                    float h0 = __half2float(__float2half_rn(g0));
                    float h1 = __half2float(__float2half_rn(g1));
                    *(uint32_t*)&Ghi[(size_t)r * N + c0] = pack_h2(h0, h1);
                    *(uint32_t*)&Glo[(size_t)r * N + c0] = pack_h2(g0 - h0, g1 - h1);
                }
            }
        }
    }
}

// ================= tau: HMMA fp16 2-term split-K GEMM =================
#define TAPL 10240
#define TBPL 5120
#define TSTAGE (2 * TAPL + TBPL)    // Ahi, Alo, Bhi = 25600
#define TSMEM (4 * TSTAGE)          // 102400

__global__ __launch_bounds__(256)
void tau_hmma_kernel(const __half* __restrict__ Ghi, const __half* __restrict__ Glo,
                     const __half* __restrict__ Twhi,
                     float* __restrict__ part) {
    extern __shared__ char smem[];
    const uint32_t sbase = smem_u32(smem);
    const int tid = threadIdx.x;
    const int wid = tid >> 5;
    const int lane = tid & 31;
    const int wm = wid >> 1;
    const int wn = wid & 1;
    const int t0 = blockIdx.x * 128;
    const int kbase = blockIdx.y * 768;

    float acc[2][4][4];
#pragma unroll
    for (int mt = 0; mt < 2; mt++)
#pragma unroll
        for (int nt = 0; nt < 4; nt++)
#pragma unroll
            for (int r = 0; r < 4; r++) acc[mt][nt][r] = 0.f;

    // 1024 A chunks + 256 B chunks = 1280 -> 5 per thread
    auto load_stage = [&](int ci) {
        if (ci < 24) {
            uint32_t st = sbase + (ci & 3) * TSTAGE;
            int k0 = kbase + ci * 32;
#pragma unroll
            for (int i = 0; i < 5; i++) {
                int c = tid + i * 256;
                if (c < 1024) {
                    int pl = c >> 9, idx = c & 511;
                    int r = idx >> 2, k4 = idx & 3;
                    cp_async16(st + pl * TAPL + (uint32_t)r * 80 + k4 * 16,
                               (pl ? Glo : Ghi) + (size_t)(t0 + r) * QKVD + k0 + k4 * 8);
                } else {
                    int c2 = c - 1024;
                    int r = c2 >> 2, k4 = c2 & 3;
                    cp_async16(st + 2 * TAPL + (uint32_t)r * 80 + k4 * 16,
                               Twhi + (size_t)r * QKVD + k0 + k4 * 8);
                }
            }
        }
        CP_COMMIT();
    };

    load_stage(0); load_stage(1); load_stage(2);

    for (int ci = 0; ci < 24; ci++) {
        CP_WAIT(2);
        __syncthreads();
        load_stage(ci + 3);

        uint32_t st = sbase + (ci & 3) * TSTAGE;
        const int g = lane >> 3;
#pragma unroll
        for (int ks = 0; ks < 2; ks++) {
            uint32_t ah[2][4], al[2][4];
#pragma unroll
            for (int mt = 0; mt < 2; mt++) {
                uint32_t aoff = (uint32_t)(wm * 32 + mt * 16 + (lane & 15)) * 80
                                + ks * 32 + (lane >> 4) * 16;
                ldsm4(ah[mt], st + aoff);
                ldsm4(al[mt], st + TAPL + aoff);
            }
            uint32_t bh[2][4];
#pragma unroll
            for (int p = 0; p < 2; p++) {
                int row = wn * 32 + p * 16 + (g >> 1) * 8 + (lane & 7);
                uint32_t boff = (uint32_t)row * 80 + ks * 32 + (g & 1) * 16;
                ldsm4(bh[p], st + 2 * TAPL + boff);
            }
#pragma unroll
            for (int mt = 0; mt < 2; mt++)
#pragma unroll
                for (int p = 0; p < 2; p++)
#pragma unroll
                    for (int pt = 0; pt < 2; pt++)
                        mma16816(acc[mt][p * 2 + pt], ah[mt], &bh[p][pt * 2]);
#pragma unroll
            for (int mt = 0; mt < 2; mt++)
#pragma unroll
                for (int p = 0; p < 2; p++)
#pragma unroll
                    for (int pt = 0; pt < 2; pt++)
                        mma16816(acc[mt][p * 2 + pt], al[mt], &bh[p][pt * 2]);
        }
    }

    float* pb = part + (size_t)blockIdx.y * T_ * 64;
#pragma unroll
    for (int mt = 0; mt < 2; mt++) {
        int r0 = t0 + wm * 32 + mt * 16 + (lane >> 2);
#pragma unroll
        for (int nt = 0; nt < 4; nt++) {
            int c0 = wn * 32 + nt * 8 + (lane & 3) * 2;
            *(float2*)&pb[(size_t)r0 * 64 + c0]       = make_float2(acc[mt][nt][0], acc[mt][nt][1]);
            *(float2*)&pb[(size_t)(r0 + 8) * 64 + c0] = make_float2(acc[mt][nt][2], acc[mt][nt][3]);
        }
    }
}

__global__ __launch_bounds__(256)
void tau_finish_kernel(const float* __restrict__ part, const float* __restrict__ alpha,
                       const int* __restrict__ positions,
                       float* __restrict__ tauq, float* __restrict__ tauv) {
    int idx = blockIdx.x * 256 + threadIdx.x;
    if (idx >= T_ * 64) return;
    int t = idx >> 6, o = idx & 63;
    float s = 0.f;
#pragma unroll
    for (int ks = 0; ks < 8; ks++) s += part[(size_t)ks * T_ * 64 + idx];
    int h = o & 31;
    float pl = logf(fmaxf((float)positions[t] + 1.0f, 1e-6f));
    float tp = 0.5f + 1.0f / (1.0f + expf(-alpha[h] * pl));
    float v = tanhf(s) + tp;
    if (o < 32) tauq[t * NH + h] = v;
    else        tauv[t * NH + h] = v;
}

// ================= prep: tau scale + RoPE -> Qhi,Qlo,Khi,Vhi =================
__global__ __launch_bounds__(256)
void prep_kernel(const float* __restrict__ qkv, const int* __restrict__ positions,
                 const float* __restrict__ tauq, const float* __restrict__ tauv,
                 __half* __restrict__ Qhi, __half* __restrict__ Qlo,
                 __half* __restrict__ Khi, __half* __restrict__ Vhi) {
    const int t = blockIdx.x;
    const float p = (float)positions[t];
    const float* row = qkv + (size_t)t * QKVD;

    for (int e = threadIdx.x; e < DIM_; e += 256) {
        int h = e >> 6;
        int d = e & 63;
        float tq = tauq[t * NH + h];
        float tv = tauv[t * NH + h];

        float qo = row[e] * tq;
        float ko = row[DIM_ + e];
        float vo = row[2 * DIM_ + e] * tv;

        if (d < 32) {
            int i = (d < 16) ? d : (d - 16);
            float ang = p * exp2f(-(float)i * 1.2457230355827609f);
            float s, c;
            sincosf(ang, &s, &c);
            if (d < 16) {
                float q2 = row[e + 16] * tq;
                float k2 = row[DIM_ + e + 16];
                qo = qo * c - q2 * s;
                ko = ko * c - k2 * s;
            } else {
                float q1 = row[e - 16] * tq;
                float k1 = row[DIM_ + e - 16];
                qo = qo * c + q1 * s;
                ko = ko * c + k1 * s;
            }
        }
        qo *= 0.125f;
        size_t o = (size_t)h * T_ * HD + (size_t)t * HD + d;
        __half qh = __float2half_rn(qo);
        Qhi[o] = qh;
        Qlo[o] = __float2half_rn(qo - __half2float(qh));
        Khi[o] = __float2half_rn(ko);
        Vhi[o] = __float2half_rn(vo);
    }
}

// ================= HMMA fp16 2-term flash attention =================
#define FROW 144
#define FQL_OFF (128 * FROW)
#define FSTG0   (2 * 128 * FROW)          // Q hi+lo
#define FSTG_BYTES (2 * 64 * FROW)        // Khi + Vhi = 18432
#define FKH 0
#define FVH (64 * FROW)
#define FLASH2_SMEM (FSTG0 + 4 * FSTG_BYTES)   // 110592

__global__ __launch_bounds__(256, 1)
void flash_hmma_kernel(const __half* __restrict__ Qhi, const __half* __restrict__ Qlo,
                       const __half* __restrict__ Khi, const __half* __restrict__ Vhi,
                       __half* __restrict__ Ahi, __half* __restrict__ Alo) {
    extern __shared__ char smem[];
    const uint32_t sb = smem_u32(smem);
    const int tid = threadIdx.x;
    const int wid = tid >> 5;
    const int lane = tid & 31;
    const int h = blockIdx.y;
    const int qt = (int)gridDim.x - 1 - (int)blockIdx.x;
    const int q0 = qt * 128;
    const size_t hb = (size_t)h * T_ * HD;
    const int nkt = 2 * qt + 2;

#pragma unroll
    for (int i = 0; i < 8; i++) {
        int c = tid + i * 256;
        int pl = c >> 10;
        int r = (c >> 3) & 127;
        int k8 = c & 7;
        const __half* src = (pl ? Qlo : Qhi) + hb + (size_t)(q0 + r) * HD + k8 * 8;
        cp_async16(sb + pl * FQL_OFF + (uint32_t)r * FROW + k8 * 16, src);
    }
    CP_COMMIT();

    auto load_kv = [&](int kt) {
        if (kt < nkt) {
            uint32_t stg = sb + FSTG0 + (kt & 3) * FSTG_BYTES;
#pragma unroll
            for (int i = 0; i < 4; i++) {
                int c = tid + i * 256;
                int pl = c >> 9;             // 0=Khi 1=Vhi
                int r = (c >> 3) & 63;
                int k8 = c & 7;
                const __half* base = pl ? Vhi : Khi;
                cp_async16(stg + pl * (64 * FROW) + (uint32_t)r * FROW + k8 * 16,
                           base + hb + (size_t)(kt * 64 + r) * HD + k8 * 8);
            }
        }
        CP_COMMIT();
    };
    load_kv(0); load_kv(1); load_kv(2);

    CP_WAIT(3);
    __syncthreads();

    uint32_t aqh[4][4], aql[4][4];
#pragma unroll
    for (int ks = 0; ks < 4; ks++) {
        uint32_t addr = sb + (uint32_t)(wid * 16 + (lane & 15)) * FROW + ks * 32 + (lane >> 4) * 16;
        ldsm4(aqh[ks], addr);
        ldsm4(aql[ks], addr + FQL_OFF);
    }

    float m0 = -1e30f, m1 = -1e30f, l0 = 0.f, l1 = 0.f;
    float O[8][4];
#pragma unroll
    for (int nf = 0; nf < 8; nf++)
#pragma unroll
        for (int c = 0; c < 4; c++) O[nf][c] = 0.f;

    for (int kt = 0; kt < nkt; kt++) {
        CP_WAIT(2);
        __syncthreads();
        load_kv(kt + 3);

        const bool active = (kt * 64 <= q0 + wid * 16 + 15);
        const uint32_t stg = sb + FSTG0 + (kt & 3) * FSTG_BYTES;

        if (active) {
            float S[8][4];
#pragma unroll
            for (int nf = 0; nf < 8; nf++)
#pragma unroll
                for (int c = 0; c < 4; c++) S[nf][c] = 0.f;

            // ---- S = Q K^T : (qhi + qlo) . khi ----
#pragma unroll
            for (int ks = 0; ks < 4; ks++) {
                uint32_t bh[4][4];
#pragma unroll
                for (int kp = 0; kp < 4; kp++) {
                    uint32_t ka = stg + (uint32_t)(kp * 16 + ((lane >> 4) << 3) + (lane & 7)) * FROW
                                  + ks * 32 + ((lane >> 3) & 1) * 16;
                    ldsm4(bh[kp], ka + FKH);
                }
#pragma unroll
                for (int kp = 0; kp < 4; kp++)
#pragma unroll
                    for (int half = 0; half < 2; half++)
                        mma16816(S[kp * 2 + half], aqh[ks], &bh[kp][half * 2]);
#pragma unroll
                for (int kp = 0; kp < 4; kp++)
#pragma unroll
                    for (int half = 0; half < 2; half++)
                        mma16816(S[kp * 2 + half], aql[ks], &bh[kp][half * 2]);
            }

            if (kt >= 2 * qt) {
                int rbase = q0 + wid * 16 + (lane >> 2);
                int cbase = kt * 64 + (lane & 3) * 2;
#pragma unroll
                for (int nf = 0; nf < 8; nf++)
#pragma unroll
                    for (int c = 0; c < 4; c++) {
                        int row = rbase + ((c >> 1) & 1) * 8;
                        int col = cbase + nf * 8 + (c & 1);
                        if (col > row) S[nf][c] = -1e30f;
                    }
            }

#pragma unroll
            for (int j = 0; j < 2; j++) {
                float& mj = j ? m1 : m0;
                float& lj = j ? l1 : l0;
                float rm = -1e30f;
#pragma unroll
                for (int nf = 0; nf < 8; nf++) {
                    rm = fmaxf(rm, S[nf][2 * j]);
                    rm = fmaxf(rm, S[nf][2 * j + 1]);
                }
                rm = fmaxf(rm, __shfl_xor_sync(0xffffffffu, rm, 1));
                rm = fmaxf(rm, __shfl_xor_sync(0xffffffffu, rm, 2));
                float mn = fmaxf(mj, rm);
                float alpha = __expf(mj - mn);
                float rs = 0.f;
#pragma unroll
                for (int nf = 0; nf < 8; nf++) {
                    float p0 = __expf(S[nf][2 * j] - mn);
                    float p1 = __expf(S[nf][2 * j + 1] - mn);
                    S[nf][2 * j] = p0; S[nf][2 * j + 1] = p1;
                    rs += p0 + p1;
                }
                rs += __shfl_xor_sync(0xffffffffu, rs, 1);
                rs += __shfl_xor_sync(0xffffffffu, rs, 2);
                lj = lj * alpha + rs;
                mj = mn;
#pragma unroll
                for (int nf = 0; nf < 8; nf++) {
                    O[nf][2 * j] *= alpha;
                    O[nf][2 * j + 1] *= alpha;
                }
            }

            // ---- O += P V : (phi + plo) . vhi ----
#pragma unroll
            for (int ks = 0; ks < 4; ks++) {
                uint32_t ah[4], al[4];
#pragma unroll
                for (int q = 0; q < 4; q++) {
                    int sf = 2 * ks + (q >> 1);
                    int c0 = (q & 1) * 2;
                    float p0 = S[sf][c0], p1 = S[sf][c0 + 1];
                    float h0 = __half2float(__float2half_rn(p0));
                    float h1 = __half2float(__float2half_rn(p1));
                    ah[q] = pack_h2(h0, h1);
                    al[q] = pack_h2(p0 - h0, p1 - h1);
                }
                uint32_t vh[4][4];
#pragma unroll
                for (int dp = 0; dp < 4; dp++) {
                    uint32_t va = stg + (uint32_t)(ks * 16 + ((lane >> 3) & 1) * 8 + (lane & 7)) * FROW
                                  + dp * 32 + (lane >> 4) * 16;
                    ldsm4t(vh[dp], va + FVH);
                }
#pragma unroll
                for (int dp = 0; dp < 4; dp++) {
                    mma16816(O[2 * dp],     ah, &vh[dp][0]);
                    mma16816(O[2 * dp + 1], ah, &vh[dp][2]);
                }
#pragma unroll
                for (int dp = 0; dp < 4; dp++) {
                    mma16816(O[2 * dp],     al, &vh[dp][0]);
                    mma16816(O[2 * dp + 1], al, &vh[dp][2]);
                }
            }
        }
    }

    float inv0 = 1.0f / l0;
    float inv1 = 1.0f / l1;
    int r0 = q0 + wid * 16 + (lane >> 2);
#pragma unroll
    for (int nf = 0; nf < 8; nf++)
#pragma unroll
        for (int j = 0; j < 2; j++) {
            float inv = j ? inv1 : inv0;
            float v0 = O[nf][2 * j] * inv;
            float v1 = O[nf][2 * j + 1] * inv;
            int t = r0 + j * 8;
            int col = h * 64 + nf * 8 + (lane & 3) * 2;
            float h0 = __half2float(__float2half_rn(v0));
            float h1 = __half2float(__float2half_rn(v1));
            *(uint32_t*)&Ahi[(size_t)t * DIM_ + col] = pack_h2(h0, h1);
            *(uint32_t*)&Alo[(size_t)t * DIM_ + col] = pack_h2(v0 - h0, v1 - h1);
        }
}

// ================= host launch =================
extern "C" void kernel_launch(void* const* d_in, const int* in_sizes, int n_in,
                              void* d_out, int out_size) {
    const int*   positions = (const int*)d_in[0];
    const float* hidden    = (const float*)d_in[1];
    const float* Wqkv      = (const float*)d_in[2];
    const float* bqkv      = (const float*)d_in[3];
    const float* Wout      = (const float*)d_in[4];
    const float* bout      = (const float*)d_in[5];
    const float* tau_alpha = (const float*)d_in[6];
    const float* tau_wq    = (const float*)d_in[7];
    const float* tau_wv    = (const float*)d_in[8];
    float* out = (float*)d_out;

    float *qkv, *tauq, *tauv, *taupart;
    __half *Ahi, *Alo, *Whi, *Ghi, *Glo, *Twhi, *Qhi, *Qlo, *Khi, *Vhi;
    cudaGetSymbolAddress((void**)&qkv,     g_qkv);
    cudaGetSymbolAddress((void**)&tauq,    g_tauq);
    cudaGetSymbolAddress((void**)&tauv,    g_tauv);
    cudaGetSymbolAddress((void**)&taupart, g_taupart);
    cudaGetSymbolAddress((void**)&Ahi,     g_Ahi);
    cudaGetSymbolAddress((void**)&Alo,     g_Alo);
    cudaGetSymbolAddress((void**)&Whi,     g_Whi);
    cudaGetSymbolAddress((void**)&Ghi,     g_Ghi);
    cudaGetSymbolAddress((void**)&Glo,     g_Glo);
    cudaGetSymbolAddress((void**)&Twhi,    g_Twhi);
    cudaGetSymbolAddress((void**)&Qhi,     g_Qhi);
    cudaGetSymbolAddress((void**)&Qlo,     g_Qlo);
    cudaGetSymbolAddress((void**)&Khi,     g_Khi);
    cudaGetSymbolAddress((void**)&Vhi,     g_Vhi);

    cudaFuncSetAttribute(gemm_hmma_kernel, cudaFuncAttributeMaxDynamicSharedMemorySize, GSMEM);
    cudaFuncSetAttribute(tau_hmma_kernel, cudaFuncAttributeMaxDynamicSharedMemorySize, TSMEM);
    cudaFuncSetAttribute(flash_hmma_kernel, cudaFuncAttributeMaxDynamicSharedMemorySize, FLASH2_SMEM);

    // decompose: hidden -> hi+lo ; weights -> hi only
    decomp_kernel<<<(T_ * DIM_ / 4 + 255) / 256, 256>>>(hidden, Ahi, Alo, T_ * DIM_ / 4);
    decomp1_kernel<<<(QKVD * DIM_ / 4 + 255) / 256, 256>>>(Wqkv, Whi, QKVD * DIM_ / 4);
    decomp1_kernel<<<(32 * QKVD / 4 + 255) / 256, 256>>>(tau_wq, Twhi, 32 * QKVD / 4);
    decomp1_kernel<<<(32 * QKVD / 4 + 255) / 256, 256>>>(tau_wv, Twhi + 32 * QKVD, 32 * QKVD / 4);
    // qkv = hidden @ Wqkv^T + bqkv (+ fused gelu split)
    gemm_hmma_kernel<<<dim3(QKVD / 128, T_ / 128), 256, GSMEM>>>(
        Ahi, Alo, Whi, bqkv, qkv, Ghi, Glo, QKVD, DIM_);
    // tau projections
    tau_hmma_kernel<<<dim3(T_ / 128, 8), 256, TSMEM>>>(Ghi, Glo, Twhi, taupart);
    tau_finish_kernel<<<(T_ * 64 + 255) / 256, 256>>>(taupart, tau_alpha, positions, tauq, tauv);
    // prep
    prep_kernel<<<T_, 256>>>(qkv, positions, tauq, tauv, Qhi, Qlo, Khi, Vhi);
    // flash attention
    flash_hmma_kernel<<<dim3(T_ / 128, NH), 256, FLASH2_SMEM>>>(
        Qhi, Qlo, Khi, Vhi, Ahi, Alo);
    // out = attn @ Wout^T + bout
    decomp1_kernel<<<(DIM_ * DIM_ / 4 + 255) / 256, 256>>>(Wout, Whi, DIM_ * DIM_ / 4);
    gemm_hmma_kernel<<<dim3(DIM_ / 128, T_ / 128), 256, GSMEM>>>(
        Ahi, Alo, Whi, bout, out, nullptr, nullptr, DIM_, DIM_);
}

// round 11
// speedup vs baseline: 1.4702x; 1.0721x over previous
#include <cuda_runtime.h>
#include <cuda_fp16.h>
#include <math.h>
#include <stdint.h>

#define T_ 2048
#define DIM_ 2048
#define NH 32
#define HD 64
#define QKVD 6144

// ---------------- scratch ----------------
__device__ float g_qkv[T_ * QKVD];
__device__ float g_tauq[T_ * NH];
__device__ float g_tauv[T_ * NH];
__device__ float g_taupart[8 * T_ * 64];
__device__ __half g_Ahi[T_ * DIM_];
__device__ __half g_Alo[T_ * DIM_];
__device__ __half g_Whi[QKVD * DIM_];
__device__ __half g_Ghi[T_ * QKVD];
__device__ __half g_Glo[T_ * QKVD];
__device__ __half g_Twhi[64 * QKVD];
__device__ __half g_Qhi[NH * T_ * HD];
__device__ __half g_Qlo[NH * T_ * HD];
__device__ __half g_Khi[NH * T_ * HD];
__device__ __half g_Vhi[NH * T_ * HD];

// ================= helpers =================
__device__ __forceinline__ uint32_t smem_u32(const void* p) {
    uint32_t a;
    asm("{ .reg .u64 t; cvta.to.shared.u64 t, %1; cvt.u32.u64 %0, t; }" : "=r"(a) : "l"(p));
    return a;
}
__device__ __forceinline__ void ldsm4(uint32_t* r, uint32_t addr) {
    asm volatile("ldmatrix.sync.aligned.m8n8.x4.shared.b16 {%0,%1,%2,%3}, [%4];"
        : "=r"(r[0]), "=r"(r[1]), "=r"(r[2]), "=r"(r[3]) : "r"(addr));
}
__device__ __forceinline__ void ldsm4t(uint32_t* r, uint32_t addr) {
    asm volatile("ldmatrix.sync.aligned.m8n8.x4.trans.shared.b16 {%0,%1,%2,%3}, [%4];"
        : "=r"(r[0]), "=r"(r[1]), "=r"(r[2]), "=r"(r[3]) : "r"(addr));
}
__device__ __forceinline__ void mma16816(float* d, const uint32_t* a, const uint32_t* b) {
    asm volatile("mma.sync.aligned.m16n8k16.row.col.f32.f16.f16.f32 "
        "{%0,%1,%2,%3}, {%4,%5,%6,%7}, {%8,%9}, {%0,%1,%2,%3};"
        : "+f"(d[0]), "+f"(d[1]), "+f"(d[2]), "+f"(d[3])
        : "r"(a[0]), "r"(a[1]), "r"(a[2]), "r"(a[3]), "r"(b[0]), "r"(b[1]));
}
__device__ __forceinline__ void cp_async16(uint32_t dst, const void* src) {
    asm volatile("cp.async.cg.shared.global [%0], [%1], 16;" :: "r"(dst), "l"(src) : "memory");
}
#define CP_COMMIT() asm volatile("cp.async.commit_group;" ::: "memory")
#define CP_WAIT(n)  asm volatile("cp.async.wait_group %0;" :: "n"(n) : "memory")

__device__ __forceinline__ uint32_t pack_h2(float lo, float hi) {
    __half2 t = __floats2half2_rn(lo, hi);
    return *reinterpret_cast<uint32_t*>(&t);
}

// ================= split-fp16 decomposition =================
__global__ __launch_bounds__(256)
void decomp_kernel(const float* __restrict__ in, __half* __restrict__ hi,
                   __half* __restrict__ lo, int n4) {
    int i = blockIdx.x * 256 + threadIdx.x;
    if (i >= n4) return;
    float4 v = ((const float4*)in)[i];
    __half h0 = __float2half_rn(v.x);
    __half h1 = __float2half_rn(v.y);
    __half h2 = __float2half_rn(v.z);
    __half h3 = __float2half_rn(v.w);
    ((__half2*)hi)[i * 2 + 0] = __halves2half2(h0, h1);
    ((__half2*)hi)[i * 2 + 1] = __halves2half2(h2, h3);
    ((__half2*)lo)[i * 2 + 0] = __floats2half2_rn(v.x - __half2float(h0), v.y - __half2float(h1));
    ((__half2*)lo)[i * 2 + 1] = __floats2half2_rn(v.z - __half2float(h2), v.w - __half2float(h3));
}

__global__ __launch_bounds__(256)
void decomp1_kernel(const float* __restrict__ in, __half* __restrict__ hi, int n4) {
    int i = blockIdx.x * 256 + threadIdx.x;
    if (i >= n4) return;
    float4 v = ((const float4*)in)[i];
    ((__half2*)hi)[i * 2 + 0] = __floats2half2_rn(v.x, v.y);
    ((__half2*)hi)[i * 2 + 1] = __floats2half2_rn(v.z, v.w);
}

// ================= HMMA fp16 2-term GEMM, 3-stage, 2 CTAs/SM =================
#define MAT_BYTES  (128 * 80)
#define STAGE_BYTES (3 * MAT_BYTES)   // Ahi, Alo, Bhi = 30720
#define GSMEM (3 * STAGE_BYTES)       // 92160 -> x2 CTAs = 184320 <= 233472

__global__ __launch_bounds__(256, 2)
void gemm_hmma_kernel(const __half* __restrict__ Ahi, const __half* __restrict__ Alo,
                      const __half* __restrict__ Bhi,
                      const float* __restrict__ bias, float* __restrict__ C,
                      __half* __restrict__ Ghi, __half* __restrict__ Glo,
                      int N, int K) {
    extern __shared__ char smem[];
    const uint32_t sbase = smem_u32(smem);
    const int tid = threadIdx.x;
    const int wid = tid >> 5;
    const int lane = tid & 31;
    const int wm = wid >> 2;
    const int wn = wid & 3;
    const int bx = blockIdx.x, by = blockIdx.y;
    const int nch = K / 32;

    float acc[4][4][4];
#pragma unroll
    for (int mt = 0; mt < 4; mt++)
#pragma unroll
        for (int nt = 0; nt < 4; nt++)
#pragma unroll
            for (int r = 0; r < 4; r++) acc[mt][nt][r] = 0.f;

    auto load_stage = [&](int ci) {
        if (ci < nch) {
            uint32_t st = sbase + (ci % 3) * STAGE_BYTES;
            int k0 = ci * 32;
#pragma unroll
            for (int i = 0; i < 6; i++) {
                int c = tid + i * 256;
                int pl = c / 512;
                int idx = c & 511;
                int row = idx >> 2, k4 = idx & 3;
                uint32_t so = (uint32_t)row * 80 + k4 * 16;
                if (pl == 0)
                    cp_async16(st + so, Ahi + (size_t)(by * 128 + row) * K + k0 + k4 * 8);
                else if (pl == 1)
                    cp_async16(st + MAT_BYTES + so, Alo + (size_t)(by * 128 + row) * K + k0 + k4 * 8);
                else
                    cp_async16(st + 2 * MAT_BYTES + so, Bhi + (size_t)(bx * 128 + row) * K + k0 + k4 * 8);
            }
        }
        CP_COMMIT();
    };

    load_stage(0); load_stage(1);

    for (int ci = 0; ci < nch; ci++) {
        CP_WAIT(1);
        __syncthreads();

        uint32_t st = sbase + (ci % 3) * STAGE_BYTES;
        uint32_t aHi = st, aLo = st + MAT_BYTES, bHi = st + 2 * MAT_BYTES;
        const int g = lane >> 3;

#pragma unroll
        for (int ks = 0; ks < 2; ks++) {
            uint32_t ah[4][4], al[4][4];
#pragma unroll
            for (int mt = 0; mt < 4; mt++) {
                uint32_t aoff = (uint32_t)(wm * 64 + mt * 16 + (lane & 15)) * 80
                                + ks * 32 + (lane >> 4) * 16;
                ldsm4(ah[mt], aHi + aoff);
                ldsm4(al[mt], aLo + aoff);
            }
            uint32_t bh[2][4];
#pragma unroll
            for (int p = 0; p < 2; p++) {
                int row = wn * 32 + p * 16 + (g >> 1) * 8 + (lane & 7);
                uint32_t boff = (uint32_t)row * 80 + ks * 32 + (g & 1) * 16;
                ldsm4(bh[p], bHi + boff);
            }
#pragma unroll
            for (int mt = 0; mt < 4; mt++)
#pragma unroll
                for (int p = 0; p < 2; p++)
#pragma unroll
                    for (int pt = 0; pt < 2; pt++)
                        mma16816(acc[mt][p * 2 + pt], ah[mt], &bh[p][pt * 2]);
#pragma unroll
            for (int mt = 0; mt < 4; mt++)
#pragma unroll
                for (int p = 0; p < 2; p++)
#pragma unroll
                    for (int pt = 0; pt < 2; pt++)
                        mma16816(acc[mt][p * 2 + pt], al[mt], &bh[p][pt * 2]);
        }
        __syncthreads();
        load_stage(ci + 2);
    }

    const bool do_gelu = (Ghi != nullptr);
#pragma unroll
    for (int mt = 0; mt < 4; mt++) {
        int r0 = by * 128 + wm * 64 + mt * 16 + (lane >> 2);
#pragma unroll
        for (int nt = 0; nt < 4; nt++) {
            int c0 = bx * 128 + wn * 32 + nt * 8 + (lane & 3) * 2;
            float b0 = bias[c0], b1 = bias[c0 + 1];
#pragma unroll
            for (int rr = 0; rr < 2; rr++) {
                int r = r0 + rr * 8;
                float v0 = acc[mt][nt][rr * 2 + 0] + b0;
                float v1 = acc[mt][nt][rr * 2 + 1] + b1;
                *(float2*)&C[(size_t)r * N + c0] = make_float2(v0, v1);
                if (do_gelu) {
                    float g0 = 0.5f * v0 * (1.0f + erff(v0 * 0.70710678118654752f));
                    float g1 = 0.5f * v1 * (1.0f + erff(v1 * 0.70710678118654752f));
                    float h0 = __half2float(__float2half_rn(g0));
                    float h1 = __half2float(__float2half_rn(g1));
                    *(uint32_t*)&Ghi[(size_t)r * N + c0] = pack_h2(h0, h1);
                    *(uint32_t*)&Glo[(size_t)r * N + c0] = pack_h2(g0 - h0, g1 - h1);
                }
            }
        }
    }
}

// ================= tau: HMMA fp16 2-term split-K GEMM, 2 CTAs/SM =================
#define TAPL 10240
#define TBPL 5120
#define TSTAGE (2 * TAPL + TBPL)
#define TSMEM (4 * TSTAGE)   // 102400 -> x2 = 204800 <= 233472

__global__ __launch_bounds__(256, 2)
void tau_hmma_kernel(const __half* __restrict__ Ghi, const __half* __restrict__ Glo,
                     const __half* __restrict__ Twhi,
                     float* __restrict__ part) {
    extern __shared__ char smem[];
    const uint32_t sbase = smem_u32(smem);
    const int tid = threadIdx.x;
    const int wid = tid >> 5;
    const int lane = tid & 31;
    const int wm = wid >> 1;
    const int wn = wid & 1;
    const int t0 = blockIdx.x * 128;
    const int kbase = blockIdx.y * 768;

    float acc[2][4][4];
#pragma unroll
    for (int mt = 0; mt < 2; mt++)
#pragma unroll
        for (int nt = 0; nt < 4; nt++)
#pragma unroll
            for (int r = 0; r < 4; r++) acc[mt][nt][r] = 0.f;

    auto load_stage = [&](int ci) {
        if (ci < 24) {
            uint32_t st = sbase + (ci & 3) * TSTAGE;
            int k0 = kbase + ci * 32;
#pragma unroll
            for (int i = 0; i < 5; i++) {
                int c = tid + i * 256;
                if (c < 1024) {
                    int pl = c >> 9, idx = c & 511;
                    int r = idx >> 2, k4 = idx & 3;
                    cp_async16(st + pl * TAPL + (uint32_t)r * 80 + k4 * 16,
                               (pl ? Glo : Ghi) + (size_t)(t0 + r) * QKVD + k0 + k4 * 8);
                } else {
                    int c2 = c - 1024;
                    int r = c2 >> 2, k4 = c2 & 3;
                    cp_async16(st + 2 * TAPL + (uint32_t)r * 80 + k4 * 16,
                               Twhi + (size_t)r * QKVD + k0 + k4 * 8);
                }
            }
        }
        CP_COMMIT();
    };

    load_stage(0); load_stage(1); load_stage(2);

    for (int ci = 0; ci < 24; ci++) {
        CP_WAIT(2);
        __syncthreads();
        load_stage(ci + 3);

        uint32_t st = sbase + (ci & 3) * TSTAGE;
        const int g = lane >> 3;
#pragma unroll
        for (int ks = 0; ks < 2; ks++) {
            uint32_t ah[2][4], al[2][4];
#pragma unroll
            for (int mt = 0; mt < 2; mt++) {
                uint32_t aoff = (uint32_t)(wm * 32 + mt * 16 + (lane & 15)) * 80
                                + ks * 32 + (lane >> 4) * 16;
                ldsm4(ah[mt], st + aoff);
                ldsm4(al[mt], st + TAPL + aoff);
            }
            uint32_t bh[2][4];
#pragma unroll
            for (int p = 0; p < 2; p++) {
                int row = wn * 32 + p * 16 + (g >> 1) * 8 + (lane & 7);
                uint32_t boff = (uint32_t)row * 80 + ks * 32 + (g & 1) * 16;
                ldsm4(bh[p], st + 2 * TAPL + boff);
            }
#pragma unroll
            for (int mt = 0; mt < 2; mt++)
#pragma unroll
                for (int p = 0; p < 2; p++)
#pragma unroll
                    for (int pt = 0; pt < 2; pt++)
                        mma16816(acc[mt][p * 2 + pt], ah[mt], &bh[p][pt * 2]);
#pragma unroll
            for (int mt = 0; mt < 2; mt++)
#pragma unroll
                for (int p = 0; p < 2; p++)
#pragma unroll
                    for (int pt = 0; pt < 2; pt++)
                        mma16816(acc[mt][p * 2 + pt], al[mt], &bh[p][pt * 2]);
        }
    }

    float* pb = part + (size_t)blockIdx.y * T_ * 64;
#pragma unroll
    for (int mt = 0; mt < 2; mt++) {
        int r0 = t0 + wm * 32 + mt * 16 + (lane >> 2);
#pragma unroll
        for (int nt = 0; nt < 4; nt++) {
            int c0 = wn * 32 + nt * 8 + (lane & 3) * 2;
            *(float2*)&pb[(size_t)r0 * 64 + c0]       = make_float2(acc[mt][nt][0], acc[mt][nt][1]);
            *(float2*)&pb[(size_t)(r0 + 8) * 64 + c0] = make_float2(acc[mt][nt][2], acc[mt][nt][3]);
        }
    }
}

__global__ __launch_bounds__(256)
void tau_finish_kernel(const float* __restrict__ part, const float* __restrict__ alpha,
                       const int* __restrict__ positions,
                       float* __restrict__ tauq, float* __restrict__ tauv) {
    int idx = blockIdx.x * 256 + threadIdx.x;
    if (idx >= T_ * 64) return;
    int t = idx >> 6, o = idx & 63;
    float s = 0.f;
#pragma unroll
    for (int ks = 0; ks < 8; ks++) s += part[(size_t)ks * T_ * 64 + idx];
    int h = o & 31;
    float pl = logf(fmaxf((float)positions[t] + 1.0f, 1e-6f));
    float tp = 0.5f + 1.0f / (1.0f + expf(-alpha[h] * pl));
    float v = tanhf(s) + tp;
    if (o < 32) tauq[t * NH + h] = v;
    else        tauv[t * NH + h] = v;
}

// ================= prep =================
__global__ __launch_bounds__(256)
void prep_kernel(const float* __restrict__ qkv, const int* __restrict__ positions,
                 const float* __restrict__ tauq, const float* __restrict__ tauv,
                 __half* __restrict__ Qhi, __half* __restrict__ Qlo,
                 __half* __restrict__ Khi, __half* __restrict__ Vhi) {
    const int t = blockIdx.x;
    const float p = (float)positions[t];
    const float* row = qkv + (size_t)t * QKVD;

    for (int e = threadIdx.x; e < DIM_; e += 256) {
        int h = e >> 6;
        int d = e & 63;
        float tq = tauq[t * NH + h];
        float tv = tauv[t * NH + h];

        float qo = row[e] * tq;
        float ko = row[DIM_ + e];
        float vo = row[2 * DIM_ + e] * tv;

        if (d < 32) {
            int i = (d < 16) ? d : (d - 16);
            float ang = p * exp2f(-(float)i * 1.2457230355827609f);
            float s, c;
            sincosf(ang, &s, &c);
            if (d < 16) {
                float q2 = row[e + 16] * tq;
                float k2 = row[DIM_ + e + 16];
                qo = qo * c - q2 * s;
                ko = ko * c - k2 * s;
            } else {
                float q1 = row[e - 16] * tq;
                float k1 = row[DIM_ + e - 16];
                qo = qo * c + q1 * s;
                ko = ko * c + k1 * s;
            }
        }
        qo *= 0.125f;
        size_t o = (size_t)h * T_ * HD + (size_t)t * HD + d;
        __half qh = __float2half_rn(qo);
        Qhi[o] = qh;
        Qlo[o] = __float2half_rn(qo - __half2float(qh));
        Khi[o] = __float2half_rn(ko);
        Vhi[o] = __float2half_rn(vo);
    }
}

// ================= HMMA fp16 2-term flash attention, 2 CTAs/SM =================
#define FROW 144
#define FQL_OFF (128 * FROW)
#define FSTG0   (2 * 128 * FROW)
#define FSTG_BYTES (2 * 64 * FROW)
#define FKH 0
#define FVH (64 * FROW)
#define FLASH2_SMEM (FSTG0 + 4 * FSTG_BYTES)   // 110592 -> x2 = 221184 <= 233472

__global__ __launch_bounds__(256, 2)
void flash_hmma_kernel(const __half* __restrict__ Qhi, const __half* __restrict__ Qlo,
                       const __half* __restrict__ Khi, const __half* __restrict__ Vhi,
                       __half* __restrict__ Ahi, __half* __restrict__ Alo) {
    extern __shared__ char smem[];
    const uint32_t sb = smem_u32(smem);
    const int tid = threadIdx.x;
    const int wid = tid >> 5;
    const int lane = tid & 31;
    const int h = blockIdx.y;
    const int qt = (int)gridDim.x - 1 - (int)blockIdx.x;
    const int q0 = qt * 128;
    const size_t hb = (size_t)h * T_ * HD;
    const int nkt = 2 * qt + 2;

#pragma unroll
    for (int i = 0; i < 8; i++) {
        int c = tid + i * 256;
        int pl = c >> 10;
        int r = (c >> 3) & 127;
        int k8 = c & 7;
        const __half* src = (pl ? Qlo : Qhi) + hb + (size_t)(q0 + r) * HD + k8 * 8;
        cp_async16(sb + pl * FQL_OFF + (uint32_t)r * FROW + k8 * 16, src);
    }
    CP_COMMIT();

    auto load_kv = [&](int kt) {
        if (kt < nkt) {
            uint32_t stg = sb + FSTG0 + (kt & 3) * FSTG_BYTES;
#pragma unroll
            for (int i = 0; i < 4; i++) {
                int c = tid + i * 256;
                int pl = c >> 9;
                int r = (c >> 3) & 63;
                int k8 = c & 7;
                const __half* base = pl ? Vhi : Khi;
                cp_async16(stg + pl * (64 * FROW) + (uint32_t)r * FROW + k8 * 16,
                           base + hb + (size_t)(kt * 64 + r) * HD + k8 * 8);
            }
        }
        CP_COMMIT();
    };
    load_kv(0); load_kv(1); load_kv(2);

    CP_WAIT(3);
    __syncthreads();

    uint32_t aqh[4][4], aql[4][4];
#pragma unroll
    for (int ks = 0; ks < 4; ks++) {
        uint32_t addr = sb + (uint32_t)(wid * 16 + (lane & 15)) * FROW + ks * 32 + (lane >> 4) * 16;
        ldsm4(aqh[ks], addr);
        ldsm4(aql[ks], addr + FQL_OFF);
    }

    float m0 = -1e30f, m1 = -1e30f, l0 = 0.f, l1 = 0.f;
    float O[8][4];
#pragma unroll
    for (int nf = 0; nf < 8; nf++)
#pragma unroll
        for (int c = 0; c < 4; c++) O[nf][c] = 0.f;

    for (int kt = 0; kt < nkt; kt++) {
        CP_WAIT(2);
        __syncthreads();
        load_kv(kt + 3);

        const bool active = (kt * 64 <= q0 + wid * 16 + 15);
        const uint32_t stg = sb + FSTG0 + (kt & 3) * FSTG_BYTES;

        if (active) {
            float S[8][4];
#pragma unroll
            for (int nf = 0; nf < 8; nf++)
#pragma unroll
                for (int c = 0; c < 4; c++) S[nf][c] = 0.f;

#pragma unroll
            for (int ks = 0; ks < 4; ks++) {
                uint32_t bh[4][4];
#pragma unroll
                for (int kp = 0; kp < 4; kp++) {
                    uint32_t ka = stg + (uint32_t)(kp * 16 + ((lane >> 4) << 3) + (lane & 7)) * FROW
                                  + ks * 32 + ((lane >> 3) & 1) * 16;
                    ldsm4(bh[kp], ka + FKH);
                }
#pragma unroll
                for (int kp = 0; kp < 4; kp++)
#pragma unroll
                    for (int half = 0; half < 2; half++)
                        mma16816(S[kp * 2 + half], aqh[ks], &bh[kp][half * 2]);
#pragma unroll
                for (int kp = 0; kp < 4; kp++)
#pragma unroll
                    for (int half = 0; half < 2; half++)
                        mma16816(S[kp * 2 + half], aql[ks], &bh[kp][half * 2]);
            }

            if (kt >= 2 * qt) {
                int rbase = q0 + wid * 16 + (lane >> 2);
                int cbase = kt * 64 + (lane & 3) * 2;
#pragma unroll
                for (int nf = 0; nf < 8; nf++)
#pragma unroll
                    for (int c = 0; c < 4; c++) {
                        int row = rbase + ((c >> 1) & 1) * 8;
                        int col = cbase + nf * 8 + (c & 1);
                        if (col > row) S[nf][c] = -1e30f;
                    }
            }

#pragma unroll
            for (int j = 0; j < 2; j++) {
                float& mj = j ? m1 : m0;
                float& lj = j ? l1 : l0;
                float rm = -1e30f;
#pragma unroll
                for (int nf = 0; nf < 8; nf++) {
                    rm = fmaxf(rm, S[nf][2 * j]);
                    rm = fmaxf(rm, S[nf][2 * j + 1]);
                }
                rm = fmaxf(rm, __shfl_xor_sync(0xffffffffu, rm, 1));
                rm = fmaxf(rm, __shfl_xor_sync(0xffffffffu, rm, 2));
                float mn = fmaxf(mj, rm);
                float alpha = __expf(mj - mn);
                float rs = 0.f;
#pragma unroll
                for (int nf = 0; nf < 8; nf++) {
                    float p0 = __expf(S[nf][2 * j] - mn);
                    float p1 = __expf(S[nf][2 * j + 1] - mn);
                    S[nf][2 * j] = p0; S[nf][2 * j + 1] = p1;
                    rs += p0 + p1;
                }
                rs += __shfl_xor_sync(0xffffffffu, rs, 1);
                rs += __shfl_xor_sync(0xffffffffu, rs, 2);
                lj = lj * alpha + rs;
                mj = mn;
#pragma unroll
                for (int nf = 0; nf < 8; nf++) {
                    O[nf][2 * j] *= alpha;
                    O[nf][2 * j + 1] *= alpha;
                }
            }

#pragma unroll
            for (int ks = 0; ks < 4; ks++) {
                uint32_t ah[4], al[4];
#pragma unroll
                for (int q = 0; q < 4; q++) {
                    int sf = 2 * ks + (q >> 1);
                    int c0 = (q & 1) * 2;
                    float p0 = S[sf][c0], p1 = S[sf][c0 + 1];
                    float h0 = __half2float(__float2half_rn(p0));
                    float h1 = __half2float(__float2half_rn(p1));
                    ah[q] = pack_h2(h0, h1);
                    al[q] = pack_h2(p0 - h0, p1 - h1);
                }
                uint32_t vh[4][4];
#pragma unroll
                for (int dp = 0; dp < 4; dp++) {
                    uint32_t va = stg + (uint32_t)(ks * 16 + ((lane >> 3) & 1) * 8 + (lane & 7)) * FROW
                                  + dp * 32 + (lane >> 4) * 16;
                    ldsm4t(vh[dp], va + FVH);
                }
#pragma unroll
                for (int dp = 0; dp < 4; dp++) {
                    mma16816(O[2 * dp],     ah, &vh[dp][0]);
                    mma16816(O[2 * dp + 1], ah, &vh[dp][2]);
                }
#pragma unroll
                for (int dp = 0; dp < 4; dp++) {
                    mma16816(O[2 * dp],     al, &vh[dp][0]);
                    mma16816(O[2 * dp + 1], al, &vh[dp][2]);
                }
            }
        }
    }

    float inv0 = 1.0f / l0;
    float inv1 = 1.0f / l1;
    int r0 = q0 + wid * 16 + (lane >> 2);
#pragma unroll
    for (int nf = 0; nf < 8; nf++)
#pragma unroll
        for (int j = 0; j < 2; j++) {
            float inv = j ? inv1 : inv0;
            float v0 = O[nf][2 * j] * inv;
            float v1 = O[nf][2 * j + 1] * inv;
            int t = r0 + j * 8;
            int col = h * 64 + nf * 8 + (lane & 3) * 2;
            float h0 = __half2float(__float2half_rn(v0));
            float h1 = __half2float(__float2half_rn(v1));
            *(uint32_t*)&Ahi[(size_t)t * DIM_ + col] = pack_h2(h0, h1);
            *(uint32_t*)&Alo[(size_t)t * DIM_ + col] = pack_h2(v0 - h0, v1 - h1);
        }
}

// ================= host launch =================
extern "C" void kernel_launch(void* const* d_in, const int* in_sizes, int n_in,
                              void* d_out, int out_size) {
    const int*   positions = (const int*)d_in[0];
    const float* hidden    = (const float*)d_in[1];
    const float* Wqkv      = (const float*)d_in[2];
    const float* bqkv      = (const float*)d_in[3];
    const float* Wout      = (const float*)d_in[4];
    const float* bout      = (const float*)d_in[5];
    const float* tau_alpha = (const float*)d_in[6];
    const float* tau_wq    = (const float*)d_in[7];
    const float* tau_wv    = (const float*)d_in[8];
    float* out = (float*)d_out;

    float *qkv, *tauq, *tauv, *taupart;
    __half *Ahi, *Alo, *Whi, *Ghi, *Glo, *Twhi, *Qhi, *Qlo, *Khi, *Vhi;
    cudaGetSymbolAddress((void**)&qkv,     g_qkv);
    cudaGetSymbolAddress((void**)&tauq,    g_tauq);
    cudaGetSymbolAddress((void**)&tauv,    g_tauv);
    cudaGetSymbolAddress((void**)&taupart, g_taupart);
    cudaGetSymbolAddress((void**)&Ahi,     g_Ahi);
    cudaGetSymbolAddress((void**)&Alo,     g_Alo);
    cudaGetSymbolAddress((void**)&Whi,     g_Whi);
    cudaGetSymbolAddress((void**)&Ghi,     g_Ghi);
    cudaGetSymbolAddress((void**)&Glo,     g_Glo);
    cudaGetSymbolAddress((void**)&Twhi,    g_Twhi);
    cudaGetSymbolAddress((void**)&Qhi,     g_Qhi);
    cudaGetSymbolAddress((void**)&Qlo,     g_Qlo);
    cudaGetSymbolAddress((void**)&Khi,     g_Khi);
    cudaGetSymbolAddress((void**)&Vhi,     g_Vhi);

    cudaFuncSetAttribute(gemm_hmma_kernel, cudaFuncAttributeMaxDynamicSharedMemorySize, GSMEM);
    cudaFuncSetAttribute(tau_hmma_kernel, cudaFuncAttributeMaxDynamicSharedMemorySize, TSMEM);
    cudaFuncSetAttribute(flash_hmma_kernel, cudaFuncAttributeMaxDynamicSharedMemorySize, FLASH2_SMEM);

    decomp_kernel<<<(T_ * DIM_ / 4 + 255) / 256, 256>>>(hidden, Ahi, Alo, T_ * DIM_ / 4);
    decomp1_kernel<<<(QKVD * DIM_ / 4 + 255) / 256, 256>>>(Wqkv, Whi, QKVD * DIM_ / 4);
    decomp1_kernel<<<(32 * QKVD / 4 + 255) / 256, 256>>>(tau_wq, Twhi, 32 * QKVD / 4);
    decomp1_kernel<<<(32 * QKVD / 4 + 255) / 256, 256>>>(tau_wv, Twhi + 32 * QKVD, 32 * QKVD / 4);
    gemm_hmma_kernel<<<dim3(QKVD / 128, T_ / 128), 256, GSMEM>>>(
        Ahi, Alo, Whi, bqkv, qkv, Ghi, Glo, QKVD, DIM_);
    tau_hmma_kernel<<<dim3(T_ / 128, 8), 256, TSMEM>>>(Ghi, Glo, Twhi, taupart);
    tau_finish_kernel<<<(T_ * 64 + 255) / 256, 256>>>(taupart, tau_alpha, positions, tauq, tauv);
    prep_kernel<<<T_, 256>>>(qkv, positions, tauq, tauv, Qhi, Qlo, Khi, Vhi);
    flash_hmma_kernel<<<dim3(T_ / 128, NH), 256, FLASH2_SMEM>>>(
        Qhi, Qlo, Khi, Vhi, Ahi, Alo);
    decomp1_kernel<<<(DIM_ * DIM_ / 4 + 255) / 256, 256>>>(Wout, Whi, DIM_ * DIM_ / 4);
    gemm_hmma_kernel<<<dim3(DIM_ / 128, T_ / 128), 256, GSMEM>>>(
        Ahi, Alo, Whi, bout, out, nullptr, nullptr, DIM_, DIM_);
}

// round 12
// speedup vs baseline: 1.6164x; 1.0995x over previous
#include <cuda_runtime.h>
#include <cuda_fp16.h>
#include <math.h>
#include <stdint.h>

#define T_ 2048
#define DIM_ 2048
#define NH 32
#define HD 64
#define QKVD 6144

// ---------------- scratch ----------------
__device__ float g_qkv[T_ * QKVD];
__device__ float g_tauq[T_ * NH];
__device__ float g_tauv[T_ * NH];
__device__ float g_taupart[8 * T_ * 64];
__device__ __half g_Ahi[T_ * DIM_];
__device__ __half g_Alo[T_ * DIM_];
__device__ __half g_Whi[QKVD * DIM_];
__device__ __half g_Ghi[T_ * QKVD];
__device__ __half g_Glo[T_ * QKVD];
__device__ __half g_Twhi[64 * QKVD];
__device__ __half g_Qhi[NH * T_ * HD];
__device__ __half g_Qlo[NH * T_ * HD];
__device__ __half g_Khi[NH * T_ * HD];
__device__ __half g_Vhi[NH * T_ * HD];

// ================= helpers =================
__device__ __forceinline__ uint32_t smem_u32(const void* p) {
    uint32_t a;
    asm("{ .reg .u64 t; cvta.to.shared.u64 t, %1; cvt.u32.u64 %0, t; }" : "=r"(a) : "l"(p));
    return a;
}
__device__ __forceinline__ void ldsm4(uint32_t* r, uint32_t addr) {
    asm volatile("ldmatrix.sync.aligned.m8n8.x4.shared.b16 {%0,%1,%2,%3}, [%4];"
        : "=r"(r[0]), "=r"(r[1]), "=r"(r[2]), "=r"(r[3]) : "r"(addr));
}
__device__ __forceinline__ void ldsm4t(uint32_t* r, uint32_t addr) {
    asm volatile("ldmatrix.sync.aligned.m8n8.x4.trans.shared.b16 {%0,%1,%2,%3}, [%4];"
        : "=r"(r[0]), "=r"(r[1]), "=r"(r[2]), "=r"(r[3]) : "r"(addr));
}
__device__ __forceinline__ void mma16816(float* d, const uint32_t* a, const uint32_t* b) {
    asm volatile("mma.sync.aligned.m16n8k16.row.col.f32.f16.f16.f32 "
        "{%0,%1,%2,%3}, {%4,%5,%6,%7}, {%8,%9}, {%0,%1,%2,%3};"
        : "+f"(d[0]), "+f"(d[1]), "+f"(d[2]), "+f"(d[3])
        : "r"(a[0]), "r"(a[1]), "r"(a[2]), "r"(a[3]), "r"(b[0]), "r"(b[1]));
}
__device__ __forceinline__ void cp_async16(uint32_t dst, const void* src) {
    asm volatile("cp.async.cg.shared.global [%0], [%1], 16;" :: "r"(dst), "l"(src) : "memory");
}
#define CP_COMMIT() asm volatile("cp.async.commit_group;" ::: "memory")
#define CP_WAIT(n)  asm volatile("cp.async.wait_group %0;" :: "n"(n) : "memory")

__device__ __forceinline__ uint32_t pack_h2(float lo, float hi) {
    __half2 t = __floats2half2_rn(lo, hi);
    return *reinterpret_cast<uint32_t*>(&t);
}

// ================= split-fp16 decomposition =================
__global__ __launch_bounds__(256)
void decomp_kernel(const float* __restrict__ in, __half* __restrict__ hi,
                   __half* __restrict__ lo, int n4) {
    int i = blockIdx.x * 256 + threadIdx.x;
    if (i >= n4) return;
    float4 v = ((const float4*)in)[i];
    __half h0 = __float2half_rn(v.x);
    __half h1 = __float2half_rn(v.y);
    __half h2 = __float2half_rn(v.z);
    __half h3 = __float2half_rn(v.w);
    ((__half2*)hi)[i * 2 + 0] = __halves2half2(h0, h1);
    ((__half2*)hi)[i * 2 + 1] = __halves2half2(h2, h3);
    ((__half2*)lo)[i * 2 + 0] = __floats2half2_rn(v.x - __half2float(h0), v.y - __half2float(h1));
    ((__half2*)lo)[i * 2 + 1] = __floats2half2_rn(v.z - __half2float(h2), v.w - __half2float(h3));
}

__global__ __launch_bounds__(256)
void decomp1_kernel(const float* __restrict__ in, __half* __restrict__ hi, int n4) {
    int i = blockIdx.x * 256 + threadIdx.x;
    if (i >= n4) return;
    float4 v = ((const float4*)in)[i];
    ((__half2*)hi)[i * 2 + 0] = __floats2half2_rn(v.x, v.y);
    ((__half2*)hi)[i * 2 + 1] = __floats2half2_rn(v.z, v.w);
}

// ================= HMMA fp16 GEMM, column-dependent term count =================
// Tiles with bx*128 < n_2term use (Ahi+Alo).Bhi ; others Ahi.Bhi only.
#define MAT_BYTES  (128 * 80)
#define STAGE_BYTES (3 * MAT_BYTES)
#define GSMEM (3 * STAGE_BYTES)

__global__ __launch_bounds__(256, 2)
void gemm_hmma_kernel(const __half* __restrict__ Ahi, const __half* __restrict__ Alo,
                      const __half* __restrict__ Bhi,
                      const float* __restrict__ bias, float* __restrict__ C,
                      __half* __restrict__ Ghi, __half* __restrict__ Glo,
                      int N, int K, int n_2term) {
    extern __shared__ char smem[];
    const uint32_t sbase = smem_u32(smem);
    const int tid = threadIdx.x;
    const int wid = tid >> 5;
    const int lane = tid & 31;
    const int wm = wid >> 2;
    const int wn = wid & 3;
    const int bx = blockIdx.x, by = blockIdx.y;
    const int nch = K / 32;
    const bool two_term = (bx * 128) < n_2term;

    float acc[4][4][4];
#pragma unroll
    for (int mt = 0; mt < 4; mt++)
#pragma unroll
        for (int nt = 0; nt < 4; nt++)
#pragma unroll
            for (int r = 0; r < 4; r++) acc[mt][nt][r] = 0.f;

    auto load_stage = [&](int ci) {
        if (ci < nch) {
            uint32_t st = sbase + (ci % 3) * STAGE_BYTES;
            int k0 = ci * 32;
#pragma unroll
            for (int i = 0; i < 6; i++) {
                int c = tid + i * 256;
                int pl = c / 512;
                int idx = c & 511;
                int row = idx >> 2, k4 = idx & 3;
                uint32_t so = (uint32_t)row * 80 + k4 * 16;
                if (pl == 0)
                    cp_async16(st + so, Ahi + (size_t)(by * 128 + row) * K + k0 + k4 * 8);
                else if (pl == 1) {
                    if (two_term)
                        cp_async16(st + MAT_BYTES + so, Alo + (size_t)(by * 128 + row) * K + k0 + k4 * 8);
                } else
                    cp_async16(st + 2 * MAT_BYTES + so, Bhi + (size_t)(bx * 128 + row) * K + k0 + k4 * 8);
            }
        }
        CP_COMMIT();
    };

    load_stage(0); load_stage(1);

    for (int ci = 0; ci < nch; ci++) {
        CP_WAIT(1);
        __syncthreads();

        uint32_t st = sbase + (ci % 3) * STAGE_BYTES;
        uint32_t aHi = st, aLo = st + MAT_BYTES, bHi = st + 2 * MAT_BYTES;
        const int g = lane >> 3;

#pragma unroll
        for (int ks = 0; ks < 2; ks++) {
            uint32_t ah[4][4], al[4][4];
#pragma unroll
            for (int mt = 0; mt < 4; mt++) {
                uint32_t aoff = (uint32_t)(wm * 64 + mt * 16 + (lane & 15)) * 80
                                + ks * 32 + (lane >> 4) * 16;
                ldsm4(ah[mt], aHi + aoff);
                if (two_term) ldsm4(al[mt], aLo + aoff);
            }
            uint32_t bh[2][4];
#pragma unroll
            for (int p = 0; p < 2; p++) {
                int row = wn * 32 + p * 16 + (g >> 1) * 8 + (lane & 7);
                uint32_t boff = (uint32_t)row * 80 + ks * 32 + (g & 1) * 16;
                ldsm4(bh[p], bHi + boff);
            }
#pragma unroll
            for (int mt = 0; mt < 4; mt++)
#pragma unroll
                for (int p = 0; p < 2; p++)
#pragma unroll
                    for (int pt = 0; pt < 2; pt++)
                        mma16816(acc[mt][p * 2 + pt], ah[mt], &bh[p][pt * 2]);
            if (two_term) {
#pragma unroll
                for (int mt = 0; mt < 4; mt++)
#pragma unroll
                    for (int p = 0; p < 2; p++)
#pragma unroll
                        for (int pt = 0; pt < 2; pt++)
                            mma16816(acc[mt][p * 2 + pt], al[mt], &bh[p][pt * 2]);
            }
        }
        __syncthreads();
        load_stage(ci + 2);
    }

    const bool do_gelu = (Ghi != nullptr);
#pragma unroll
    for (int mt = 0; mt < 4; mt++) {
        int r0 = by * 128 + wm * 64 + mt * 16 + (lane >> 2);
#pragma unroll
        for (int nt = 0; nt < 4; nt++) {
            int c0 = bx * 128 + wn * 32 + nt * 8 + (lane & 3) * 2;
            float b0 = bias[c0], b1 = bias[c0 + 1];
#pragma unroll
            for (int rr = 0; rr < 2; rr++) {
                int r = r0 + rr * 8;
                float v0 = acc[mt][nt][rr * 2 + 0] + b0;
                float v1 = acc[mt][nt][rr * 2 + 1] + b1;
                *(float2*)&C[(size_t)r * N + c0] = make_float2(v0, v1);
                if (do_gelu) {
                    float g0 = 0.5f * v0 * (1.0f + erff(v0 * 0.70710678118654752f));
                    float g1 = 0.5f * v1 * (1.0f + erff(v1 * 0.70710678118654752f));
                    float h0 = __half2float(__float2half_rn(g0));
                    float h1 = __half2float(__float2half_rn(g1));
                    *(uint32_t*)&Ghi[(size_t)r * N + c0] = pack_h2(h0, h1);
                    *(uint32_t*)&Glo[(size_t)r * N + c0] = pack_h2(g0 - h0, g1 - h1);
                }
            }
        }
    }
}

// ================= tau: HMMA fp16 2-term split-K GEMM =================
#define TAPL 10240
#define TBPL 5120
#define TSTAGE (2 * TAPL + TBPL)
#define TSMEM (4 * TSTAGE)

__global__ __launch_bounds__(256, 2)
void tau_hmma_kernel(const __half* __restrict__ Ghi, const __half* __restrict__ Glo,
                     const __half* __restrict__ Twhi,
                     float* __restrict__ part) {
    extern __shared__ char smem[];
    const uint32_t sbase = smem_u32(smem);
    const int tid = threadIdx.x;
    const int wid = tid >> 5;
    const int lane = tid & 31;
    const int wm = wid >> 1;
    const int wn = wid & 1;
    const int t0 = blockIdx.x * 128;
    const int kbase = blockIdx.y * 768;

    float acc[2][4][4];
#pragma unroll
    for (int mt = 0; mt < 2; mt++)
#pragma unroll
        for (int nt = 0; nt < 4; nt++)
#pragma unroll
            for (int r = 0; r < 4; r++) acc[mt][nt][r] = 0.f;

    auto load_stage = [&](int ci) {
        if (ci < 24) {
            uint32_t st = sbase + (ci & 3) * TSTAGE;
            int k0 = kbase + ci * 32;
#pragma unroll
            for (int i = 0; i < 5; i++) {
                int c = tid + i * 256;
                if (c < 1024) {
                    int pl = c >> 9, idx = c & 511;
                    int r = idx >> 2, k4 = idx & 3;
                    cp_async16(st + pl * TAPL + (uint32_t)r * 80 + k4 * 16,
                               (pl ? Glo : Ghi) + (size_t)(t0 + r) * QKVD + k0 + k4 * 8);
                } else {
                    int c2 = c - 1024;
                    int r = c2 >> 2, k4 = c2 & 3;
                    cp_async16(st + 2 * TAPL + (uint32_t)r * 80 + k4 * 16,
                               Twhi + (size_t)r * QKVD + k0 + k4 * 8);
                }
            }
        }
        CP_COMMIT();
    };

    load_stage(0); load_stage(1); load_stage(2);

    for (int ci = 0; ci < 24; ci++) {
        CP_WAIT(2);
        __syncthreads();
        load_stage(ci + 3);

        uint32_t st = sbase + (ci & 3) * TSTAGE;
        const int g = lane >> 3;
#pragma unroll
        for (int ks = 0; ks < 2; ks++) {
            uint32_t ah[2][4], al[2][4];
#pragma unroll
            for (int mt = 0; mt < 2; mt++) {
                uint32_t aoff = (uint32_t)(wm * 32 + mt * 16 + (lane & 15)) * 80
                                + ks * 32 + (lane >> 4) * 16;
                ldsm4(ah[mt], st + aoff);
                ldsm4(al[mt], st + TAPL + aoff);
            }
            uint32_t bh[2][4];
#pragma unroll
            for (int p = 0; p < 2; p++) {
                int row = wn * 32 + p * 16 + (g >> 1) * 8 + (lane & 7);
                uint32_t boff = (uint32_t)row * 80 + ks * 32 + (g & 1) * 16;
                ldsm4(bh[p], st + 2 * TAPL + boff);
            }
#pragma unroll
            for (int mt = 0; mt < 2; mt++)
#pragma unroll
                for (int p = 0; p < 2; p++)
#pragma unroll
                    for (int pt = 0; pt < 2; pt++)
                        mma16816(acc[mt][p * 2 + pt], ah[mt], &bh[p][pt * 2]);
#pragma unroll
            for (int mt = 0; mt < 2; mt++)
#pragma unroll
                for (int p = 0; p < 2; p++)
#pragma unroll
                    for (int pt = 0; pt < 2; pt++)
                        mma16816(acc[mt][p * 2 + pt], al[mt], &bh[p][pt * 2]);
        }
    }

    float* pb = part + (size_t)blockIdx.y * T_ * 64;
#pragma unroll
    for (int mt = 0; mt < 2; mt++) {
        int r0 = t0 + wm * 32 + mt * 16 + (lane >> 2);
#pragma unroll
        for (int nt = 0; nt < 4; nt++) {
            int c0 = wn * 32 + nt * 8 + (lane & 3) * 2;
            *(float2*)&pb[(size_t)r0 * 64 + c0]       = make_float2(acc[mt][nt][0], acc[mt][nt][1]);
            *(float2*)&pb[(size_t)(r0 + 8) * 64 + c0] = make_float2(acc[mt][nt][2], acc[mt][nt][3]);
        }
    }
}

__global__ __launch_bounds__(256)
void tau_finish_kernel(const float* __restrict__ part, const float* __restrict__ alpha,
                       const int* __restrict__ positions,
                       float* __restrict__ tauq, float* __restrict__ tauv) {
    int idx = blockIdx.x * 256 + threadIdx.x;
    if (idx >= T_ * 64) return;
    int t = idx >> 6, o = idx & 63;
    float s = 0.f;
#pragma unroll
    for (int ks = 0; ks < 8; ks++) s += part[(size_t)ks * T_ * 64 + idx];
    int h = o & 31;
    float pl = logf(fmaxf((float)positions[t] + 1.0f, 1e-6f));
    float tp = 0.5f + 1.0f / (1.0f + expf(-alpha[h] * pl));
    float v = tanhf(s) + tp;
    if (o < 32) tauq[t * NH + h] = v;
    else        tauv[t * NH + h] = v;
}

// ================= prep =================
__global__ __launch_bounds__(256)
void prep_kernel(const float* __restrict__ qkv, const int* __restrict__ positions,
                 const float* __restrict__ tauq, const float* __restrict__ tauv,
                 __half* __restrict__ Qhi, __half* __restrict__ Qlo,
                 __half* __restrict__ Khi, __half* __restrict__ Vhi) {
    const int t = blockIdx.x;
    const float p = (float)positions[t];
    const float* row = qkv + (size_t)t * QKVD;

    for (int e = threadIdx.x; e < DIM_; e += 256) {
        int h = e >> 6;
        int d = e & 63;
        float tq = tauq[t * NH + h];
        float tv = tauv[t * NH + h];

        float qo = row[e] * tq;
        float ko = row[DIM_ + e];
        float vo = row[2 * DIM_ + e] * tv;

        if (d < 32) {
            int i = (d < 16) ? d : (d - 16);
            float ang = p * exp2f(-(float)i * 1.2457230355827609f);
            float s, c;
            sincosf(ang, &s, &c);
            if (d < 16) {
                float q2 = row[e + 16] * tq;
                float k2 = row[DIM_ + e + 16];
                qo = qo * c - q2 * s;
                ko = ko * c - k2 * s;
            } else {
                float q1 = row[e - 16] * tq;
                float k1 = row[DIM_ + e - 16];
                qo = qo * c + q1 * s;
                ko = ko * c + k1 * s;
            }
        }
        qo *= 0.125f;
        size_t o = (size_t)h * T_ * HD + (size_t)t * HD + d;
        __half qh = __float2half_rn(qo);
        Qhi[o] = qh;
        Qlo[o] = __float2half_rn(qo - __half2float(qh));
        Khi[o] = __float2half_rn(ko);
        Vhi[o] = __float2half_rn(vo);
    }
}

// ================= HMMA fp16 2-term flash attention, deferred l-reduce =================
#define FROW 144
#define FQL_OFF (128 * FROW)
#define FSTG0   (2 * 128 * FROW)
#define FSTG_BYTES (2 * 64 * FROW)
#define FKH 0
#define FVH (64 * FROW)
#define FLASH2_SMEM (FSTG0 + 4 * FSTG_BYTES)

__global__ __launch_bounds__(256, 2)
void flash_hmma_kernel(const __half* __restrict__ Qhi, const __half* __restrict__ Qlo,
                       const __half* __restrict__ Khi, const __half* __restrict__ Vhi,
                       __half* __restrict__ Ahi, __half* __restrict__ Alo) {
    extern __shared__ char smem[];
    const uint32_t sb = smem_u32(smem);
    const int tid = threadIdx.x;
    const int wid = tid >> 5;
    const int lane = tid & 31;
    const int h = blockIdx.y;
    const int qt = (int)gridDim.x - 1 - (int)blockIdx.x;
    const int q0 = qt * 128;
    const size_t hb = (size_t)h * T_ * HD;
    const int nkt = 2 * qt + 2;

#pragma unroll
    for (int i = 0; i < 8; i++) {
        int c = tid + i * 256;
        int pl = c >> 10;
        int r = (c >> 3) & 127;
        int k8 = c & 7;
        const __half* src = (pl ? Qlo : Qhi) + hb + (size_t)(q0 + r) * HD + k8 * 8;
        cp_async16(sb + pl * FQL_OFF + (uint32_t)r * FROW + k8 * 16, src);
    }
    CP_COMMIT();

    auto load_kv = [&](int kt) {
        if (kt < nkt) {
            uint32_t stg = sb + FSTG0 + (kt & 3) * FSTG_BYTES;
#pragma unroll
            for (int i = 0; i < 4; i++) {
                int c = tid + i * 256;
                int pl = c >> 9;
                int r = (c >> 3) & 63;
                int k8 = c & 7;
                const __half* base = pl ? Vhi : Khi;
                cp_async16(stg + pl * (64 * FROW) + (uint32_t)r * FROW + k8 * 16,
                           base + hb + (size_t)(kt * 64 + r) * HD + k8 * 8);
            }
        }
        CP_COMMIT();
    };
    load_kv(0); load_kv(1); load_kv(2);

    CP_WAIT(3);
    __syncthreads();

    uint32_t aqh[4][4], aql[4][4];
#pragma unroll
    for (int ks = 0; ks < 4; ks++) {
        uint32_t addr = sb + (uint32_t)(wid * 16 + (lane & 15)) * FROW + ks * 32 + (lane >> 4) * 16;
        ldsm4(aqh[ks], addr);
        ldsm4(aql[ks], addr + FQL_OFF);
    }

    float m0 = -1e30f, m1 = -1e30f, l0 = 0.f, l1 = 0.f;   // l: per-thread partial
    float O[8][4];
#pragma unroll
    for (int nf = 0; nf < 8; nf++)
#pragma unroll
        for (int c = 0; c < 4; c++) O[nf][c] = 0.f;

    for (int kt = 0; kt < nkt; kt++) {
        CP_WAIT(2);
        __syncthreads();
        load_kv(kt + 3);

        const bool active = (kt * 64 <= q0 + wid * 16 + 15);
        const uint32_t stg = sb + FSTG0 + (kt & 3) * FSTG_BYTES;

        if (active) {
            float S[8][4];
#pragma unroll
            for (int nf = 0; nf < 8; nf++)
#pragma unroll
                for (int c = 0; c < 4; c++) S[nf][c] = 0.f;

#pragma unroll
            for (int ks = 0; ks < 4; ks++) {
                uint32_t bh[4][4];
#pragma unroll
                for (int kp = 0; kp < 4; kp++) {
                    uint32_t ka = stg + (uint32_t)(kp * 16 + ((lane >> 4) << 3) + (lane & 7)) * FROW
                                  + ks * 32 + ((lane >> 3) & 1) * 16;
                    ldsm4(bh[kp], ka + FKH);
                }
#pragma unroll
                for (int kp = 0; kp < 4; kp++)
#pragma unroll
                    for (int half = 0; half < 2; half++)
                        mma16816(S[kp * 2 + half], aqh[ks], &bh[kp][half * 2]);
#pragma unroll
                for (int kp = 0; kp < 4; kp++)
#pragma unroll
                    for (int half = 0; half < 2; half++)
                        mma16816(S[kp * 2 + half], aql[ks], &bh[kp][half * 2]);
            }

            if (kt >= 2 * qt) {
                int rbase = q0 + wid * 16 + (lane >> 2);
                int cbase = kt * 64 + (lane & 3) * 2;
#pragma unroll
                for (int nf = 0; nf < 8; nf++)
#pragma unroll
                    for (int c = 0; c < 4; c++) {
                        int row = rbase + ((c >> 1) & 1) * 8;
                        int col = cbase + nf * 8 + (c & 1);
                        if (col > row) S[nf][c] = -1e30f;
                    }
            }

#pragma unroll
            for (int j = 0; j < 2; j++) {
                float& mj = j ? m1 : m0;
                float& lj = j ? l1 : l0;
                float rm = -1e30f;
#pragma unroll
                for (int nf = 0; nf < 8; nf++) {
                    rm = fmaxf(rm, S[nf][2 * j]);
                    rm = fmaxf(rm, S[nf][2 * j + 1]);
                }
                rm = fmaxf(rm, __shfl_xor_sync(0xffffffffu, rm, 1));
                rm = fmaxf(rm, __shfl_xor_sync(0xffffffffu, rm, 2));
                float mn = fmaxf(mj, rm);
                float alpha = __expf(mj - mn);
                float rs = 0.f;
#pragma unroll
                for (int nf = 0; nf < 8; nf++) {
                    float p0 = __expf(S[nf][2 * j] - mn);
                    float p1 = __expf(S[nf][2 * j + 1] - mn);
                    S[nf][2 * j] = p0; S[nf][2 * j + 1] = p1;
                    rs += p0 + p1;
                }
                // deferred: no cross-thread sum here
                lj = lj * alpha + rs;
                mj = mn;
#pragma unroll
                for (int nf = 0; nf < 8; nf++) {
                    O[nf][2 * j] *= alpha;
                    O[nf][2 * j + 1] *= alpha;
                }
            }

#pragma unroll
            for (int ks = 0; ks < 4; ks++) {
                uint32_t ah[4], al[4];
#pragma unroll
                for (int q = 0; q < 4; q++) {
                    int sf = 2 * ks + (q >> 1);
                    int c0 = (q & 1) * 2;
                    float p0 = S[sf][c0], p1 = S[sf][c0 + 1];
                    float h0 = __half2float(__float2half_rn(p0));
                    float h1 = __half2float(__float2half_rn(p1));
                    ah[q] = pack_h2(h0, h1);
                    al[q] = pack_h2(p0 - h0, p1 - h1);
                }
                uint32_t vh[4][4];
#pragma unroll
                for (int dp = 0; dp < 4; dp++) {
                    uint32_t va = stg + (uint32_t)(ks * 16 + ((lane >> 3) & 1) * 8 + (lane & 7)) * FROW
                                  + dp * 32 + (lane >> 4) * 16;
                    ldsm4t(vh[dp], va + FVH);
                }
#pragma unroll
                for (int dp = 0; dp < 4; dp++) {
                    mma16816(O[2 * dp],     ah, &vh[dp][0]);
                    mma16816(O[2 * dp + 1], ah, &vh[dp][2]);
                }
#pragma unroll
                for (int dp = 0; dp < 4; dp++) {
                    mma16816(O[2 * dp],     al, &vh[dp][0]);
                    mma16816(O[2 * dp + 1], al, &vh[dp][2]);
                }
            }
        }
    }

    // final cross-thread l reduction (lanes sharing a row differ in bits 0,1)
    l0 += __shfl_xor_sync(0xffffffffu, l0, 1);
    l0 += __shfl_xor_sync(0xffffffffu, l0, 2);
    l1 += __shfl_xor_sync(0xffffffffu, l1, 1);
    l1 += __shfl_xor_sync(0xffffffffu, l1, 2);

    float inv0 = 1.0f / l0;
    float inv1 = 1.0f / l1;
    int r0 = q0 + wid * 16 + (lane >> 2);
#pragma unroll
    for (int nf = 0; nf < 8; nf++)
#pragma unroll
        for (int j = 0; j < 2; j++) {
            float inv = j ? inv1 : inv0;
            float v0 = O[nf][2 * j] * inv;
            float v1 = O[nf][2 * j + 1] * inv;
            int t = r0 + j * 8;
            int col = h * 64 + nf * 8 + (lane & 3) * 2;
            float h0 = __half2float(__float2half_rn(v0));
            float h1 = __half2float(__float2half_rn(v1));
            *(uint32_t*)&Ahi[(size_t)t * DIM_ + col] = pack_h2(h0, h1);
            *(uint32_t*)&Alo[(size_t)t * DIM_ + col] = pack_h2(v0 - h0, v1 - h1);
        }
}

// ================= host launch =================
extern "C" void kernel_launch(void* const* d_in, const int* in_sizes, int n_in,
                              void* d_out, int out_size) {
    const int*   positions = (const int*)d_in[0];
    const float* hidden    = (const float*)d_in[1];
    const float* Wqkv      = (const float*)d_in[2];
    const float* bqkv      = (const float*)d_in[3];
    const float* Wout      = (const float*)d_in[4];
    const float* bout      = (const float*)d_in[5];
    const float* tau_alpha = (const float*)d_in[6];
    const float* tau_wq    = (const float*)d_in[7];
    const float* tau_wv    = (const float*)d_in[8];
    float* out = (float*)d_out;

    float *qkv, *tauq, *tauv, *taupart;
    __half *Ahi, *Alo, *Whi, *Ghi, *Glo, *Twhi, *Qhi, *Qlo, *Khi, *Vhi;
    cudaGetSymbolAddress((void**)&qkv,     g_qkv);
    cudaGetSymbolAddress((void**)&tauq,    g_tauq);
    cudaGetSymbolAddress((void**)&tauv,    g_tauv);
    cudaGetSymbolAddress((void**)&taupart, g_taupart);
    cudaGetSymbolAddress((void**)&Ahi,     g_Ahi);
    cudaGetSymbolAddress((void**)&Alo,     g_Alo);
    cudaGetSymbolAddress((void**)&Whi,     g_Whi);
    cudaGetSymbolAddress((void**)&Ghi,     g_Ghi);
    cudaGetSymbolAddress((void**)&Glo,     g_Glo);
    cudaGetSymbolAddress((void**)&Twhi,    g_Twhi);
    cudaGetSymbolAddress((void**)&Qhi,     g_Qhi);
    cudaGetSymbolAddress((void**)&Qlo,     g_Qlo);
    cudaGetSymbolAddress((void**)&Khi,     g_Khi);
    cudaGetSymbolAddress((void**)&Vhi,     g_Vhi);

    cudaFuncSetAttribute(gemm_hmma_kernel, cudaFuncAttributeMaxDynamicSharedMemorySize, GSMEM);
    cudaFuncSetAttribute(tau_hmma_kernel, cudaFuncAttributeMaxDynamicSharedMemorySize, TSMEM);
    cudaFuncSetAttribute(flash_hmma_kernel, cudaFuncAttributeMaxDynamicSharedMemorySize, FLASH2_SMEM);

    decomp_kernel<<<(T_ * DIM_ / 4 + 255) / 256, 256>>>(hidden, Ahi, Alo, T_ * DIM_ / 4);
    decomp1_kernel<<<(QKVD * DIM_ / 4 + 255) / 256, 256>>>(Wqkv, Whi, QKVD * DIM_ / 4);
    decomp1_kernel<<<(32 * QKVD / 4 + 255) / 256, 256>>>(tau_wq, Twhi, 32 * QKVD / 4);
    decomp1_kernel<<<(32 * QKVD / 4 + 255) / 256, 256>>>(tau_wv, Twhi + 32 * QKVD, 32 * QKVD / 4);
    // q columns (< 2048) 2-term, k/v columns 1-term
    gemm_hmma_kernel<<<dim3(QKVD / 128, T_ / 128), 256, GSMEM>>>(
        Ahi, Alo, Whi, bqkv, qkv, Ghi, Glo, QKVD, DIM_, DIM_);
    tau_hmma_kernel<<<dim3(T_ / 128, 8), 256, TSMEM>>>(Ghi, Glo, Twhi, taupart);
    tau_finish_kernel<<<(T_ * 64 + 255) / 256, 256>>>(taupart, tau_alpha, positions, tauq, tauv);
    prep_kernel<<<T_, 256>>>(qkv, positions, tauq, tauv, Qhi, Qlo, Khi, Vhi);
    flash_hmma_kernel<<<dim3(T_ / 128, NH), 256, FLASH2_SMEM>>>(
        Qhi, Qlo, Khi, Vhi, Ahi, Alo);
    // gemm2: all columns 2-term
    decomp1_kernel<<<(DIM_ * DIM_ / 4 + 255) / 256, 256>>>(Wout, Whi, DIM_ * DIM_ / 4);
    gemm_hmma_kernel<<<dim3(DIM_ / 128, T_ / 128), 256, GSMEM>>>(
        Ahi, Alo, Whi, bout, out, nullptr, nullptr, DIM_, DIM_, DIM_);
}

// round 13
// speedup vs baseline: 1.6204x; 1.0025x over previous
#include <cuda_runtime.h>
#include <cuda_fp16.h>
#include <math.h>
#include <stdint.h>

#define T_ 2048
#define DIM_ 2048
#define NH 32
#define HD 64
#define QKVD 6144

// ---------------- scratch ----------------
__device__ float g_qkv[T_ * QKVD];
__device__ float g_taupart[8 * T_ * 64];
__device__ __half g_Ahi[T_ * DIM_];
__device__ __half g_Alo[T_ * DIM_];
__device__ __half g_Whi[QKVD * DIM_];
__device__ __half g_Ghi[T_ * QKVD];
__device__ __half g_Glo[T_ * QKVD];
__device__ __half g_Twhi[64 * QKVD];
__device__ __half g_Qhi[NH * T_ * HD];
__device__ __half g_Qlo[NH * T_ * HD];
__device__ __half g_Khi[NH * T_ * HD];
__device__ __half g_Vhi[NH * T_ * HD];

// ================= helpers =================
__device__ __forceinline__ uint32_t smem_u32(const void* p) {
    uint32_t a;
    asm("{ .reg .u64 t; cvta.to.shared.u64 t, %1; cvt.u32.u64 %0, t; }" : "=r"(a) : "l"(p));
    return a;
}
__device__ __forceinline__ void ldsm4(uint32_t* r, uint32_t addr) {
    asm volatile("ldmatrix.sync.aligned.m8n8.x4.shared.b16 {%0,%1,%2,%3}, [%4];"
        : "=r"(r[0]), "=r"(r[1]), "=r"(r[2]), "=r"(r[3]) : "r"(addr));
}
__device__ __forceinline__ void ldsm4t(uint32_t* r, uint32_t addr) {
    asm volatile("ldmatrix.sync.aligned.m8n8.x4.trans.shared.b16 {%0,%1,%2,%3}, [%4];"
        : "=r"(r[0]), "=r"(r[1]), "=r"(r[2]), "=r"(r[3]) : "r"(addr));
}
__device__ __forceinline__ void mma16816(float* d, const uint32_t* a, const uint32_t* b) {
    asm volatile("mma.sync.aligned.m16n8k16.row.col.f32.f16.f16.f32 "
        "{%0,%1,%2,%3}, {%4,%5,%6,%7}, {%8,%9}, {%0,%1,%2,%3};"
        : "+f"(d[0]), "+f"(d[1]), "+f"(d[2]), "+f"(d[3])
        : "r"(a[0]), "r"(a[1]), "r"(a[2]), "r"(a[3]), "r"(b[0]), "r"(b[1]));
}
__device__ __forceinline__ void cp_async16(uint32_t dst, const void* src) {
    asm volatile("cp.async.cg.shared.global [%0], [%1], 16;" :: "r"(dst), "l"(src) : "memory");
}
#define CP_COMMIT() asm volatile("cp.async.commit_group;" ::: "memory")
#define CP_WAIT(n)  asm volatile("cp.async.wait_group %0;" :: "n"(n) : "memory")

__device__ __forceinline__ uint32_t pack_h2(float lo, float hi) {
    __half2 t = __floats2half2_rn(lo, hi);
    return *reinterpret_cast<uint32_t*>(&t);
}
__device__ __forceinline__ float ex2(float x) {     // raw exp2, single MUFU op
    float y;
    asm("ex2.approx.f32 %0, %1;" : "=f"(y) : "f"(x));
    return y;
}

// ================= split-fp16 decomposition =================
__global__ __launch_bounds__(256)
void decomp_kernel(const float* __restrict__ in, __half* __restrict__ hi,
                   __half* __restrict__ lo, int n4) {
    int i = blockIdx.x * 256 + threadIdx.x;
    if (i >= n4) return;
    float4 v = ((const float4*)in)[i];
    __half h0 = __float2half_rn(v.x);
    __half h1 = __float2half_rn(v.y);
    __half h2 = __float2half_rn(v.z);
    __half h3 = __float2half_rn(v.w);
    ((__half2*)hi)[i * 2 + 0] = __halves2half2(h0, h1);
    ((__half2*)hi)[i * 2 + 1] = __halves2half2(h2, h3);
    ((__half2*)lo)[i * 2 + 0] = __floats2half2_rn(v.x - __half2float(h0), v.y - __half2float(h1));
    ((__half2*)lo)[i * 2 + 1] = __floats2half2_rn(v.z - __half2float(h2), v.w - __half2float(h3));
}

__global__ __launch_bounds__(256)
void decomp1_kernel(const float* __restrict__ in, __half* __restrict__ hi, int n4) {
    int i = blockIdx.x * 256 + threadIdx.x;
    if (i >= n4) return;
    float4 v = ((const float4*)in)[i];
    ((__half2*)hi)[i * 2 + 0] = __floats2half2_rn(v.x, v.y);
    ((__half2*)hi)[i * 2 + 1] = __floats2half2_rn(v.z, v.w);
}

// ================= HMMA fp16 GEMM, column-dependent term count =================
#define MAT_BYTES  (128 * 80)
#define STAGE_BYTES (3 * MAT_BYTES)
#define GSMEM (3 * STAGE_BYTES)

__global__ __launch_bounds__(256, 2)
void gemm_hmma_kernel(const __half* __restrict__ Ahi, const __half* __restrict__ Alo,
                      const __half* __restrict__ Bhi,
                      const float* __restrict__ bias, float* __restrict__ C,
                      __half* __restrict__ Ghi, __half* __restrict__ Glo,
                      int N, int K, int n_2term) {
    extern __shared__ char smem[];
    const uint32_t sbase = smem_u32(smem);
    const int tid = threadIdx.x;
    const int wid = tid >> 5;
    const int lane = tid & 31;
    const int wm = wid >> 2;
    const int wn = wid & 3;
    const int bx = blockIdx.x, by = blockIdx.y;
    const int nch = K / 32;
    const bool two_term = (bx * 128) < n_2term;

    float acc[4][4][4];
#pragma unroll
    for (int mt = 0; mt < 4; mt++)
#pragma unroll
        for (int nt = 0; nt < 4; nt++)
#pragma unroll
            for (int r = 0; r < 4; r++) acc[mt][nt][r] = 0.f;

    auto load_stage = [&](int ci) {
        if (ci < nch) {
            uint32_t st = sbase + (ci % 3) * STAGE_BYTES;
            int k0 = ci * 32;
#pragma unroll
            for (int i = 0; i < 6; i++) {
                int c = tid + i * 256;
                int pl = c / 512;
                int idx = c & 511;
                int row = idx >> 2, k4 = idx & 3;
                uint32_t so = (uint32_t)row * 80 + k4 * 16;
                if (pl == 0)
                    cp_async16(st + so, Ahi + (size_t)(by * 128 + row) * K + k0 + k4 * 8);
                else if (pl == 1) {
                    if (two_term)
                        cp_async16(st + MAT_BYTES + so, Alo + (size_t)(by * 128 + row) * K + k0 + k4 * 8);
                } else
                    cp_async16(st + 2 * MAT_BYTES + so, Bhi + (size_t)(bx * 128 + row) * K + k0 + k4 * 8);
            }
        }
        CP_COMMIT();
    };

    load_stage(0); load_stage(1);

    for (int ci = 0; ci < nch; ci++) {
        CP_WAIT(1);
        __syncthreads();

        uint32_t st = sbase + (ci % 3) * STAGE_BYTES;
        uint32_t aHi = st, aLo = st + MAT_BYTES, bHi = st + 2 * MAT_BYTES;
        const int g = lane >> 3;

#pragma unroll
        for (int ks = 0; ks < 2; ks++) {
            uint32_t ah[4][4], al[4][4];
#pragma unroll
            for (int mt = 0; mt < 4; mt++) {
                uint32_t aoff = (uint32_t)(wm * 64 + mt * 16 + (lane & 15)) * 80
                                + ks * 32 + (lane >> 4) * 16;
                ldsm4(ah[mt], aHi + aoff);
                if (two_term) ldsm4(al[mt], aLo + aoff);
            }
            uint32_t bh[2][4];
#pragma unroll
            for (int p = 0; p < 2; p++) {
                int row = wn * 32 + p * 16 + (g >> 1) * 8 + (lane & 7);
                uint32_t boff = (uint32_t)row * 80 + ks * 32 + (g & 1) * 16;
                ldsm4(bh[p], bHi + boff);
            }
#pragma unroll
            for (int mt = 0; mt < 4; mt++)
#pragma unroll
                for (int p = 0; p < 2; p++)
#pragma unroll
                    for (int pt = 0; pt < 2; pt++)
                        mma16816(acc[mt][p * 2 + pt], ah[mt], &bh[p][pt * 2]);
            if (two_term) {
#pragma unroll
                for (int mt = 0; mt < 4; mt++)
#pragma unroll
                    for (int p = 0; p < 2; p++)
#pragma unroll
                        for (int pt = 0; pt < 2; pt++)
                            mma16816(acc[mt][p * 2 + pt], al[mt], &bh[p][pt * 2]);
            }
        }
        __syncthreads();
        load_stage(ci + 2);
    }

    const bool do_gelu = (Ghi != nullptr);
#pragma unroll
    for (int mt = 0; mt < 4; mt++) {
        int r0 = by * 128 + wm * 64 + mt * 16 + (lane >> 2);
#pragma unroll
        for (int nt = 0; nt < 4; nt++) {
            int c0 = bx * 128 + wn * 32 + nt * 8 + (lane & 3) * 2;
            float b0 = bias[c0], b1 = bias[c0 + 1];
#pragma unroll
            for (int rr = 0; rr < 2; rr++) {
                int r = r0 + rr * 8;
                float v0 = acc[mt][nt][rr * 2 + 0] + b0;
                float v1 = acc[mt][nt][rr * 2 + 1] + b1;
                *(float2*)&C[(size_t)r * N + c0] = make_float2(v0, v1);
                if (do_gelu) {
                    float g0 = 0.5f * v0 * (1.0f + erff(v0 * 0.70710678118654752f));
                    float g1 = 0.5f * v1 * (1.0f + erff(v1 * 0.70710678118654752f));
                    float h0 = __half2float(__float2half_rn(g0));
                    float h1 = __half2float(__float2half_rn(g1));
                    *(uint32_t*)&Ghi[(size_t)r * N + c0] = pack_h2(h0, h1);
                    *(uint32_t*)&Glo[(size_t)r * N + c0] = pack_h2(g0 - h0, g1 - h1);
                }
            }
        }
    }
}

// ================= tau: HMMA fp16 2-term split-K GEMM =================
#define TAPL 10240
#define TBPL 5120
#define TSTAGE (2 * TAPL + TBPL)
#define TSMEM (4 * TSTAGE)

__global__ __launch_bounds__(256, 2)
void tau_hmma_kernel(const __half* __restrict__ Ghi, const __half* __restrict__ Glo,
                     const __half* __restrict__ Twhi,
                     float* __restrict__ part) {
    extern __shared__ char smem[];
    const uint32_t sbase = smem_u32(smem);
    const int tid = threadIdx.x;
    const int wid = tid >> 5;
    const int lane = tid & 31;
    const int wm = wid >> 1;
    const int wn = wid & 1;
    const int t0 = blockIdx.x * 128;
    const int kbase = blockIdx.y * 768;

    float acc[2][4][4];
#pragma unroll
    for (int mt = 0; mt < 2; mt++)
#pragma unroll
        for (int nt = 0; nt < 4; nt++)
#pragma unroll
            for (int r = 0; r < 4; r++) acc[mt][nt][r] = 0.f;

    auto load_stage = [&](int ci) {
        if (ci < 24) {
            uint32_t st = sbase + (ci & 3) * TSTAGE;
            int k0 = kbase + ci * 32;
#pragma unroll
            for (int i = 0; i < 5; i++) {
                int c = tid + i * 256;
                if (c < 1024) {
                    int pl = c >> 9, idx = c & 511;
                    int r = idx >> 2, k4 = idx & 3;
                    cp_async16(st + pl * TAPL + (uint32_t)r * 80 + k4 * 16,
                               (pl ? Glo : Ghi) + (size_t)(t0 + r) * QKVD + k0 + k4 * 8);
                } else {
                    int c2 = c - 1024;
                    int r = c2 >> 2, k4 = c2 & 3;
                    cp_async16(st + 2 * TAPL + (uint32_t)r * 80 + k4 * 16,
                               Twhi + (size_t)r * QKVD + k0 + k4 * 8);
                }
            }
        }
        CP_COMMIT();
    };

    load_stage(0); load_stage(1); load_stage(2);

    for (int ci = 0; ci < 24; ci++) {
        CP_WAIT(2);
        __syncthreads();
        load_stage(ci + 3);

        uint32_t st = sbase + (ci & 3) * TSTAGE;
        const int g = lane >> 3;
#pragma unroll
        for (int ks = 0; ks < 2; ks++) {
            uint32_t ah[2][4], al[2][4];
#pragma unroll
            for (int mt = 0; mt < 2; mt++) {
                uint32_t aoff = (uint32_t)(wm * 32 + mt * 16 + (lane & 15)) * 80
                                + ks * 32 + (lane >> 4) * 16;
                ldsm4(ah[mt], st + aoff);
                ldsm4(al[mt], st + TAPL + aoff);
            }
            uint32_t bh[2][4];
#pragma unroll
            for (int p = 0; p < 2; p++) {
                int row = wn * 32 + p * 16 + (g >> 1) * 8 + (lane & 7);
                uint32_t boff = (uint32_t)row * 80 + ks * 32 + (g & 1) * 16;
                ldsm4(bh[p], st + 2 * TAPL + boff);
            }
#pragma unroll
            for (int mt = 0; mt < 2; mt++)
#pragma unroll
                for (int p = 0; p < 2; p++)
#pragma unroll
                    for (int pt = 0; pt < 2; pt++)
                        mma16816(acc[mt][p * 2 + pt], ah[mt], &bh[p][pt * 2]);
#pragma unroll
            for (int mt = 0; mt < 2; mt++)
#pragma unroll
                for (int p = 0; p < 2; p++)
#pragma unroll
                    for (int pt = 0; pt < 2; pt++)
                        mma16816(acc[mt][p * 2 + pt], al[mt], &bh[p][pt * 2]);
        }
    }

    float* pb = part + (size_t)blockIdx.y * T_ * 64;
#pragma unroll
    for (int mt = 0; mt < 2; mt++) {
        int r0 = t0 + wm * 32 + mt * 16 + (lane >> 2);
#pragma unroll
        for (int nt = 0; nt < 4; nt++) {
            int c0 = wn * 32 + nt * 8 + (lane & 3) * 2;
            *(float2*)&pb[(size_t)r0 * 64 + c0]       = make_float2(acc[mt][nt][0], acc[mt][nt][1]);
            *(float2*)&pb[(size_t)(r0 + 8) * 64 + c0] = make_float2(acc[mt][nt][2], acc[mt][nt][3]);
        }
    }
}

// ================= prep (with fused tau finish) =================
// Q pre-scale includes log2(e) so flash softmax runs in exp2 domain.
#define QSCALE 0.18033688011112042f    // 0.125 * log2(e)

__global__ __launch_bounds__(256)
void prep_kernel(const float* __restrict__ qkv, const int* __restrict__ positions,
                 const float* __restrict__ part, const float* __restrict__ alpha,
                 __half* __restrict__ Qhi, __half* __restrict__ Qlo,
                 __half* __restrict__ Khi, __half* __restrict__ Vhi) {
    const int t = blockIdx.x;
    const float p = (float)positions[t];
    const float* row = qkv + (size_t)t * QKVD;

    __shared__ float stau[64];
    if (threadIdx.x < 64) {
        int o = threadIdx.x;
        float s = 0.f;
#pragma unroll
        for (int ks = 0; ks < 8; ks++) s += part[(size_t)ks * T_ * 64 + t * 64 + o];
        int hh = o & 31;
        float pl = logf(fmaxf(p + 1.0f, 1e-6f));
        float tp = 0.5f + 1.0f / (1.0f + expf(-alpha[hh] * pl));
        stau[o] = tanhf(s) + tp;
    }
    __syncthreads();

    for (int e = threadIdx.x; e < DIM_; e += 256) {
        int h = e >> 6;
        int d = e & 63;
        float tq = stau[h];
        float tv = stau[32 + h];

        float qo = row[e] * tq;
        float ko = row[DIM_ + e];
        float vo = row[2 * DIM_ + e] * tv;

        if (d < 32) {
            int i = (d < 16) ? d : (d - 16);
            float ang = p * exp2f(-(float)i * 1.2457230355827609f);
            float s, c;
            sincosf(ang, &s, &c);
            if (d < 16) {
                float q2 = row[e + 16] * tq;
                float k2 = row[DIM_ + e + 16];
                qo = qo * c - q2 * s;
                ko = ko * c - k2 * s;
            } else {
                float q1 = row[e - 16] * tq;
                float k1 = row[DIM_ + e - 16];
                qo = qo * c + q1 * s;
                ko = ko * c + k1 * s;
            }
        }
        qo *= QSCALE;
        size_t o = (size_t)h * T_ * HD + (size_t)t * HD + d;
        __half qh = __float2half_rn(qo);
        Qhi[o] = qh;
        Qlo[o] = __float2half_rn(qo - __half2float(qh));
        Khi[o] = __float2half_rn(ko);
        Vhi[o] = __float2half_rn(vo);
    }
}

// ================= HMMA fp16 2-term flash attention (exp2 domain) =================
#define FROW 144
#define FQL_OFF (128 * FROW)
#define FSTG0   (2 * 128 * FROW)
#define FSTG_BYTES (2 * 64 * FROW)
#define FKH 0
#define FVH (64 * FROW)
#define FLASH2_SMEM (FSTG0 + 4 * FSTG_BYTES)

__global__ __launch_bounds__(256, 2)
void flash_hmma_kernel(const __half* __restrict__ Qhi, const __half* __restrict__ Qlo,
                       const __half* __restrict__ Khi, const __half* __restrict__ Vhi,
                       __half* __restrict__ Ahi, __half* __restrict__ Alo) {
    extern __shared__ char smem[];
    const uint32_t sb = smem_u32(smem);
    const int tid = threadIdx.x;
    const int wid = tid >> 5;
    const int lane = tid & 31;
    const int h = blockIdx.y;
    const int qt = (int)gridDim.x - 1 - (int)blockIdx.x;
    const int q0 = qt * 128;
    const size_t hb = (size_t)h * T_ * HD;
    const int nkt = 2 * qt + 2;

#pragma unroll
    for (int i = 0; i < 8; i++) {
        int c = tid + i * 256;
        int pl = c >> 10;
        int r = (c >> 3) & 127;
        int k8 = c & 7;
        const __half* src = (pl ? Qlo : Qhi) + hb + (size_t)(q0 + r) * HD + k8 * 8;
        cp_async16(sb + pl * FQL_OFF + (uint32_t)r * FROW + k8 * 16, src);
    }
    CP_COMMIT();

    auto load_kv = [&](int kt) {
        if (kt < nkt) {
            uint32_t stg = sb + FSTG0 + (kt & 3) * FSTG_BYTES;
#pragma unroll
            for (int i = 0; i < 4; i++) {
                int c = tid + i * 256;
                int pl = c >> 9;
                int r = (c >> 3) & 63;
                int k8 = c & 7;
                const __half* base = pl ? Vhi : Khi;
                cp_async16(stg + pl * (64 * FROW) + (uint32_t)r * FROW + k8 * 16,
                           base + hb + (size_t)(kt * 64 + r) * HD + k8 * 8);
            }
        }
        CP_COMMIT();
    };
    load_kv(0); load_kv(1); load_kv(2);

    CP_WAIT(3);
    __syncthreads();

    uint32_t aqh[4][4], aql[4][4];
#pragma unroll
    for (int ks = 0; ks < 4; ks++) {
        uint32_t addr = sb + (uint32_t)(wid * 16 + (lane & 15)) * FROW + ks * 32 + (lane >> 4) * 16;
        ldsm4(aqh[ks], addr);
        ldsm4(aql[ks], addr + FQL_OFF);
    }

    float m0 = -1e30f, m1 = -1e30f, l0 = 0.f, l1 = 0.f;
    float O[8][4];
#pragma unroll
    for (int nf = 0; nf < 8; nf++)
#pragma unroll
        for (int c = 0; c < 4; c++) O[nf][c] = 0.f;

    for (int kt = 0; kt < nkt; kt++) {
        CP_WAIT(2);
        __syncthreads();
        load_kv(kt + 3);

        const bool active = (kt * 64 <= q0 + wid * 16 + 15);
        const uint32_t stg = sb + FSTG0 + (kt & 3) * FSTG_BYTES;

        if (active) {
            float S[8][4];
#pragma unroll
            for (int nf = 0; nf < 8; nf++)
#pragma unroll
                for (int c = 0; c < 4; c++) S[nf][c] = 0.f;

#pragma unroll
            for (int ks = 0; ks < 4; ks++) {
                uint32_t bh[4][4];
#pragma unroll
                for (int kp = 0; kp < 4; kp++) {
                    uint32_t ka = stg + (uint32_t)(kp * 16 + ((lane >> 4) << 3) + (lane & 7)) * FROW
                                  + ks * 32 + ((lane >> 3) & 1) * 16;
                    ldsm4(bh[kp], ka + FKH);
                }
#pragma unroll
                for (int kp = 0; kp < 4; kp++)
#pragma unroll
                    for (int half = 0; half < 2; half++)
                        mma16816(S[kp * 2 + half], aqh[ks], &bh[kp][half * 2]);
#pragma unroll
                for (int kp = 0; kp < 4; kp++)
#pragma unroll
                    for (int half = 0; half < 2; half++)
                        mma16816(S[kp * 2 + half], aql[ks], &bh[kp][half * 2]);
            }

            if (kt >= 2 * qt) {
                int rbase = q0 + wid * 16 + (lane >> 2);
                int cbase = kt * 64 + (lane & 3) * 2;
#pragma unroll
                for (int nf = 0; nf < 8; nf++)
#pragma unroll
                    for (int c = 0; c < 4; c++) {
                        int row = rbase + ((c >> 1) & 1) * 8;
                        int col = cbase + nf * 8 + (c & 1);
                        if (col > row) S[nf][c] = -1e30f;
                    }
            }

#pragma unroll
            for (int j = 0; j < 2; j++) {
                float& mj = j ? m1 : m0;
                float& lj = j ? l1 : l0;
                float rm = -1e30f;
#pragma unroll
                for (int nf = 0; nf < 8; nf++) {
                    rm = fmaxf(rm, S[nf][2 * j]);
                    rm = fmaxf(rm, S[nf][2 * j + 1]);
                }
                rm = fmaxf(rm, __shfl_xor_sync(0xffffffffu, rm, 1));
                rm = fmaxf(rm, __shfl_xor_sync(0xffffffffu, rm, 2));
                float mn = fmaxf(mj, rm);
                float alpha = ex2(mj - mn);
                float rs = 0.f;
#pragma unroll
                for (int nf = 0; nf < 8; nf++) {
                    float p0 = ex2(S[nf][2 * j] - mn);
                    float p1 = ex2(S[nf][2 * j + 1] - mn);
                    S[nf][2 * j] = p0; S[nf][2 * j + 1] = p1;
                    rs += p0 + p1;
                }
                lj = lj * alpha + rs;   // per-thread partial; reduced in epilogue
                mj = mn;
#pragma unroll
                for (int nf = 0; nf < 8; nf++) {
                    O[nf][2 * j] *= alpha;
                    O[nf][2 * j + 1] *= alpha;
                }
            }

#pragma unroll
            for (int ks = 0; ks < 4; ks++) {
                uint32_t ah[4], al[4];
#pragma unroll
                for (int q = 0; q < 4; q++) {
                    int sf = 2 * ks + (q >> 1);
                    int c0 = (q & 1) * 2;
                    float p0 = S[sf][c0], p1 = S[sf][c0 + 1];
                    float h0 = __half2float(__float2half_rn(p0));
                    float h1 = __half2float(__float2half_rn(p1));
                    ah[q] = pack_h2(h0, h1);
                    al[q] = pack_h2(p0 - h0, p1 - h1);
                }
                uint32_t vh[4][4];
#pragma unroll
                for (int dp = 0; dp < 4; dp++) {
                    uint32_t va = stg + (uint32_t)(ks * 16 + ((lane >> 3) & 1) * 8 + (lane & 7)) * FROW
                                  + dp * 32 + (lane >> 4) * 16;
                    ldsm4t(vh[dp], va + FVH);
                }
#pragma unroll
                for (int dp = 0; dp < 4; dp++) {
                    mma16816(O[2 * dp],     ah, &vh[dp][0]);
                    mma16816(O[2 * dp + 1], ah, &vh[dp][2]);
                }
#pragma unroll
                for (int dp = 0; dp < 4; dp++) {
                    mma16816(O[2 * dp],     al, &vh[dp][0]);
                    mma16816(O[2 * dp + 1], al, &vh[dp][2]);
                }
            }
        }
    }

    l0 += __shfl_xor_sync(0xffffffffu, l0, 1);
    l0 += __shfl_xor_sync(0xffffffffu, l0, 2);
    l1 += __shfl_xor_sync(0xffffffffu, l1, 1);
    l1 += __shfl_xor_sync(0xffffffffu, l1, 2);

    float inv0 = 1.0f / l0;
    float inv1 = 1.0f / l1;
    int r0 = q0 + wid * 16 + (lane >> 2);
#pragma unroll
    for (int nf = 0; nf < 8; nf++)
#pragma unroll
        for (int j = 0; j < 2; j++) {
            float inv = j ? inv1 : inv0;
            float v0 = O[nf][2 * j] * inv;
            float v1 = O[nf][2 * j + 1] * inv;
            int t = r0 + j * 8;
            int col = h * 64 + nf * 8 + (lane & 3) * 2;
            float h0 = __half2float(__float2half_rn(v0));
            float h1 = __half2float(__float2half_rn(v1));
            *(uint32_t*)&Ahi[(size_t)t * DIM_ + col] = pack_h2(h0, h1);
            *(uint32_t*)&Alo[(size_t)t * DIM_ + col] = pack_h2(v0 - h0, v1 - h1);
        }
}

// ================= host launch =================
extern "C" void kernel_launch(void* const* d_in, const int* in_sizes, int n_in,
                              void* d_out, int out_size) {
    const int*   positions = (const int*)d_in[0];
    const float* hidden    = (const float*)d_in[1];
    const float* Wqkv      = (const float*)d_in[2];
    const float* bqkv      = (const float*)d_in[3];
    const float* Wout      = (const float*)d_in[4];
    const float* bout      = (const float*)d_in[5];
    const float* tau_alpha = (const float*)d_in[6];
    const float* tau_wq    = (const float*)d_in[7];
    const float* tau_wv    = (const float*)d_in[8];
    float* out = (float*)d_out;

    float *qkv, *taupart;
    __half *Ahi, *Alo, *Whi, *Ghi, *Glo, *Twhi, *Qhi, *Qlo, *Khi, *Vhi;
    cudaGetSymbolAddress((void**)&qkv,     g_qkv);
    cudaGetSymbolAddress((void**)&taupart, g_taupart);
    cudaGetSymbolAddress((void**)&Ahi,     g_Ahi);
    cudaGetSymbolAddress((void**)&Alo,     g_Alo);
    cudaGetSymbolAddress((void**)&Whi,     g_Whi);
    cudaGetSymbolAddress((void**)&Ghi,     g_Ghi);
    cudaGetSymbolAddress((void**)&Glo,     g_Glo);
    cudaGetSymbolAddress((void**)&Twhi,    g_Twhi);
    cudaGetSymbolAddress((void**)&Qhi,     g_Qhi);
    cudaGetSymbolAddress((void**)&Qlo,     g_Qlo);
    cudaGetSymbolAddress((void**)&Khi,     g_Khi);
    cudaGetSymbolAddress((void**)&Vhi,     g_Vhi);

    cudaFuncSetAttribute(gemm_hmma_kernel, cudaFuncAttributeMaxDynamicSharedMemorySize, GSMEM);
    cudaFuncSetAttribute(tau_hmma_kernel, cudaFuncAttributeMaxDynamicSharedMemorySize, TSMEM);
    cudaFuncSetAttribute(flash_hmma_kernel, cudaFuncAttributeMaxDynamicSharedMemorySize, FLASH2_SMEM);

    decomp_kernel<<<(T_ * DIM_ / 4 + 255) / 256, 256>>>(hidden, Ahi, Alo, T_ * DIM_ / 4);
    decomp1_kernel<<<(QKVD * DIM_ / 4 + 255) / 256, 256>>>(Wqkv, Whi, QKVD * DIM_ / 4);
    decomp1_kernel<<<(32 * QKVD / 4 + 255) / 256, 256>>>(tau_wq, Twhi, 32 * QKVD / 4);
    decomp1_kernel<<<(32 * QKVD / 4 + 255) / 256, 256>>>(tau_wv, Twhi + 32 * QKVD, 32 * QKVD / 4);
    // q columns 2-term, k/v columns 1-term
    gemm_hmma_kernel<<<dim3(QKVD / 128, T_ / 128), 256, GSMEM>>>(
        Ahi, Alo, Whi, bqkv, qkv, Ghi, Glo, QKVD, DIM_, DIM_);
    tau_hmma_kernel<<<dim3(T_ / 128, 8), 256, TSMEM>>>(Ghi, Glo, Twhi, taupart);
    // prep with fused tau finish
    prep_kernel<<<T_, 256>>>(qkv, positions, taupart, tau_alpha, Qhi, Qlo, Khi, Vhi);
    flash_hmma_kernel<<<dim3(T_ / 128, NH), 256, FLASH2_SMEM>>>(
        Qhi, Qlo, Khi, Vhi, Ahi, Alo);
    decomp1_kernel<<<(DIM_ * DIM_ / 4 + 255) / 256, 256>>>(Wout, Whi, DIM_ * DIM_ / 4);
    gemm_hmma_kernel<<<dim3(DIM_ / 128, T_ / 128), 256, GSMEM>>>(
        Ahi, Alo, Whi, bout, out, nullptr, nullptr, DIM_, DIM_, DIM_);
}

// round 14
// speedup vs baseline: 1.6394x; 1.0117x over previous
#include <cuda_runtime.h>
#include <cuda_fp16.h>
#include <math.h>
#include <stdint.h>

#define T_ 2048
#define DIM_ 2048
#define NH 32
#define HD 64
#define QKVD 6144

// ---------------- scratch ----------------
__device__ float g_qkv[T_ * QKVD];
__device__ float g_taupart[8 * T_ * 64];
__device__ __half g_Ahi[T_ * DIM_];
__device__ __half g_Alo[T_ * DIM_];
__device__ __half g_Whi[QKVD * DIM_];
__device__ __half g_Ghi[T_ * QKVD];
__device__ __half g_Glo[T_ * QKVD];
__device__ __half g_Twhi[64 * QKVD];
__device__ __half g_Qhi[NH * T_ * HD];
__device__ __half g_Qlo[NH * T_ * HD];
__device__ __half g_Khi[NH * T_ * HD];
__device__ __half g_Vhi[NH * T_ * HD];

// ================= helpers =================
__device__ __forceinline__ uint32_t smem_u32(const void* p) {
    uint32_t a;
    asm("{ .reg .u64 t; cvta.to.shared.u64 t, %1; cvt.u32.u64 %0, t; }" : "=r"(a) : "l"(p));
    return a;
}
__device__ __forceinline__ void ldsm4(uint32_t* r, uint32_t addr) {
    asm volatile("ldmatrix.sync.aligned.m8n8.x4.shared.b16 {%0,%1,%2,%3}, [%4];"
        : "=r"(r[0]), "=r"(r[1]), "=r"(r[2]), "=r"(r[3]) : "r"(addr));
}
__device__ __forceinline__ void ldsm4t(uint32_t* r, uint32_t addr) {
    asm volatile("ldmatrix.sync.aligned.m8n8.x4.trans.shared.b16 {%0,%1,%2,%3}, [%4];"
        : "=r"(r[0]), "=r"(r[1]), "=r"(r[2]), "=r"(r[3]) : "r"(addr));
}
__device__ __forceinline__ void mma16816(float* d, const uint32_t* a, const uint32_t* b) {
    asm volatile("mma.sync.aligned.m16n8k16.row.col.f32.f16.f16.f32 "
        "{%0,%1,%2,%3}, {%4,%5,%6,%7}, {%8,%9}, {%0,%1,%2,%3};"
        : "+f"(d[0]), "+f"(d[1]), "+f"(d[2]), "+f"(d[3])
        : "r"(a[0]), "r"(a[1]), "r"(a[2]), "r"(a[3]), "r"(b[0]), "r"(b[1]));
}
__device__ __forceinline__ void cp_async16(uint32_t dst, const void* src) {
    asm volatile("cp.async.cg.shared.global [%0], [%1], 16;" :: "r"(dst), "l"(src) : "memory");
}
#define CP_COMMIT() asm volatile("cp.async.commit_group;" ::: "memory")
#define CP_WAIT(n)  asm volatile("cp.async.wait_group %0;" :: "n"(n) : "memory")

__device__ __forceinline__ uint32_t pack_h2(float lo, float hi) {
    __half2 t = __floats2half2_rn(lo, hi);
    return *reinterpret_cast<uint32_t*>(&t);
}
__device__ __forceinline__ float ex2(float x) {
    float y;
    asm("ex2.approx.f32 %0, %1;" : "=f"(y) : "f"(x));
    return y;
}

// ================= split-fp16 decomposition =================
__global__ __launch_bounds__(256)
void decomp_kernel(const float* __restrict__ in, __half* __restrict__ hi,
                   __half* __restrict__ lo, int n4) {
    int i = blockIdx.x * 256 + threadIdx.x;
    if (i >= n4) return;
    float4 v = ((const float4*)in)[i];
    __half h0 = __float2half_rn(v.x);
    __half h1 = __float2half_rn(v.y);
    __half h2 = __float2half_rn(v.z);
    __half h3 = __float2half_rn(v.w);
    ((__half2*)hi)[i * 2 + 0] = __halves2half2(h0, h1);
    ((__half2*)hi)[i * 2 + 1] = __halves2half2(h2, h3);
    ((__half2*)lo)[i * 2 + 0] = __floats2half2_rn(v.x - __half2float(h0), v.y - __half2float(h1));
    ((__half2*)lo)[i * 2 + 1] = __floats2half2_rn(v.z - __half2float(h2), v.w - __half2float(h3));
}

__global__ __launch_bounds__(256)
void decomp1_kernel(const float* __restrict__ in, __half* __restrict__ hi, int n4) {
    int i = blockIdx.x * 256 + threadIdx.x;
    if (i >= n4) return;
    float4 v = ((const float4*)in)[i];
    ((__half2*)hi)[i * 2 + 0] = __floats2half2_rn(v.x, v.y);
    ((__half2*)hi)[i * 2 + 1] = __floats2half2_rn(v.z, v.w);
}

// ================= HMMA fp16 GEMM, column-dependent term count =================
#define MAT_BYTES  (128 * 80)
#define STAGE_BYTES (3 * MAT_BYTES)
#define GSMEM (3 * STAGE_BYTES)

__global__ __launch_bounds__(256, 2)
void gemm_hmma_kernel(const __half* __restrict__ Ahi, const __half* __restrict__ Alo,
                      const __half* __restrict__ Bhi,
                      const float* __restrict__ bias, float* __restrict__ C,
                      __half* __restrict__ Ghi, __half* __restrict__ Glo,
                      int N, int K, int n_2term) {
    extern __shared__ char smem[];
    const uint32_t sbase = smem_u32(smem);
    const int tid = threadIdx.x;
    const int wid = tid >> 5;
    const int lane = tid & 31;
    const int wm = wid >> 2;
    const int wn = wid & 3;
    const int bx = blockIdx.x, by = blockIdx.y;
    const int nch = K / 32;
    const bool two_term = (bx * 128) < n_2term;

    float acc[4][4][4];
#pragma unroll
    for (int mt = 0; mt < 4; mt++)
#pragma unroll
        for (int nt = 0; nt < 4; nt++)
#pragma unroll
            for (int r = 0; r < 4; r++) acc[mt][nt][r] = 0.f;

    auto load_stage = [&](int ci) {
        if (ci < nch) {
            uint32_t st = sbase + (ci % 3) * STAGE_BYTES;
            int k0 = ci * 32;
#pragma unroll
            for (int i = 0; i < 6; i++) {
                int c = tid + i * 256;
                int pl = c / 512;
                int idx = c & 511;
                int row = idx >> 2, k4 = idx & 3;
                uint32_t so = (uint32_t)row * 80 + k4 * 16;
                if (pl == 0)
                    cp_async16(st + so, Ahi + (size_t)(by * 128 + row) * K + k0 + k4 * 8);
                else if (pl == 1) {
                    if (two_term)
                        cp_async16(st + MAT_BYTES + so, Alo + (size_t)(by * 128 + row) * K + k0 + k4 * 8);
                } else
                    cp_async16(st + 2 * MAT_BYTES + so, Bhi + (size_t)(bx * 128 + row) * K + k0 + k4 * 8);
            }
        }
        CP_COMMIT();
    };

    load_stage(0); load_stage(1);

    for (int ci = 0; ci < nch; ci++) {
        CP_WAIT(1);
        __syncthreads();

        uint32_t st = sbase + (ci % 3) * STAGE_BYTES;
        uint32_t aHi = st, aLo = st + MAT_BYTES, bHi = st + 2 * MAT_BYTES;
        const int g = lane >> 3;

#pragma unroll
        for (int ks = 0; ks < 2; ks++) {
            uint32_t ah[4][4], al[4][4];
#pragma unroll
            for (int mt = 0; mt < 4; mt++) {
                uint32_t aoff = (uint32_t)(wm * 64 + mt * 16 + (lane & 15)) * 80
                                + ks * 32 + (lane >> 4) * 16;
                ldsm4(ah[mt], aHi + aoff);
                if (two_term) ldsm4(al[mt], aLo + aoff);
            }
            uint32_t bh[2][4];
#pragma unroll
            for (int p = 0; p < 2; p++) {
                int row = wn * 32 + p * 16 + (g >> 1) * 8 + (lane & 7);
                uint32_t boff = (uint32_t)row * 80 + ks * 32 + (g & 1) * 16;
                ldsm4(bh[p], bHi + boff);
            }
#pragma unroll
            for (int mt = 0; mt < 4; mt++)
#pragma unroll
                for (int p = 0; p < 2; p++)
#pragma unroll
                    for (int pt = 0; pt < 2; pt++)
                        mma16816(acc[mt][p * 2 + pt], ah[mt], &bh[p][pt * 2]);
            if (two_term) {
#pragma unroll
                for (int mt = 0; mt < 4; mt++)
#pragma unroll
                    for (int p = 0; p < 2; p++)
#pragma unroll
                        for (int pt = 0; pt < 2; pt++)
                            mma16816(acc[mt][p * 2 + pt], al[mt], &bh[p][pt * 2]);
            }
        }
        __syncthreads();
        load_stage(ci + 2);
    }

    const bool do_gelu = (Ghi != nullptr);
#pragma unroll
    for (int mt = 0; mt < 4; mt++) {
        int r0 = by * 128 + wm * 64 + mt * 16 + (lane >> 2);
#pragma unroll
        for (int nt = 0; nt < 4; nt++) {
            int c0 = bx * 128 + wn * 32 + nt * 8 + (lane & 3) * 2;
            float b0 = bias[c0], b1 = bias[c0 + 1];
#pragma unroll
            for (int rr = 0; rr < 2; rr++) {
                int r = r0 + rr * 8;
                float v0 = acc[mt][nt][rr * 2 + 0] + b0;
                float v1 = acc[mt][nt][rr * 2 + 1] + b1;
                *(float2*)&C[(size_t)r * N + c0] = make_float2(v0, v1);
                if (do_gelu) {
                    float g0 = 0.5f * v0 * (1.0f + erff(v0 * 0.70710678118654752f));
                    float g1 = 0.5f * v1 * (1.0f + erff(v1 * 0.70710678118654752f));
                    float h0 = __half2float(__float2half_rn(g0));
                    float h1 = __half2float(__float2half_rn(g1));
                    *(uint32_t*)&Ghi[(size_t)r * N + c0] = pack_h2(h0, h1);
                    *(uint32_t*)&Glo[(size_t)r * N + c0] = pack_h2(g0 - h0, g1 - h1);
                }
            }
        }
    }
}

// ================= tau: HMMA fp16 2-term split-K GEMM =================
#define TAPL 10240
#define TBPL 5120
#define TSTAGE (2 * TAPL + TBPL)
#define TSMEM (4 * TSTAGE)

__global__ __launch_bounds__(256, 2)
void tau_hmma_kernel(const __half* __restrict__ Ghi, const __half* __restrict__ Glo,
                     const __half* __restrict__ Twhi,
                     float* __restrict__ part) {
    extern __shared__ char smem[];
    const uint32_t sbase = smem_u32(smem);
    const int tid = threadIdx.x;
    const int wid = tid >> 5;
    const int lane = tid & 31;
    const int wm = wid >> 1;
    const int wn = wid & 1;
    const int t0 = blockIdx.x * 128;
    const int kbase = blockIdx.y * 768;

    float acc[2][4][4];
#pragma unroll
    for (int mt = 0; mt < 2; mt++)
#pragma unroll
        for (int nt = 0; nt < 4; nt++)
#pragma unroll
            for (int r = 0; r < 4; r++) acc[mt][nt][r] = 0.f;

    auto load_stage = [&](int ci) {
        if (ci < 24) {
            uint32_t st = sbase + (ci & 3) * TSTAGE;
            int k0 = kbase + ci * 32;
#pragma unroll
            for (int i = 0; i < 5; i++) {
                int c = tid + i * 256;
                if (c < 1024) {
                    int pl = c >> 9, idx = c & 511;
                    int r = idx >> 2, k4 = idx & 3;
                    cp_async16(st + pl * TAPL + (uint32_t)r * 80 + k4 * 16,
                               (pl ? Glo : Ghi) + (size_t)(t0 + r) * QKVD + k0 + k4 * 8);
                } else {
                    int c2 = c - 1024;
                    int r = c2 >> 2, k4 = c2 & 3;
                    cp_async16(st + 2 * TAPL + (uint32_t)r * 80 + k4 * 16,
                               Twhi + (size_t)r * QKVD + k0 + k4 * 8);
                }
            }
        }
        CP_COMMIT();
    };

    load_stage(0); load_stage(1); load_stage(2);

    for (int ci = 0; ci < 24; ci++) {
        CP_WAIT(2);
        __syncthreads();
        load_stage(ci + 3);

        uint32_t st = sbase + (ci & 3) * TSTAGE;
        const int g = lane >> 3;
#pragma unroll
        for (int ks = 0; ks < 2; ks++) {
            uint32_t ah[2][4], al[2][4];
#pragma unroll
            for (int mt = 0; mt < 2; mt++) {
                uint32_t aoff = (uint32_t)(wm * 32 + mt * 16 + (lane & 15)) * 80
                                + ks * 32 + (lane >> 4) * 16;
                ldsm4(ah[mt], st + aoff);
                ldsm4(al[mt], st + TAPL + aoff);
            }
            uint32_t bh[2][4];
#pragma unroll
            for (int p = 0; p < 2; p++) {
                int row = wn * 32 + p * 16 + (g >> 1) * 8 + (lane & 7);
                uint32_t boff = (uint32_t)row * 80 + ks * 32 + (g & 1) * 16;
                ldsm4(bh[p], st + 2 * TAPL + boff);
            }
#pragma unroll
            for (int mt = 0; mt < 2; mt++)
#pragma unroll
                for (int p = 0; p < 2; p++)
#pragma unroll
                    for (int pt = 0; pt < 2; pt++)
                        mma16816(acc[mt][p * 2 + pt], ah[mt], &bh[p][pt * 2]);
#pragma unroll
            for (int mt = 0; mt < 2; mt++)
#pragma unroll
                for (int p = 0; p < 2; p++)
#pragma unroll
                    for (int pt = 0; pt < 2; pt++)
                        mma16816(acc[mt][p * 2 + pt], al[mt], &bh[p][pt * 2]);
        }
    }

    float* pb = part + (size_t)blockIdx.y * T_ * 64;
#pragma unroll
    for (int mt = 0; mt < 2; mt++) {
        int r0 = t0 + wm * 32 + mt * 16 + (lane >> 2);
#pragma unroll
        for (int nt = 0; nt < 4; nt++) {
            int c0 = wn * 32 + nt * 8 + (lane & 3) * 2;
            *(float2*)&pb[(size_t)r0 * 64 + c0]       = make_float2(acc[mt][nt][0], acc[mt][nt][1]);
            *(float2*)&pb[(size_t)(r0 + 8) * 64 + c0] = make_float2(acc[mt][nt][2], acc[mt][nt][3]);
        }
    }
}

// ================= prep (with fused tau finish) =================
#define QSCALE 0.18033688011112042f    // 0.125 * log2(e)

__global__ __launch_bounds__(256)
void prep_kernel(const float* __restrict__ qkv, const int* __restrict__ positions,
                 const float* __restrict__ part, const float* __restrict__ alpha,
                 __half* __restrict__ Qhi, __half* __restrict__ Qlo,
                 __half* __restrict__ Khi, __half* __restrict__ Vhi) {
    const int t = blockIdx.x;
    const float p = (float)positions[t];
    const float* row = qkv + (size_t)t * QKVD;

    __shared__ float stau[64];
    if (threadIdx.x < 64) {
        int o = threadIdx.x;
        float s = 0.f;
#pragma unroll
        for (int ks = 0; ks < 8; ks++) s += part[(size_t)ks * T_ * 64 + t * 64 + o];
        int hh = o & 31;
        float pl = logf(fmaxf(p + 1.0f, 1e-6f));
        float tp = 0.5f + 1.0f / (1.0f + expf(-alpha[hh] * pl));
        stau[o] = tanhf(s) + tp;
    }
    __syncthreads();

    for (int e = threadIdx.x; e < DIM_; e += 256) {
        int h = e >> 6;
        int d = e & 63;
        float tq = stau[h];
        float tv = stau[32 + h];

        float qo = row[e] * tq;
        float ko = row[DIM_ + e];
        float vo = row[2 * DIM_ + e] * tv;

        if (d < 32) {
            int i = (d < 16) ? d : (d - 16);
            float ang = p * exp2f(-(float)i * 1.2457230355827609f);
            float s, c;
            sincosf(ang, &s, &c);
            if (d < 16) {
                float q2 = row[e + 16] * tq;
                float k2 = row[DIM_ + e + 16];
                qo = qo * c - q2 * s;
                ko = ko * c - k2 * s;
            } else {
                float q1 = row[e - 16] * tq;
                float k1 = row[DIM_ + e - 16];
                qo = qo * c + q1 * s;
                ko = ko * c + k1 * s;
            }
        }
        qo *= QSCALE;
        size_t o = (size_t)h * T_ * HD + (size_t)t * HD + d;
        __half qh = __float2half_rn(qo);
        Qhi[o] = qh;
        Qlo[o] = __float2half_rn(qo - __half2float(qh));
        Khi[o] = __float2half_rn(ko);
        Vhi[o] = __float2half_rn(vo);
    }
}

// ================= HMMA fp16 2-term flash attention (exp2, Q reloaded from smem) =================
#define FROW 144
#define FQL_OFF (128 * FROW)
#define FSTG0   (2 * 128 * FROW)
#define FSTG_BYTES (2 * 64 * FROW)
#define FKH 0
#define FVH (64 * FROW)
#define FLASH2_SMEM (FSTG0 + 4 * FSTG_BYTES)

__global__ __launch_bounds__(256, 2)
void flash_hmma_kernel(const __half* __restrict__ Qhi, const __half* __restrict__ Qlo,
                       const __half* __restrict__ Khi, const __half* __restrict__ Vhi,
                       __half* __restrict__ Ahi, __half* __restrict__ Alo) {
    extern __shared__ char smem[];
    const uint32_t sb = smem_u32(smem);
    const int tid = threadIdx.x;
    const int wid = tid >> 5;
    const int lane = tid & 31;
    const int h = blockIdx.y;
    const int qt = (int)gridDim.x - 1 - (int)blockIdx.x;
    const int q0 = qt * 128;
    const size_t hb = (size_t)h * T_ * HD;
    const int nkt = 2 * qt + 2;

#pragma unroll
    for (int i = 0; i < 8; i++) {
        int c = tid + i * 256;
        int pl = c >> 10;
        int r = (c >> 3) & 127;
        int k8 = c & 7;
        const __half* src = (pl ? Qlo : Qhi) + hb + (size_t)(q0 + r) * HD + k8 * 8;
        cp_async16(sb + pl * FQL_OFF + (uint32_t)r * FROW + k8 * 16, src);
    }
    CP_COMMIT();

    auto load_kv = [&](int kt) {
        if (kt < nkt) {
            uint32_t stg = sb + FSTG0 + (kt & 3) * FSTG_BYTES;
#pragma unroll
            for (int i = 0; i < 4; i++) {
                int c = tid + i * 256;
                int pl = c >> 9;
                int r = (c >> 3) & 63;
                int k8 = c & 7;
                const __half* base = pl ? Vhi : Khi;
                cp_async16(stg + pl * (64 * FROW) + (uint32_t)r * FROW + k8 * 16,
                           base + hb + (size_t)(kt * 64 + r) * HD + k8 * 8);
            }
        }
        CP_COMMIT();
    };
    load_kv(0); load_kv(1); load_kv(2);

    CP_WAIT(3);
    __syncthreads();

    // NOTE: Q fragments are NOT cached in registers — reloaded from smem per
    // tile (frees 32 regs, eliminating spills under the 128-reg cap).
    const uint32_t qbase = sb + (uint32_t)(wid * 16 + (lane & 15)) * FROW + (lane >> 4) * 16;

    float m0 = -1e30f, m1 = -1e30f, l0 = 0.f, l1 = 0.f;
    float O[8][4];
#pragma unroll
    for (int nf = 0; nf < 8; nf++)
#pragma unroll
        for (int c = 0; c < 4; c++) O[nf][c] = 0.f;

    for (int kt = 0; kt < nkt; kt++) {
        CP_WAIT(2);
        __syncthreads();
        load_kv(kt + 3);

        const bool active = (kt * 64 <= q0 + wid * 16 + 15);
        const uint32_t stg = sb + FSTG0 + (kt & 3) * FSTG_BYTES;

        if (active) {
            float S[8][4];
#pragma unroll
            for (int nf = 0; nf < 8; nf++)
#pragma unroll
                for (int c = 0; c < 4; c++) S[nf][c] = 0.f;

#pragma unroll
            for (int ks = 0; ks < 4; ks++) {
                uint32_t aqh[4], aql[4];
                ldsm4(aqh, qbase + ks * 32);
                ldsm4(aql, qbase + ks * 32 + FQL_OFF);
                uint32_t bh[4][4];
#pragma unroll
                for (int kp = 0; kp < 4; kp++) {
                    uint32_t ka = stg + (uint32_t)(kp * 16 + ((lane >> 4) << 3) + (lane & 7)) * FROW
                                  + ks * 32 + ((lane >> 3) & 1) * 16;
                    ldsm4(bh[kp], ka + FKH);
                }
#pragma unroll
                for (int kp = 0; kp < 4; kp++)
#pragma unroll
                    for (int half = 0; half < 2; half++)
                        mma16816(S[kp * 2 + half], aqh, &bh[kp][half * 2]);
#pragma unroll
                for (int kp = 0; kp < 4; kp++)
#pragma unroll
                    for (int half = 0; half < 2; half++)
                        mma16816(S[kp * 2 + half], aql, &bh[kp][half * 2]);
            }

            if (kt >= 2 * qt) {
                int rbase = q0 + wid * 16 + (lane >> 2);
                int cbase = kt * 64 + (lane & 3) * 2;
#pragma unroll
                for (int nf = 0; nf < 8; nf++)
#pragma unroll
                    for (int c = 0; c < 4; c++) {
                        int row = rbase + ((c >> 1) & 1) * 8;
                        int col = cbase + nf * 8 + (c & 1);
                        if (col > row) S[nf][c] = -1e30f;
                    }
            }

#pragma unroll
            for (int j = 0; j < 2; j++) {
                float& mj = j ? m1 : m0;
                float& lj = j ? l1 : l0;
                float rm = -1e30f;
#pragma unroll
                for (int nf = 0; nf < 8; nf++) {
                    rm = fmaxf(rm, S[nf][2 * j]);
                    rm = fmaxf(rm, S[nf][2 * j + 1]);
                }
                rm = fmaxf(rm, __shfl_xor_sync(0xffffffffu, rm, 1));
                rm = fmaxf(rm, __shfl_xor_sync(0xffffffffu, rm, 2));
                float mn = fmaxf(mj, rm);
                float alpha = ex2(mj - mn);
                float rs = 0.f;
#pragma unroll
                for (int nf = 0; nf < 8; nf++) {
                    float p0 = ex2(S[nf][2 * j] - mn);
                    float p1 = ex2(S[nf][2 * j + 1] - mn);
                    S[nf][2 * j] = p0; S[nf][2 * j + 1] = p1;
                    rs += p0 + p1;
                }
                lj = lj * alpha + rs;
                mj = mn;
#pragma unroll
                for (int nf = 0; nf < 8; nf++) {
                    O[nf][2 * j] *= alpha;
                    O[nf][2 * j + 1] *= alpha;
                }
            }

#pragma unroll
            for (int ks = 0; ks < 4; ks++) {
                uint32_t ah[4], al[4];
#pragma unroll
                for (int q = 0; q < 4; q++) {
                    int sf = 2 * ks + (q >> 1);
                    int c0 = (q & 1) * 2;
                    float p0 = S[sf][c0], p1 = S[sf][c0 + 1];
                    float h0 = __half2float(__float2half_rn(p0));
                    float h1 = __half2float(__float2half_rn(p1));
                    ah[q] = pack_h2(h0, h1);
                    al[q] = pack_h2(p0 - h0, p1 - h1);
                }
                uint32_t vh[4][4];
#pragma unroll
                for (int dp = 0; dp < 4; dp++) {
                    uint32_t va = stg + (uint32_t)(ks * 16 + ((lane >> 3) & 1) * 8 + (lane & 7)) * FROW
                                  + dp * 32 + (lane >> 4) * 16;
                    ldsm4t(vh[dp], va + FVH);
                }
#pragma unroll
                for (int dp = 0; dp < 4; dp++) {
                    mma16816(O[2 * dp],     ah, &vh[dp][0]);
                    mma16816(O[2 * dp + 1], ah, &vh[dp][2]);
                }
#pragma unroll
                for (int dp = 0; dp < 4; dp++) {
                    mma16816(O[2 * dp],     al, &vh[dp][0]);
                    mma16816(O[2 * dp + 1], al, &vh[dp][2]);
                }
            }
        }
    }

    l0 += __shfl_xor_sync(0xffffffffu, l0, 1);
    l0 += __shfl_xor_sync(0xffffffffu, l0, 2);
    l1 += __shfl_xor_sync(0xffffffffu, l1, 1);
    l1 += __shfl_xor_sync(0xffffffffu, l1, 2);

    float inv0 = 1.0f / l0;
    float inv1 = 1.0f / l1;
    int r0 = q0 + wid * 16 + (lane >> 2);
#pragma unroll
    for (int nf = 0; nf < 8; nf++)
#pragma unroll
        for (int j = 0; j < 2; j++) {
            float inv = j ? inv1 : inv0;
            float v0 = O[nf][2 * j] * inv;
            float v1 = O[nf][2 * j + 1] * inv;
            int t = r0 + j * 8;
            int col = h * 64 + nf * 8 + (lane & 3) * 2;
            float h0 = __half2float(__float2half_rn(v0));
            float h1 = __half2float(__float2half_rn(v1));
            *(uint32_t*)&Ahi[(size_t)t * DIM_ + col] = pack_h2(h0, h1);
            *(uint32_t*)&Alo[(size_t)t * DIM_ + col] = pack_h2(v0 - h0, v1 - h1);
        }
}

// ================= host launch =================
extern "C" void kernel_launch(void* const* d_in, const int* in_sizes, int n_in,
                              void* d_out, int out_size) {
    const int*   positions = (const int*)d_in[0];
    const float* hidden    = (const float*)d_in[1];
    const float* Wqkv      = (const float*)d_in[2];
    const float* bqkv      = (const float*)d_in[3];
    const float* Wout      = (const float*)d_in[4];
    const float* bout      = (const float*)d_in[5];
    const float* tau_alpha = (const float*)d_in[6];
    const float* tau_wq    = (const float*)d_in[7];
    const float* tau_wv    = (const float*)d_in[8];
    float* out = (float*)d_out;

    float *qkv, *taupart;
    __half *Ahi, *Alo, *Whi, *Ghi, *Glo, *Twhi, *Qhi, *Qlo, *Khi, *Vhi;
    cudaGetSymbolAddress((void**)&qkv,     g_qkv);
    cudaGetSymbolAddress((void**)&taupart, g_taupart);
    cudaGetSymbolAddress((void**)&Ahi,     g_Ahi);
    cudaGetSymbolAddress((void**)&Alo,     g_Alo);
    cudaGetSymbolAddress((void**)&Whi,     g_Whi);
    cudaGetSymbolAddress((void**)&Ghi,     g_Ghi);
    cudaGetSymbolAddress((void**)&Glo,     g_Glo);
    cudaGetSymbolAddress((void**)&Twhi,    g_Twhi);
    cudaGetSymbolAddress((void**)&Qhi,     g_Qhi);
    cudaGetSymbolAddress((void**)&Qlo,     g_Qlo);
    cudaGetSymbolAddress((void**)&Khi,     g_Khi);
    cudaGetSymbolAddress((void**)&Vhi,     g_Vhi);

    cudaFuncSetAttribute(gemm_hmma_kernel, cudaFuncAttributeMaxDynamicSharedMemorySize, GSMEM);
    cudaFuncSetAttribute(tau_hmma_kernel, cudaFuncAttributeMaxDynamicSharedMemorySize, TSMEM);
    cudaFuncSetAttribute(flash_hmma_kernel, cudaFuncAttributeMaxDynamicSharedMemorySize, FLASH2_SMEM);

    decomp_kernel<<<(T_ * DIM_ / 4 + 255) / 256, 256>>>(hidden, Ahi, Alo, T_ * DIM_ / 4);
    decomp1_kernel<<<(QKVD * DIM_ / 4 + 255) / 256, 256>>>(Wqkv, Whi, QKVD * DIM_ / 4);
    decomp1_kernel<<<(32 * QKVD / 4 + 255) / 256, 256>>>(tau_wq, Twhi, 32 * QKVD / 4);
    decomp1_kernel<<<(32 * QKVD / 4 + 255) / 256, 256>>>(tau_wv, Twhi + 32 * QKVD, 32 * QKVD / 4);
    gemm_hmma_kernel<<<dim3(QKVD / 128, T_ / 128), 256, GSMEM>>>(
        Ahi, Alo, Whi, bqkv, qkv, Ghi, Glo, QKVD, DIM_, DIM_);
    tau_hmma_kernel<<<dim3(T_ / 128, 8), 256, TSMEM>>>(Ghi, Glo, Twhi, taupart);
    prep_kernel<<<T_, 256>>>(qkv, positions, taupart, tau_alpha, Qhi, Qlo, Khi, Vhi);
    flash_hmma_kernel<<<dim3(T_ / 128, NH), 256, FLASH2_SMEM>>>(
        Qhi, Qlo, Khi, Vhi, Ahi, Alo);
    decomp1_kernel<<<(DIM_ * DIM_ / 4 + 255) / 256, 256>>>(Wout, Whi, DIM_ * DIM_ / 4);
    gemm_hmma_kernel<<<dim3(DIM_ / 128, T_ / 128), 256, GSMEM>>>(
        Ahi, Alo, Whi, bout, out, nullptr, nullptr, DIM_, DIM_, DIM_);
}

// round 15
// speedup vs baseline: 1.6476x; 1.0050x over previous
#include <cuda_runtime.h>
#include <cuda_fp16.h>
#include <math.h>
#include <stdint.h>

#define T_ 2048
#define DIM_ 2048
#define NH 32
#define HD 64
#define QKVD 6144

// ---------------- scratch ----------------
__device__ float g_qkv[T_ * QKVD];
__device__ float g_taupart[8 * T_ * 64];
__device__ __half g_Ahi[T_ * DIM_];
__device__ __half g_Alo[T_ * DIM_];
__device__ __half g_Whi[QKVD * DIM_];
__device__ __half g_Ghi[T_ * QKVD];
__device__ __half g_Glo[T_ * QKVD];
__device__ __half g_Twhi[64 * QKVD];
__device__ __half g_Qhi[NH * T_ * HD];
__device__ __half g_Qlo[NH * T_ * HD];
__device__ __half g_Khi[NH * T_ * HD];
__device__ __half g_Vhi[NH * T_ * HD];

// ================= helpers =================
__device__ __forceinline__ uint32_t smem_u32(const void* p) {
    uint32_t a;
    asm("{ .reg .u64 t; cvta.to.shared.u64 t, %1; cvt.u32.u64 %0, t; }" : "=r"(a) : "l"(p));
    return a;
}
__device__ __forceinline__ void ldsm4(uint32_t* r, uint32_t addr) {
    asm volatile("ldmatrix.sync.aligned.m8n8.x4.shared.b16 {%0,%1,%2,%3}, [%4];"
        : "=r"(r[0]), "=r"(r[1]), "=r"(r[2]), "=r"(r[3]) : "r"(addr));
}
__device__ __forceinline__ void ldsm4t(uint32_t* r, uint32_t addr) {
    asm volatile("ldmatrix.sync.aligned.m8n8.x4.trans.shared.b16 {%0,%1,%2,%3}, [%4];"
        : "=r"(r[0]), "=r"(r[1]), "=r"(r[2]), "=r"(r[3]) : "r"(addr));
}
__device__ __forceinline__ void mma16816(float* d, const uint32_t* a, const uint32_t* b) {
    asm volatile("mma.sync.aligned.m16n8k16.row.col.f32.f16.f16.f32 "
        "{%0,%1,%2,%3}, {%4,%5,%6,%7}, {%8,%9}, {%0,%1,%2,%3};"
        : "+f"(d[0]), "+f"(d[1]), "+f"(d[2]), "+f"(d[3])
        : "r"(a[0]), "r"(a[1]), "r"(a[2]), "r"(a[3]), "r"(b[0]), "r"(b[1]));
}
__device__ __forceinline__ void cp_async16(uint32_t dst, const void* src) {
    asm volatile("cp.async.cg.shared.global [%0], [%1], 16;" :: "r"(dst), "l"(src) : "memory");
}
#define CP_COMMIT() asm volatile("cp.async.commit_group;" ::: "memory")
#define CP_WAIT(n)  asm volatile("cp.async.wait_group %0;" :: "n"(n) : "memory")

__device__ __forceinline__ uint32_t pack_h2(float lo, float hi) {
    __half2 t = __floats2half2_rn(lo, hi);
    return *reinterpret_cast<uint32_t*>(&t);
}
__device__ __forceinline__ float ex2(float x) {
    float y;
    asm("ex2.approx.f32 %0, %1;" : "=f"(y) : "f"(x));
    return y;
}

// ================= split-fp16 decomposition =================
__global__ __launch_bounds__(256)
void decomp_kernel(const float* __restrict__ in, __half* __restrict__ hi,
                   __half* __restrict__ lo, int n4) {
    int i = blockIdx.x * 256 + threadIdx.x;
    if (i >= n4) return;
    float4 v = ((const float4*)in)[i];
    __half h0 = __float2half_rn(v.x);
    __half h1 = __float2half_rn(v.y);
    __half h2 = __float2half_rn(v.z);
    __half h3 = __float2half_rn(v.w);
    ((__half2*)hi)[i * 2 + 0] = __halves2half2(h0, h1);
    ((__half2*)hi)[i * 2 + 1] = __halves2half2(h2, h3);
    ((__half2*)lo)[i * 2 + 0] = __floats2half2_rn(v.x - __half2float(h0), v.y - __half2float(h1));
    ((__half2*)lo)[i * 2 + 1] = __floats2half2_rn(v.z - __half2float(h2), v.w - __half2float(h3));
}

__global__ __launch_bounds__(256)
void decomp1_kernel(const float* __restrict__ in, __half* __restrict__ hi, int n4) {
    int i = blockIdx.x * 256 + threadIdx.x;
    if (i >= n4) return;
    float4 v = ((const float4*)in)[i];
    ((__half2*)hi)[i * 2 + 0] = __floats2half2_rn(v.x, v.y);
    ((__half2*)hi)[i * 2 + 1] = __floats2half2_rn(v.z, v.w);
}

// ================= HMMA fp16 GEMM, column-dependent term count =================
#define MAT_BYTES  (128 * 80)
#define STAGE_BYTES (3 * MAT_BYTES)
#define GSMEM (3 * STAGE_BYTES)

__global__ __launch_bounds__(256, 2)
void gemm_hmma_kernel(const __half* __restrict__ Ahi, const __half* __restrict__ Alo,
                      const __half* __restrict__ Bhi,
                      const float* __restrict__ bias, float* __restrict__ C,
                      __half* __restrict__ Ghi, __half* __restrict__ Glo,
                      int N, int K, int n_2term) {
    extern __shared__ char smem[];
    const uint32_t sbase = smem_u32(smem);
    const int tid = threadIdx.x;
    const int wid = tid >> 5;
    const int lane = tid & 31;
    const int wm = wid >> 2;
    const int wn = wid & 3;
    const int bx = blockIdx.x, by = blockIdx.y;
    const int nch = K / 32;
    const bool two_term = (bx * 128) < n_2term;

    float acc[4][4][4];
#pragma unroll
    for (int mt = 0; mt < 4; mt++)
#pragma unroll
        for (int nt = 0; nt < 4; nt++)
#pragma unroll
            for (int r = 0; r < 4; r++) acc[mt][nt][r] = 0.f;

    auto load_stage = [&](int ci) {
        if (ci < nch) {
            uint32_t st = sbase + (ci % 3) * STAGE_BYTES;
            int k0 = ci * 32;
#pragma unroll
            for (int i = 0; i < 6; i++) {
                int c = tid + i * 256;
                int pl = c / 512;
                int idx = c & 511;
                int row = idx >> 2, k4 = idx & 3;
                uint32_t so = (uint32_t)row * 80 + k4 * 16;
                if (pl == 0)
                    cp_async16(st + so, Ahi + (size_t)(by * 128 + row) * K + k0 + k4 * 8);
                else if (pl == 1) {
                    if (two_term)
                        cp_async16(st + MAT_BYTES + so, Alo + (size_t)(by * 128 + row) * K + k0 + k4 * 8);
                } else
                    cp_async16(st + 2 * MAT_BYTES + so, Bhi + (size_t)(bx * 128 + row) * K + k0 + k4 * 8);
            }
        }
        CP_COMMIT();
    };

    load_stage(0); load_stage(1);

    for (int ci = 0; ci < nch; ci++) {
        CP_WAIT(1);
        __syncthreads();

        uint32_t st = sbase + (ci % 3) * STAGE_BYTES;
        uint32_t aHi = st, aLo = st + MAT_BYTES, bHi = st + 2 * MAT_BYTES;
        const int g = lane >> 3;

#pragma unroll
        for (int ks = 0; ks < 2; ks++) {
            uint32_t ah[4][4], al[4][4];
#pragma unroll
            for (int mt = 0; mt < 4; mt++) {
                uint32_t aoff = (uint32_t)(wm * 64 + mt * 16 + (lane & 15)) * 80
                                + ks * 32 + (lane >> 4) * 16;
                ldsm4(ah[mt], aHi + aoff);
                if (two_term) ldsm4(al[mt], aLo + aoff);
            }
            uint32_t bh[2][4];
#pragma unroll
            for (int p = 0; p < 2; p++) {
                int row = wn * 32 + p * 16 + (g >> 1) * 8 + (lane & 7);
                uint32_t boff = (uint32_t)row * 80 + ks * 32 + (g & 1) * 16;
                ldsm4(bh[p], bHi + boff);
            }
#pragma unroll
            for (int mt = 0; mt < 4; mt++)
#pragma unroll
                for (int p = 0; p < 2; p++)
#pragma unroll
                    for (int pt = 0; pt < 2; pt++)
                        mma16816(acc[mt][p * 2 + pt], ah[mt], &bh[p][pt * 2]);
            if (two_term) {
#pragma unroll
                for (int mt = 0; mt < 4; mt++)
#pragma unroll
                    for (int p = 0; p < 2; p++)
#pragma unroll
                        for (int pt = 0; pt < 2; pt++)
                            mma16816(acc[mt][p * 2 + pt], al[mt], &bh[p][pt * 2]);
            }
        }
        __syncthreads();
        load_stage(ci + 2);
    }

    const bool do_gelu = (Ghi != nullptr);
#pragma unroll
    for (int mt = 0; mt < 4; mt++) {
        int r0 = by * 128 + wm * 64 + mt * 16 + (lane >> 2);
#pragma unroll
        for (int nt = 0; nt < 4; nt++) {
            int c0 = bx * 128 + wn * 32 + nt * 8 + (lane & 3) * 2;
            float b0 = bias[c0], b1 = bias[c0 + 1];
#pragma unroll
            for (int rr = 0; rr < 2; rr++) {
                int r = r0 + rr * 8;
                float v0 = acc[mt][nt][rr * 2 + 0] + b0;
                float v1 = acc[mt][nt][rr * 2 + 1] + b1;
                *(float2*)&C[(size_t)r * N + c0] = make_float2(v0, v1);
                if (do_gelu) {
                    float g0 = 0.5f * v0 * (1.0f + erff(v0 * 0.70710678118654752f));
                    float g1 = 0.5f * v1 * (1.0f + erff(v1 * 0.70710678118654752f));
                    float h0 = __half2float(__float2half_rn(g0));
                    float h1 = __half2float(__float2half_rn(g1));
                    *(uint32_t*)&Ghi[(size_t)r * N + c0] = pack_h2(h0, h1);
                    *(uint32_t*)&Glo[(size_t)r * N + c0] = pack_h2(g0 - h0, g1 - h1);
                }
            }
        }
    }
}

// ================= tau: HMMA fp16 2-term split-K GEMM =================
#define TAPL 10240
#define TBPL 5120
#define TSTAGE (2 * TAPL + TBPL)
#define TSMEM (4 * TSTAGE)

__global__ __launch_bounds__(256, 2)
void tau_hmma_kernel(const __half* __restrict__ Ghi, const __half* __restrict__ Glo,
                     const __half* __restrict__ Twhi,
                     float* __restrict__ part) {
    extern __shared__ char smem[];
    const uint32_t sbase = smem_u32(smem);
    const int tid = threadIdx.x;
    const int wid = tid >> 5;
    const int lane = tid & 31;
    const int wm = wid >> 1;
    const int wn = wid & 1;
    const int t0 = blockIdx.x * 128;
    const int kbase = blockIdx.y * 768;

    float acc[2][4][4];
#pragma unroll
    for (int mt = 0; mt < 2; mt++)
#pragma unroll
        for (int nt = 0; nt < 4; nt++)
#pragma unroll
            for (int r = 0; r < 4; r++) acc[mt][nt][r] = 0.f;

    auto load_stage = [&](int ci) {
        if (ci < 24) {
            uint32_t st = sbase + (ci & 3) * TSTAGE;
            int k0 = kbase + ci * 32;
#pragma unroll
            for (int i = 0; i < 5; i++) {
                int c = tid + i * 256;
                if (c < 1024) {
                    int pl = c >> 9, idx = c & 511;
                    int r = idx >> 2, k4 = idx & 3;
                    cp_async16(st + pl * TAPL + (uint32_t)r * 80 + k4 * 16,
                               (pl ? Glo : Ghi) + (size_t)(t0 + r) * QKVD + k0 + k4 * 8);
                } else {
                    int c2 = c - 1024;
                    int r = c2 >> 2, k4 = c2 & 3;
                    cp_async16(st + 2 * TAPL + (uint32_t)r * 80 + k4 * 16,
                               Twhi + (size_t)r * QKVD + k0 + k4 * 8);
                }
            }
        }
        CP_COMMIT();
    };

    load_stage(0); load_stage(1); load_stage(2);

    for (int ci = 0; ci < 24; ci++) {
        CP_WAIT(2);
        __syncthreads();
        load_stage(ci + 3);

        uint32_t st = sbase + (ci & 3) * TSTAGE;
        const int g = lane >> 3;
#pragma unroll
        for (int ks = 0; ks < 2; ks++) {
            uint32_t ah[2][4], al[2][4];
#pragma unroll
            for (int mt = 0; mt < 2; mt++) {
                uint32_t aoff = (uint32_t)(wm * 32 + mt * 16 + (lane & 15)) * 80
                                + ks * 32 + (lane >> 4) * 16;
                ldsm4(ah[mt], st + aoff);
                ldsm4(al[mt], st + TAPL + aoff);
            }
            uint32_t bh[2][4];
#pragma unroll
            for (int p = 0; p < 2; p++) {
                int row = wn * 32 + p * 16 + (g >> 1) * 8 + (lane & 7);
                uint32_t boff = (uint32_t)row * 80 + ks * 32 + (g & 1) * 16;
                ldsm4(bh[p], st + 2 * TAPL + boff);
            }
#pragma unroll
            for (int mt = 0; mt < 2; mt++)
#pragma unroll
                for (int p = 0; p < 2; p++)
#pragma unroll
                    for (int pt = 0; pt < 2; pt++)
                        mma16816(acc[mt][p * 2 + pt], ah[mt], &bh[p][pt * 2]);
#pragma unroll
            for (int mt = 0; mt < 2; mt++)
#pragma unroll
                for (int p = 0; p < 2; p++)
#pragma unroll
                    for (int pt = 0; pt < 2; pt++)
                        mma16816(acc[mt][p * 2 + pt], al[mt], &bh[p][pt * 2]);
        }
    }

    float* pb = part + (size_t)blockIdx.y * T_ * 64;
#pragma unroll
    for (int mt = 0; mt < 2; mt++) {
        int r0 = t0 + wm * 32 + mt * 16 + (lane >> 2);
#pragma unroll
        for (int nt = 0; nt < 4; nt++) {
            int c0 = wn * 32 + nt * 8 + (lane & 3) * 2;
            *(float2*)&pb[(size_t)r0 * 64 + c0]       = make_float2(acc[mt][nt][0], acc[mt][nt][1]);
            *(float2*)&pb[(size_t)(r0 + 8) * 64 + c0] = make_float2(acc[mt][nt][2], acc[mt][nt][3]);
        }
    }
}

// ================= prep (with fused tau finish) =================
#define QSCALE 0.18033688011112042f    // 0.125 * log2(e)

__global__ __launch_bounds__(256)
void prep_kernel(const float* __restrict__ qkv, const int* __restrict__ positions,
                 const float* __restrict__ part, const float* __restrict__ alpha,
                 __half* __restrict__ Qhi, __half* __restrict__ Qlo,
                 __half* __restrict__ Khi, __half* __restrict__ Vhi) {
    const int t = blockIdx.x;
    const float p = (float)positions[t];
    const float* row = qkv + (size_t)t * QKVD;

    __shared__ float stau[64];
    if (threadIdx.x < 64) {
        int o = threadIdx.x;
        float s = 0.f;
#pragma unroll
        for (int ks = 0; ks < 8; ks++) s += part[(size_t)ks * T_ * 64 + t * 64 + o];
        int hh = o & 31;
        float pl = logf(fmaxf(p + 1.0f, 1e-6f));
        float tp = 0.5f + 1.0f / (1.0f + expf(-alpha[hh] * pl));
        stau[o] = tanhf(s) + tp;
    }
    __syncthreads();

    for (int e = threadIdx.x; e < DIM_; e += 256) {
        int h = e >> 6;
        int d = e & 63;
        float tq = stau[h];
        float tv = stau[32 + h];

        float qo = row[e] * tq;
        float ko = row[DIM_ + e];
        float vo = row[2 * DIM_ + e] * tv;

        if (d < 32) {
            int i = (d < 16) ? d : (d - 16);
            float ang = p * exp2f(-(float)i * 1.2457230355827609f);
            float s, c;
            sincosf(ang, &s, &c);
            if (d < 16) {
                float q2 = row[e + 16] * tq;
                float k2 = row[DIM_ + e + 16];
                qo = qo * c - q2 * s;
                ko = ko * c - k2 * s;
            } else {
                float q1 = row[e - 16] * tq;
                float k1 = row[DIM_ + e - 16];
                qo = qo * c + q1 * s;
                ko = ko * c + k1 * s;
            }
        }
        qo *= QSCALE;
        size_t o = (size_t)h * T_ * HD + (size_t)t * HD + d;
        __half qh = __float2half_rn(qo);
        Qhi[o] = qh;
        Qlo[o] = __float2half_rn(qo - __half2float(qh));
        Khi[o] = __float2half_rn(ko);
        Vhi[o] = __float2half_rn(vo);
    }
}

// ================= HMMA fp16 2-term flash attention (reg-diet: paired operand batches) =================
#define FROW 144
#define FQL_OFF (128 * FROW)
#define FSTG0   (2 * 128 * FROW)
#define FSTG_BYTES (2 * 64 * FROW)
#define FKH 0
#define FVH (64 * FROW)
#define FLASH2_SMEM (FSTG0 + 4 * FSTG_BYTES)

__global__ __launch_bounds__(256, 2)
void flash_hmma_kernel(const __half* __restrict__ Qhi, const __half* __restrict__ Qlo,
                       const __half* __restrict__ Khi, const __half* __restrict__ Vhi,
                       __half* __restrict__ Ahi, __half* __restrict__ Alo) {
    extern __shared__ char smem[];
    const uint32_t sb = smem_u32(smem);
    const int tid = threadIdx.x;
    const int wid = tid >> 5;
    const int lane = tid & 31;
    const int h = blockIdx.y;
    const int qt = (int)gridDim.x - 1 - (int)blockIdx.x;
    const int q0 = qt * 128;
    const size_t hb = (size_t)h * T_ * HD;
    const int nkt = 2 * qt + 2;

#pragma unroll
    for (int i = 0; i < 8; i++) {
        int c = tid + i * 256;
        int pl = c >> 10;
        int r = (c >> 3) & 127;
        int k8 = c & 7;
        const __half* src = (pl ? Qlo : Qhi) + hb + (size_t)(q0 + r) * HD + k8 * 8;
        cp_async16(sb + pl * FQL_OFF + (uint32_t)r * FROW + k8 * 16, src);
    }
    CP_COMMIT();

    auto load_kv = [&](int kt) {
        if (kt < nkt) {
            uint32_t stg = sb + FSTG0 + (kt & 3) * FSTG_BYTES;
#pragma unroll
            for (int i = 0; i < 4; i++) {
                int c = tid + i * 256;
                int pl = c >> 9;
                int r = (c >> 3) & 63;
                int k8 = c & 7;
                const __half* base = pl ? Vhi : Khi;
                cp_async16(stg + pl * (64 * FROW) + (uint32_t)r * FROW + k8 * 16,
                           base + hb + (size_t)(kt * 64 + r) * HD + k8 * 8);
            }
        }
        CP_COMMIT();
    };
    load_kv(0); load_kv(1); load_kv(2);

    CP_WAIT(3);
    __syncthreads();

    const uint32_t qbase = sb + (uint32_t)(wid * 16 + (lane & 15)) * FROW + (lane >> 4) * 16;

    float m0 = -1e30f, m1 = -1e30f, l0 = 0.f, l1 = 0.f;
    float O[8][4];
#pragma unroll
    for (int nf = 0; nf < 8; nf++)
#pragma unroll
        for (int c = 0; c < 4; c++) O[nf][c] = 0.f;

    for (int kt = 0; kt < nkt; kt++) {
        CP_WAIT(2);
        __syncthreads();
        load_kv(kt + 3);

        const bool active = (kt * 64 <= q0 + wid * 16 + 15);
        const uint32_t stg = sb + FSTG0 + (kt & 3) * FSTG_BYTES;

        if (active) {
            float S[8][4];
#pragma unroll
            for (int nf = 0; nf < 8; nf++)
#pragma unroll
                for (int c = 0; c < 4; c++) S[nf][c] = 0.f;

            // ---- S = Q K^T : kp processed in pairs (bh peak 8 regs) ----
#pragma unroll
            for (int ks = 0; ks < 4; ks++) {
                uint32_t aqh[4], aql[4];
                ldsm4(aqh, qbase + ks * 32);
                ldsm4(aql, qbase + ks * 32 + FQL_OFF);
#pragma unroll
                for (int kg = 0; kg < 2; kg++) {
                    uint32_t bh[2][4];
#pragma unroll
                    for (int kp = 0; kp < 2; kp++) {
                        uint32_t ka = stg + (uint32_t)((kg * 2 + kp) * 16 + ((lane >> 4) << 3) + (lane & 7)) * FROW
                                      + ks * 32 + ((lane >> 3) & 1) * 16;
                        ldsm4(bh[kp], ka + FKH);
                    }
#pragma unroll
                    for (int kp = 0; kp < 2; kp++)
#pragma unroll
                        for (int half = 0; half < 2; half++)
                            mma16816(S[(kg * 2 + kp) * 2 + half], aqh, &bh[kp][half * 2]);
#pragma unroll
                    for (int kp = 0; kp < 2; kp++)
#pragma unroll
                        for (int half = 0; half < 2; half++)
                            mma16816(S[(kg * 2 + kp) * 2 + half], aql, &bh[kp][half * 2]);
                }
            }

            if (kt >= 2 * qt) {
                int rbase = q0 + wid * 16 + (lane >> 2);
                int cbase = kt * 64 + (lane & 3) * 2;
#pragma unroll
                for (int nf = 0; nf < 8; nf++)
#pragma unroll
                    for (int c = 0; c < 4; c++) {
                        int row = rbase + ((c >> 1) & 1) * 8;
                        int col = cbase + nf * 8 + (c & 1);
                        if (col > row) S[nf][c] = -1e30f;
                    }
            }

#pragma unroll
            for (int j = 0; j < 2; j++) {
                float& mj = j ? m1 : m0;
                float& lj = j ? l1 : l0;
                float rm = -1e30f;
#pragma unroll
                for (int nf = 0; nf < 8; nf++) {
                    rm = fmaxf(rm, S[nf][2 * j]);
                    rm = fmaxf(rm, S[nf][2 * j + 1]);
                }
                rm = fmaxf(rm, __shfl_xor_sync(0xffffffffu, rm, 1));
                rm = fmaxf(rm, __shfl_xor_sync(0xffffffffu, rm, 2));
                float mn = fmaxf(mj, rm);
                float alpha = ex2(mj - mn);
                float rs = 0.f;
#pragma unroll
                for (int nf = 0; nf < 8; nf++) {
                    float p0 = ex2(S[nf][2 * j] - mn);
                    float p1 = ex2(S[nf][2 * j + 1] - mn);
                    S[nf][2 * j] = p0; S[nf][2 * j + 1] = p1;
                    rs += p0 + p1;
                }
                lj = lj * alpha + rs;
                mj = mn;
#pragma unroll
                for (int nf = 0; nf < 8; nf++) {
                    O[nf][2 * j] *= alpha;
                    O[nf][2 * j + 1] *= alpha;
                }
            }

            // ---- O += P V : dp processed in pairs (vh peak 8 regs) ----
#pragma unroll
            for (int ks = 0; ks < 4; ks++) {
                uint32_t ah[4], al[4];
#pragma unroll
                for (int q = 0; q < 4; q++) {
                    int sf = 2 * ks + (q >> 1);
                    int c0 = (q & 1) * 2;
                    float p0 = S[sf][c0], p1 = S[sf][c0 + 1];
                    float h0 = __half2float(__float2half_rn(p0));
                    float h1 = __half2float(__float2half_rn(p1));
                    ah[q] = pack_h2(h0, h1);
                    al[q] = pack_h2(p0 - h0, p1 - h1);
                }
#pragma unroll
                for (int dg = 0; dg < 2; dg++) {
                    uint32_t vh[2][4];
#pragma unroll
                    for (int dp = 0; dp < 2; dp++) {
                        uint32_t va = stg + (uint32_t)(ks * 16 + ((lane >> 3) & 1) * 8 + (lane & 7)) * FROW
                                      + (dg * 2 + dp) * 32 + (lane >> 4) * 16;
                        ldsm4t(vh[dp], va + FVH);
                    }
#pragma unroll
                    for (int dp = 0; dp < 2; dp++) {
                        int od = (dg * 2 + dp) * 2;
                        mma16816(O[od],     ah, &vh[dp][0]);
                        mma16816(O[od + 1], ah, &vh[dp][2]);
                    }
#pragma unroll
                    for (int dp = 0; dp < 2; dp++) {
                        int od = (dg * 2 + dp) * 2;
                        mma16816(O[od],     al, &vh[dp][0]);
                        mma16816(O[od + 1], al, &vh[dp][2]);
                    }
                }
            }
        }
    }

    l0 += __shfl_xor_sync(0xffffffffu, l0, 1);
    l0 += __shfl_xor_sync(0xffffffffu, l0, 2);
    l1 += __shfl_xor_sync(0xffffffffu, l1, 1);
    l1 += __shfl_xor_sync(0xffffffffu, l1, 2);

    float inv0 = 1.0f / l0;
    float inv1 = 1.0f / l1;
    int r0 = q0 + wid * 16 + (lane >> 2);
#pragma unroll
    for (int nf = 0; nf < 8; nf++)
#pragma unroll
        for (int j = 0; j < 2; j++) {
            float inv = j ? inv1 : inv0;
            float v0 = O[nf][2 * j] * inv;
            float v1 = O[nf][2 * j + 1] * inv;
            int t = r0 + j * 8;
            int col = h * 64 + nf * 8 + (lane & 3) * 2;
            float h0 = __half2float(__float2half_rn(v0));
            float h1 = __half2float(__float2half_rn(v1));
            *(uint32_t*)&Ahi[(size_t)t * DIM_ + col] = pack_h2(h0, h1);
            *(uint32_t*)&Alo[(size_t)t * DIM_ + col] = pack_h2(v0 - h0, v1 - h1);
        }
}

// ================= host launch =================
extern "C" void kernel_launch(void* const* d_in, const int* in_sizes, int n_in,
                              void* d_out, int out_size) {
    const int*   positions = (const int*)d_in[0];
    const float* hidden    = (const float*)d_in[1];
    const float* Wqkv      = (const float*)d_in[2];
    const float* bqkv      = (const float*)d_in[3];
    const float* Wout      = (const float*)d_in[4];
    const float* bout      = (const float*)d_in[5];
    const float* tau_alpha = (const float*)d_in[6];
    const float* tau_wq    = (const float*)d_in[7];
    const float* tau_wv    = (const float*)d_in[8];
    float* out = (float*)d_out;

    float *qkv, *taupart;
    __half *Ahi, *Alo, *Whi, *Ghi, *Glo, *Twhi, *Qhi, *Qlo, *Khi, *Vhi;
    cudaGetSymbolAddress((void**)&qkv,     g_qkv);
    cudaGetSymbolAddress((void**)&taupart, g_taupart);
    cudaGetSymbolAddress((void**)&Ahi,     g_Ahi);
    cudaGetSymbolAddress((void**)&Alo,     g_Alo);
    cudaGetSymbolAddress((void**)&Whi,     g_Whi);
    cudaGetSymbolAddress((void**)&Ghi,     g_Ghi);
    cudaGetSymbolAddress((void**)&Glo,     g_Glo);
    cudaGetSymbolAddress((void**)&Twhi,    g_Twhi);
    cudaGetSymbolAddress((void**)&Qhi,     g_Qhi);
    cudaGetSymbolAddress((void**)&Qlo,     g_Qlo);
    cudaGetSymbolAddress((void**)&Khi,     g_Khi);
    cudaGetSymbolAddress((void**)&Vhi,     g_Vhi);

    cudaFuncSetAttribute(gemm_hmma_kernel, cudaFuncAttributeMaxDynamicSharedMemorySize, GSMEM);
    cudaFuncSetAttribute(tau_hmma_kernel, cudaFuncAttributeMaxDynamicSharedMemorySize, TSMEM);
    cudaFuncSetAttribute(flash_hmma_kernel, cudaFuncAttributeMaxDynamicSharedMemorySize, FLASH2_SMEM);

    decomp_kernel<<<(T_ * DIM_ / 4 + 255) / 256, 256>>>(hidden, Ahi, Alo, T_ * DIM_ / 4);
    decomp1_kernel<<<(QKVD * DIM_ / 4 + 255) / 256, 256>>>(Wqkv, Whi, QKVD * DIM_ / 4);
    decomp1_kernel<<<(32 * QKVD / 4 + 255) / 256, 256>>>(tau_wq, Twhi, 32 * QKVD / 4);
    decomp1_kernel<<<(32 * QKVD / 4 + 255) / 256, 256>>>(tau_wv, Twhi + 32 * QKVD, 32 * QKVD / 4);
    gemm_hmma_kernel<<<dim3(QKVD / 128, T_ / 128), 256, GSMEM>>>(
        Ahi, Alo, Whi, bqkv, qkv, Ghi, Glo, QKVD, DIM_, DIM_);
    tau_hmma_kernel<<<dim3(T_ / 128, 8), 256, TSMEM>>>(Ghi, Glo, Twhi, taupart);
    prep_kernel<<<T_, 256>>>(qkv, positions, taupart, tau_alpha, Qhi, Qlo, Khi, Vhi);
    flash_hmma_kernel<<<dim3(T_ / 128, NH), 256, FLASH2_SMEM>>>(
        Qhi, Qlo, Khi, Vhi, Ahi, Alo);
    decomp1_kernel<<<(DIM_ * DIM_ / 4 + 255) / 256, 256>>>(Wout, Whi, DIM_ * DIM_ / 4);
    gemm_hmma_kernel<<<dim3(DIM_ / 128, T_ / 128), 256, GSMEM>>>(
        Ahi, Alo, Whi, bout, out, nullptr, nullptr, DIM_, DIM_, DIM_);
}

// round 16
// speedup vs baseline: 1.6814x; 1.0205x over previous
#include <cuda_runtime.h>
#include <cuda_fp16.h>
#include <math.h>
#include <stdint.h>

#define T_ 2048
#define DIM_ 2048
#define NH 32
#define HD 64
#define QKVD 6144

// ---------------- scratch ----------------
__device__ float g_qkv[T_ * QKVD];
__device__ float g_taupart[8 * T_ * 64];
__device__ float g_Opart[2 * T_ * DIM_];      // un-normalized O per split
__device__ float g_mpart[2 * NH * T_];
__device__ float g_lpart[2 * NH * T_];
__device__ __half g_Ahi[T_ * DIM_];
__device__ __half g_Alo[T_ * DIM_];
__device__ __half g_Whi[QKVD * DIM_];
__device__ __half g_Ghi[T_ * QKVD];
__device__ __half g_Glo[T_ * QKVD];
__device__ __half g_Twhi[64 * QKVD];
__device__ __half g_Qhi[NH * T_ * HD];
__device__ __half g_Qlo[NH * T_ * HD];
__device__ __half g_Khi[NH * T_ * HD];
__device__ __half g_Vhi[NH * T_ * HD];

// ================= helpers =================
__device__ __forceinline__ uint32_t smem_u32(const void* p) {
    uint32_t a;
    asm("{ .reg .u64 t; cvta.to.shared.u64 t, %1; cvt.u32.u64 %0, t; }" : "=r"(a) : "l"(p));
    return a;
}
__device__ __forceinline__ void ldsm4(uint32_t* r, uint32_t addr) {
    asm volatile("ldmatrix.sync.aligned.m8n8.x4.shared.b16 {%0,%1,%2,%3}, [%4];"
        : "=r"(r[0]), "=r"(r[1]), "=r"(r[2]), "=r"(r[3]) : "r"(addr));
}
__device__ __forceinline__ void ldsm4t(uint32_t* r, uint32_t addr) {
    asm volatile("ldmatrix.sync.aligned.m8n8.x4.trans.shared.b16 {%0,%1,%2,%3}, [%4];"
        : "=r"(r[0]), "=r"(r[1]), "=r"(r[2]), "=r"(r[3]) : "r"(addr));
}
__device__ __forceinline__ void mma16816(float* d, const uint32_t* a, const uint32_t* b) {
    asm volatile("mma.sync.aligned.m16n8k16.row.col.f32.f16.f16.f32 "
        "{%0,%1,%2,%3}, {%4,%5,%6,%7}, {%8,%9}, {%0,%1,%2,%3};"
        : "+f"(d[0]), "+f"(d[1]), "+f"(d[2]), "+f"(d[3])
        : "r"(a[0]), "r"(a[1]), "r"(a[2]), "r"(a[3]), "r"(b[0]), "r"(b[1]));
}
__device__ __forceinline__ void cp_async16(uint32_t dst, const void* src) {
    asm volatile("cp.async.cg.shared.global [%0], [%1], 16;" :: "r"(dst), "l"(src) : "memory");
}
#define CP_COMMIT() asm volatile("cp.async.commit_group;" ::: "memory")
#define CP_WAIT(n)  asm volatile("cp.async.wait_group %0;" :: "n"(n) : "memory")

__device__ __forceinline__ uint32_t pack_h2(float lo, float hi) {
    __half2 t = __floats2half2_rn(lo, hi);
    return *reinterpret_cast<uint32_t*>(&t);
}
__device__ __forceinline__ float ex2(float x) {
    float y;
    asm("ex2.approx.f32 %0, %1;" : "=f"(y) : "f"(x));
    return y;
}

// ================= split-fp16 decomposition =================
__global__ __launch_bounds__(256)
void decomp_kernel(const float* __restrict__ in, __half* __restrict__ hi,
                   __half* __restrict__ lo, int n4) {
    int i = blockIdx.x * 256 + threadIdx.x;
    if (i >= n4) return;
    float4 v = ((const float4*)in)[i];
    __half h0 = __float2half_rn(v.x);
    __half h1 = __float2half_rn(v.y);
    __half h2 = __float2half_rn(v.z);
    __half h3 = __float2half_rn(v.w);
    ((__half2*)hi)[i * 2 + 0] = __halves2half2(h0, h1);
    ((__half2*)hi)[i * 2 + 1] = __halves2half2(h2, h3);
    ((__half2*)lo)[i * 2 + 0] = __floats2half2_rn(v.x - __half2float(h0), v.y - __half2float(h1));
    ((__half2*)lo)[i * 2 + 1] = __floats2half2_rn(v.z - __half2float(h2), v.w - __half2float(h3));
}

__global__ __launch_bounds__(256)
void decomp1_kernel(const float* __restrict__ in, __half* __restrict__ hi, int n4) {
    int i = blockIdx.x * 256 + threadIdx.x;
    if (i >= n4) return;
    float4 v = ((const float4*)in)[i];
    ((__half2*)hi)[i * 2 + 0] = __floats2half2_rn(v.x, v.y);
    ((__half2*)hi)[i * 2 + 1] = __floats2half2_rn(v.z, v.w);
}

// ================= HMMA fp16 GEMM, column-dependent term count =================
#define MAT_BYTES  (128 * 80)
#define STAGE_BYTES (3 * MAT_BYTES)
#define GSMEM (3 * STAGE_BYTES)

__global__ __launch_bounds__(256, 2)
void gemm_hmma_kernel(const __half* __restrict__ Ahi, const __half* __restrict__ Alo,
                      const __half* __restrict__ Bhi,
                      const float* __restrict__ bias, float* __restrict__ C,
                      __half* __restrict__ Ghi, __half* __restrict__ Glo,
                      int N, int K, int n_2term) {
    extern __shared__ char smem[];
    const uint32_t sbase = smem_u32(smem);
    const int tid = threadIdx.x;
    const int wid = tid >> 5;
    const int lane = tid & 31;
    const int wm = wid >> 2;
    const int wn = wid & 3;
    const int bx = blockIdx.x, by = blockIdx.y;
    const int nch = K / 32;
    const bool two_term = (bx * 128) < n_2term;

    float acc[4][4][4];
#pragma unroll
    for (int mt = 0; mt < 4; mt++)
#pragma unroll
        for (int nt = 0; nt < 4; nt++)
#pragma unroll
            for (int r = 0; r < 4; r++) acc[mt][nt][r] = 0.f;

    auto load_stage = [&](int ci) {
        if (ci < nch) {
            uint32_t st = sbase + (ci % 3) * STAGE_BYTES;
            int k0 = ci * 32;
#pragma unroll
            for (int i = 0; i < 6; i++) {
                int c = tid + i * 256;
                int pl = c / 512;
                int idx = c & 511;
                int row = idx >> 2, k4 = idx & 3;
                uint32_t so = (uint32_t)row * 80 + k4 * 16;
                if (pl == 0)
                    cp_async16(st + so, Ahi + (size_t)(by * 128 + row) * K + k0 + k4 * 8);
                else if (pl == 1) {
                    if (two_term)
                        cp_async16(st + MAT_BYTES + so, Alo + (size_t)(by * 128 + row) * K + k0 + k4 * 8);
                } else
                    cp_async16(st + 2 * MAT_BYTES + so, Bhi + (size_t)(bx * 128 + row) * K + k0 + k4 * 8);
            }
        }
        CP_COMMIT();
    };

    load_stage(0); load_stage(1);

    for (int ci = 0; ci < nch; ci++) {
        CP_WAIT(1);
        __syncthreads();

        uint32_t st = sbase + (ci % 3) * STAGE_BYTES;
        uint32_t aHi = st, aLo = st + MAT_BYTES, bHi = st + 2 * MAT_BYTES;
        const int g = lane >> 3;

#pragma unroll
        for (int ks = 0; ks < 2; ks++) {
            uint32_t ah[4][4], al[4][4];
#pragma unroll
            for (int mt = 0; mt < 4; mt++) {
                uint32_t aoff = (uint32_t)(wm * 64 + mt * 16 + (lane & 15)) * 80
                                + ks * 32 + (lane >> 4) * 16;
                ldsm4(ah[mt], aHi + aoff);
                if (two_term) ldsm4(al[mt], aLo + aoff);
            }
            uint32_t bh[2][4];
#pragma unroll
            for (int p = 0; p < 2; p++) {
                int row = wn * 32 + p * 16 + (g >> 1) * 8 + (lane & 7);
                uint32_t boff = (uint32_t)row * 80 + ks * 32 + (g & 1) * 16;
                ldsm4(bh[p], bHi + boff);
            }
#pragma unroll
            for (int mt = 0; mt < 4; mt++)
#pragma unroll
                for (int p = 0; p < 2; p++)
#pragma unroll
                    for (int pt = 0; pt < 2; pt++)
                        mma16816(acc[mt][p * 2 + pt], ah[mt], &bh[p][pt * 2]);
            if (two_term) {
#pragma unroll
                for (int mt = 0; mt < 4; mt++)
#pragma unroll
                    for (int p = 0; p < 2; p++)
#pragma unroll
                        for (int pt = 0; pt < 2; pt++)
                            mma16816(acc[mt][p * 2 + pt], al[mt], &bh[p][pt * 2]);
            }
        }
        __syncthreads();
        load_stage(ci + 2);
    }

    const bool do_gelu = (Ghi != nullptr);
#pragma unroll
    for (int mt = 0; mt < 4; mt++) {
        int r0 = by * 128 + wm * 64 + mt * 16 + (lane >> 2);
#pragma unroll
        for (int nt = 0; nt < 4; nt++) {
            int c0 = bx * 128 + wn * 32 + nt * 8 + (lane & 3) * 2;
            float b0 = bias[c0], b1 = bias[c0 + 1];
#pragma unroll
            for (int rr = 0; rr < 2; rr++) {
                int r = r0 + rr * 8;
                float v0 = acc[mt][nt][rr * 2 + 0] + b0;
                float v1 = acc[mt][nt][rr * 2 + 1] + b1;
                *(float2*)&C[(size_t)r * N + c0] = make_float2(v0, v1);
                if (do_gelu) {
                    float g0 = 0.5f * v0 * (1.0f + erff(v0 * 0.70710678118654752f));
                    float g1 = 0.5f * v1 * (1.0f + erff(v1 * 0.70710678118654752f));
                    float h0 = __half2float(__float2half_rn(g0));
                    float h1 = __half2float(__float2half_rn(g1));
                    *(uint32_t*)&Ghi[(size_t)r * N + c0] = pack_h2(h0, h1);
                    *(uint32_t*)&Glo[(size_t)r * N + c0] = pack_h2(g0 - h0, g1 - h1);
                }
            }
        }
    }
}

// ================= tau: HMMA fp16 2-term split-K GEMM =================
#define TAPL 10240
#define TBPL 5120
#define TSTAGE (2 * TAPL + TBPL)
#define TSMEM (4 * TSTAGE)

__global__ __launch_bounds__(256, 2)
void tau_hmma_kernel(const __half* __restrict__ Ghi, const __half* __restrict__ Glo,
                     const __half* __restrict__ Twhi,
                     float* __restrict__ part) {
    extern __shared__ char smem[];
    const uint32_t sbase = smem_u32(smem);
    const int tid = threadIdx.x;
    const int wid = tid >> 5;
    const int lane = tid & 31;
    const int wm = wid >> 1;
    const int wn = wid & 1;
    const int t0 = blockIdx.x * 128;
    const int kbase = blockIdx.y * 768;

    float acc[2][4][4];
#pragma unroll
    for (int mt = 0; mt < 2; mt++)
#pragma unroll
        for (int nt = 0; nt < 4; nt++)
#pragma unroll
            for (int r = 0; r < 4; r++) acc[mt][nt][r] = 0.f;

    auto load_stage = [&](int ci) {
        if (ci < 24) {
            uint32_t st = sbase + (ci & 3) * TSTAGE;
            int k0 = kbase + ci * 32;
#pragma unroll
            for (int i = 0; i < 5; i++) {
                int c = tid + i * 256;
                if (c < 1024) {
                    int pl = c >> 9, idx = c & 511;
                    int r = idx >> 2, k4 = idx & 3;
                    cp_async16(st + pl * TAPL + (uint32_t)r * 80 + k4 * 16,
                               (pl ? Glo : Ghi) + (size_t)(t0 + r) * QKVD + k0 + k4 * 8);
                } else {
                    int c2 = c - 1024;
                    int r = c2 >> 2, k4 = c2 & 3;
                    cp_async16(st + 2 * TAPL + (uint32_t)r * 80 + k4 * 16,
                               Twhi + (size_t)r * QKVD + k0 + k4 * 8);
                }
            }
        }
        CP_COMMIT();
    };

    load_stage(0); load_stage(1); load_stage(2);

    for (int ci = 0; ci < 24; ci++) {
        CP_WAIT(2);
        __syncthreads();
        load_stage(ci + 3);

        uint32_t st = sbase + (ci & 3) * TSTAGE;
        const int g = lane >> 3;
#pragma unroll
        for (int ks = 0; ks < 2; ks++) {
            uint32_t ah[2][4], al[2][4];
#pragma unroll
            for (int mt = 0; mt < 2; mt++) {
                uint32_t aoff = (uint32_t)(wm * 32 + mt * 16 + (lane & 15)) * 80
                                + ks * 32 + (lane >> 4) * 16;
                ldsm4(ah[mt], st + aoff);
                ldsm4(al[mt], st + TAPL + aoff);
            }
            uint32_t bh[2][4];
#pragma unroll
            for (int p = 0; p < 2; p++) {
                int row = wn * 32 + p * 16 + (g >> 1) * 8 + (lane & 7);
                uint32_t boff = (uint32_t)row * 80 + ks * 32 + (g & 1) * 16;
                ldsm4(bh[p], st + 2 * TAPL + boff);
            }
#pragma unroll
            for (int mt = 0; mt < 2; mt++)
#pragma unroll
                for (int p = 0; p < 2; p++)
#pragma unroll
                    for (int pt = 0; pt < 2; pt++)
                        mma16816(acc[mt][p * 2 + pt], ah[mt], &bh[p][pt * 2]);
#pragma unroll
            for (int mt = 0; mt < 2; mt++)
#pragma unroll
                for (int p = 0; p < 2; p++)
#pragma unroll
                    for (int pt = 0; pt < 2; pt++)
                        mma16816(acc[mt][p * 2 + pt], al[mt], &bh[p][pt * 2]);
        }
    }

    float* pb = part + (size_t)blockIdx.y * T_ * 64;
#pragma unroll
    for (int mt = 0; mt < 2; mt++) {
        int r0 = t0 + wm * 32 + mt * 16 + (lane >> 2);
#pragma unroll
        for (int nt = 0; nt < 4; nt++) {
            int c0 = wn * 32 + nt * 8 + (lane & 3) * 2;
            *(float2*)&pb[(size_t)r0 * 64 + c0]       = make_float2(acc[mt][nt][0], acc[mt][nt][1]);
            *(float2*)&pb[(size_t)(r0 + 8) * 64 + c0] = make_float2(acc[mt][nt][2], acc[mt][nt][3]);
        }
    }
}

// ================= prep (with fused tau finish) =================
#define QSCALE 0.18033688011112042f    // 0.125 * log2(e)

__global__ __launch_bounds__(256)
void prep_kernel(const float* __restrict__ qkv, const int* __restrict__ positions,
                 const float* __restrict__ part, const float* __restrict__ alpha,
                 __half* __restrict__ Qhi, __half* __restrict__ Qlo,
                 __half* __restrict__ Khi, __half* __restrict__ Vhi) {
    const int t = blockIdx.x;
    const float p = (float)positions[t];
    const float* row = qkv + (size_t)t * QKVD;

    __shared__ float stau[64];
    if (threadIdx.x < 64) {
        int o = threadIdx.x;
        float s = 0.f;
#pragma unroll
        for (int ks = 0; ks < 8; ks++) s += part[(size_t)ks * T_ * 64 + t * 64 + o];
        int hh = o & 31;
        float pl = logf(fmaxf(p + 1.0f, 1e-6f));
        float tp = 0.5f + 1.0f / (1.0f + expf(-alpha[hh] * pl));
        stau[o] = tanhf(s) + tp;
    }
    __syncthreads();

    for (int e = threadIdx.x; e < DIM_; e += 256) {
        int h = e >> 6;
        int d = e & 63;
        float tq = stau[h];
        float tv = stau[32 + h];

        float qo = row[e] * tq;
        float ko = row[DIM_ + e];
        float vo = row[2 * DIM_ + e] * tv;

        if (d < 32) {
            int i = (d < 16) ? d : (d - 16);
            float ang = p * exp2f(-(float)i * 1.2457230355827609f);
            float s, c;
            sincosf(ang, &s, &c);
            if (d < 16) {
                float q2 = row[e + 16] * tq;
                float k2 = row[DIM_ + e + 16];
                qo = qo * c - q2 * s;
                ko = ko * c - k2 * s;
            } else {
                float q1 = row[e - 16] * tq;
                float k1 = row[DIM_ + e - 16];
                qo = qo * c + q1 * s;
                ko = ko * c + k1 * s;
            }
        }
        qo *= QSCALE;
        size_t o = (size_t)h * T_ * HD + (size_t)t * HD + d;
        __half qh = __float2half_rn(qo);
        Qhi[o] = qh;
        Qlo[o] = __float2half_rn(qo - __half2float(qh));
        Khi[o] = __float2half_rn(ko);
        Vhi[o] = __float2half_rn(vo);
    }
}

// ================= HMMA fp16 flash attention, split-KV (z = 0/1 halves) =================
#define FROW 144
#define FQL_OFF (128 * FROW)
#define FSTG0   (2 * 128 * FROW)
#define FSTG_BYTES (2 * 64 * FROW)
#define FKH 0
#define FVH (64 * FROW)
#define FLASH2_SMEM (FSTG0 + 4 * FSTG_BYTES)

__global__ __launch_bounds__(256, 2)
void flash_hmma_kernel(const __half* __restrict__ Qhi, const __half* __restrict__ Qlo,
                       const __half* __restrict__ Khi, const __half* __restrict__ Vhi,
                       float* __restrict__ Opart, float* __restrict__ mpart,
                       float* __restrict__ lpart) {
    extern __shared__ char smem[];
    const uint32_t sb = smem_u32(smem);
    const int tid = threadIdx.x;
    const int wid = tid >> 5;
    const int lane = tid & 31;
    const int h = blockIdx.y;
    const int z = blockIdx.z;
    const int qt = (int)gridDim.x - 1 - (int)blockIdx.x;   // long blocks first
    const int q0 = qt * 128;
    const size_t hb = (size_t)h * T_ * HD;
    const int kbeg = z ? (qt + 1) : 0;
    const int kend = z ? (2 * qt + 2) : (qt + 1);

#pragma unroll
    for (int i = 0; i < 8; i++) {
        int c = tid + i * 256;
        int pl = c >> 10;
        int r = (c >> 3) & 127;
        int k8 = c & 7;
        const __half* src = (pl ? Qlo : Qhi) + hb + (size_t)(q0 + r) * HD + k8 * 8;
        cp_async16(sb + pl * FQL_OFF + (uint32_t)r * FROW + k8 * 16, src);
    }
    CP_COMMIT();

    auto load_kv = [&](int kt) {
        if (kt < kend) {
            uint32_t stg = sb + FSTG0 + (kt & 3) * FSTG_BYTES;
#pragma unroll
            for (int i = 0; i < 4; i++) {
                int c = tid + i * 256;
                int pl = c >> 9;
                int r = (c >> 3) & 63;
                int k8 = c & 7;
                const __half* base = pl ? Vhi : Khi;
                cp_async16(stg + pl * (64 * FROW) + (uint32_t)r * FROW + k8 * 16,
                           base + hb + (size_t)(kt * 64 + r) * HD + k8 * 8);
            }
        }
        CP_COMMIT();
    };
    load_kv(kbeg); load_kv(kbeg + 1); load_kv(kbeg + 2);

    CP_WAIT(3);
    __syncthreads();

    const uint32_t qbase = sb + (uint32_t)(wid * 16 + (lane & 15)) * FROW + (lane >> 4) * 16;

    float m0 = -1e30f, m1 = -1e30f, l0 = 0.f, l1 = 0.f;
    float O[8][4];
#pragma unroll
    for (int nf = 0; nf < 8; nf++)
#pragma unroll
        for (int c = 0; c < 4; c++) O[nf][c] = 0.f;

    for (int kt = kbeg; kt < kend; kt++) {
        CP_WAIT(2);
        __syncthreads();
        load_kv(kt + 3);

        const bool active = (kt * 64 <= q0 + wid * 16 + 15);
        const uint32_t stg = sb + FSTG0 + (kt & 3) * FSTG_BYTES;

        if (active) {
            float S[8][4];
#pragma unroll
            for (int nf = 0; nf < 8; nf++)
#pragma unroll
                for (int c = 0; c < 4; c++) S[nf][c] = 0.f;

#pragma unroll
            for (int ks = 0; ks < 4; ks++) {
                uint32_t aqh[4], aql[4];
                ldsm4(aqh, qbase + ks * 32);
                ldsm4(aql, qbase + ks * 32 + FQL_OFF);
#pragma unroll
                for (int kg = 0; kg < 2; kg++) {
                    uint32_t bh[2][4];
#pragma unroll
                    for (int kp = 0; kp < 2; kp++) {
                        uint32_t ka = sb + FSTG0 + (kt & 3) * FSTG_BYTES
                                      + (uint32_t)((kg * 2 + kp) * 16 + ((lane >> 4) << 3) + (lane & 7)) * FROW
                                      + ks * 32 + ((lane >> 3) & 1) * 16;
                        ldsm4(bh[kp], ka + FKH);
                    }
#pragma unroll
                    for (int kp = 0; kp < 2; kp++)
#pragma unroll
                        for (int half = 0; half < 2; half++)
                            mma16816(S[(kg * 2 + kp) * 2 + half], aqh, &bh[kp][half * 2]);
#pragma unroll
                    for (int kp = 0; kp < 2; kp++)
#pragma unroll
                        for (int half = 0; half < 2; half++)
                            mma16816(S[(kg * 2 + kp) * 2 + half], aql, &bh[kp][half * 2]);
                }
            }

            if (kt >= 2 * qt) {
                int rbase = q0 + wid * 16 + (lane >> 2);
                int cbase = kt * 64 + (lane & 3) * 2;
#pragma unroll
                for (int nf = 0; nf < 8; nf++)
#pragma unroll
                    for (int c = 0; c < 4; c++) {
                        int row = rbase + ((c >> 1) & 1) * 8;
                        int col = cbase + nf * 8 + (c & 1);
                        if (col > row) S[nf][c] = -1e30f;
                    }
            }

#pragma unroll
            for (int j = 0; j < 2; j++) {
                float& mj = j ? m1 : m0;
                float& lj = j ? l1 : l0;
                float rm = -1e30f;
#pragma unroll
                for (int nf = 0; nf < 8; nf++) {
                    rm = fmaxf(rm, S[nf][2 * j]);
                    rm = fmaxf(rm, S[nf][2 * j + 1]);
                }
                rm = fmaxf(rm, __shfl_xor_sync(0xffffffffu, rm, 1));
                rm = fmaxf(rm, __shfl_xor_sync(0xffffffffu, rm, 2));
                float mn = fmaxf(mj, rm);
                float alpha = ex2(mj - mn);
                float rs = 0.f;
#pragma unroll
                for (int nf = 0; nf < 8; nf++) {
                    float p0 = ex2(S[nf][2 * j] - mn);
                    float p1 = ex2(S[nf][2 * j + 1] - mn);
                    S[nf][2 * j] = p0; S[nf][2 * j + 1] = p1;
                    rs += p0 + p1;
                }
                lj = lj * alpha + rs;
                mj = mn;
#pragma unroll
                for (int nf = 0; nf < 8; nf++) {
                    O[nf][2 * j] *= alpha;
                    O[nf][2 * j + 1] *= alpha;
                }
            }

#pragma unroll
            for (int ks = 0; ks < 4; ks++) {
                uint32_t ah[4], al[4];
#pragma unroll
                for (int q = 0; q < 4; q++) {
                    int sf = 2 * ks + (q >> 1);
                    int c0 = (q & 1) * 2;
                    float p0 = S[sf][c0], p1 = S[sf][c0 + 1];
                    float h0 = __half2float(__float2half_rn(p0));
                    float h1 = __half2float(__float2half_rn(p1));
                    ah[q] = pack_h2(h0, h1);
                    al[q] = pack_h2(p0 - h0, p1 - h1);
                }
#pragma unroll
                for (int dg = 0; dg < 2; dg++) {
                    uint32_t vh[2][4];
#pragma unroll
                    for (int dp = 0; dp < 2; dp++) {
                        uint32_t va = stg + (uint32_t)(ks * 16 + ((lane >> 3) & 1) * 8 + (lane & 7)) * FROW
                                      + (dg * 2 + dp) * 32 + (lane >> 4) * 16;
                        ldsm4t(vh[dp], va + FVH);
                    }
#pragma unroll
                    for (int dp = 0; dp < 2; dp++) {
                        int od = (dg * 2 + dp) * 2;
                        mma16816(O[od],     ah, &vh[dp][0]);
                        mma16816(O[od + 1], ah, &vh[dp][2]);
                    }
#pragma unroll
                    for (int dp = 0; dp < 2; dp++) {
                        int od = (dg * 2 + dp) * 2;
                        mma16816(O[od],     al, &vh[dp][0]);
                        mma16816(O[od + 1], al, &vh[dp][2]);
                    }
                }
            }
        }
    }

    // cross-thread l reduce (row quads differ in lane bits 0,1)
    l0 += __shfl_xor_sync(0xffffffffu, l0, 1);
    l0 += __shfl_xor_sync(0xffffffffu, l0, 2);
    l1 += __shfl_xor_sync(0xffffffffu, l1, 1);
    l1 += __shfl_xor_sync(0xffffffffu, l1, 2);

    // write un-normalized partials
    float* Oz = Opart + (size_t)z * T_ * DIM_;
    int r0 = q0 + wid * 16 + (lane >> 2);
#pragma unroll
    for (int nf = 0; nf < 8; nf++)
#pragma unroll
        for (int j = 0; j < 2; j++) {
            int t = r0 + j * 8;
            int col = h * 64 + nf * 8 + (lane & 3) * 2;
            *(float2*)&Oz[(size_t)t * DIM_ + col] =
                make_float2(O[nf][2 * j], O[nf][2 * j + 1]);
        }
    if ((lane & 3) == 0) {
        size_t mb = (size_t)z * NH * T_ + (size_t)h * T_;
        mpart[mb + r0]     = m0;
        lpart[mb + r0]     = l0;
        mpart[mb + r0 + 8] = m1;
        lpart[mb + r0 + 8] = l1;
    }
}

// ================= combine: merge the two KV splits =================
__global__ __launch_bounds__(256)
void combine_kernel(const float* __restrict__ Opart, const float* __restrict__ mpart,
                    const float* __restrict__ lpart,
                    __half* __restrict__ Ahi, __half* __restrict__ Alo) {
    const int t = blockIdx.x;
    const int tid = threadIdx.x;
    const int h = tid >> 3;                 // 8 threads per head
    const int c0 = tid * 8;                 // 8 contiguous cols per thread

    size_t mb0 = (size_t)h * T_ + t;
    size_t mb1 = (size_t)NH * T_ + mb0;
    float m0 = mpart[mb0], l0 = lpart[mb0];
    float m1 = mpart[mb1], l1 = lpart[mb1];
    float m = fmaxf(m0, m1);
    float e0 = ex2(m0 - m), e1 = ex2(m1 - m);
    float L = l0 * e0 + l1 * e1;
    float w0 = e0 / L, w1 = e1 / L;

    const float* O0 = Opart + (size_t)t * DIM_ + c0;
    const float* O1 = Opart + (size_t)T_ * DIM_ + (size_t)t * DIM_ + c0;
#pragma unroll
    for (int i = 0; i < 8; i += 2) {
        float v0 = O0[i]     * w0 + O1[i]     * w1;
        float v1 = O0[i + 1] * w0 + O1[i + 1] * w1;
        float h0 = __half2float(__float2half_rn(v0));
        float h1 = __half2float(__float2half_rn(v1));
        *(uint32_t*)&Ahi[(size_t)t * DIM_ + c0 + i] = pack_h2(h0, h1);
        *(uint32_t*)&Alo[(size_t)t * DIM_ + c0 + i] = pack_h2(v0 - h0, v1 - h1);
    }
}

// ================= host launch =================
extern "C" void kernel_launch(void* const* d_in, const int* in_sizes, int n_in,
                              void* d_out, int out_size) {
    const int*   positions = (const int*)d_in[0];
    const float* hidden    = (const float*)d_in[1];
    const float* Wqkv      = (const float*)d_in[2];
    const float* bqkv      = (const float*)d_in[3];
    const float* Wout      = (const float*)d_in[4];
    const float* bout      = (const float*)d_in[5];
    const float* tau_alpha = (const float*)d_in[6];
    const float* tau_wq    = (const float*)d_in[7];
    const float* tau_wv    = (const float*)d_in[8];
    float* out = (float*)d_out;

    float *qkv, *taupart, *Opart, *mpart, *lpart;
    __half *Ahi, *Alo, *Whi, *Ghi, *Glo, *Twhi, *Qhi, *Qlo, *Khi, *Vhi;
    cudaGetSymbolAddress((void**)&qkv,     g_qkv);
    cudaGetSymbolAddress((void**)&taupart, g_taupart);
    cudaGetSymbolAddress((void**)&Opart,   g_Opart);
    cudaGetSymbolAddress((void**)&mpart,   g_mpart);
    cudaGetSymbolAddress((void**)&lpart,   g_lpart);
    cudaGetSymbolAddress((void**)&Ahi,     g_Ahi);
    cudaGetSymbolAddress((void**)&Alo,     g_Alo);
    cudaGetSymbolAddress((void**)&Whi,     g_Whi);
    cudaGetSymbolAddress((void**)&Ghi,     g_Ghi);
    cudaGetSymbolAddress((void**)&Glo,     g_Glo);
    cudaGetSymbolAddress((void**)&Twhi,    g_Twhi);
    cudaGetSymbolAddress((void**)&Qhi,     g_Qhi);
    cudaGetSymbolAddress((void**)&Qlo,     g_Qlo);
    cudaGetSymbolAddress((void**)&Khi,     g_Khi);
    cudaGetSymbolAddress((void**)&Vhi,     g_Vhi);

    cudaFuncSetAttribute(gemm_hmma_kernel, cudaFuncAttributeMaxDynamicSharedMemorySize, GSMEM);
    cudaFuncSetAttribute(tau_hmma_kernel, cudaFuncAttributeMaxDynamicSharedMemorySize, TSMEM);
    cudaFuncSetAttribute(flash_hmma_kernel, cudaFuncAttributeMaxDynamicSharedMemorySize, FLASH2_SMEM);

    decomp_kernel<<<(T_ * DIM_ / 4 + 255) / 256, 256>>>(hidden, Ahi, Alo, T_ * DIM_ / 4);
    decomp1_kernel<<<(QKVD * DIM_ / 4 + 255) / 256, 256>>>(Wqkv, Whi, QKVD * DIM_ / 4);
    decomp1_kernel<<<(32 * QKVD / 4 + 255) / 256, 256>>>(tau_wq, Twhi, 32 * QKVD / 4);
    decomp1_kernel<<<(32 * QKVD / 4 + 255) / 256, 256>>>(tau_wv, Twhi + 32 * QKVD, 32 * QKVD / 4);
    gemm_hmma_kernel<<<dim3(QKVD / 128, T_ / 128), 256, GSMEM>>>(
        Ahi, Alo, Whi, bqkv, qkv, Ghi, Glo, QKVD, DIM_, DIM_);
    tau_hmma_kernel<<<dim3(T_ / 128, 8), 256, TSMEM>>>(Ghi, Glo, Twhi, taupart);
    prep_kernel<<<T_, 256>>>(qkv, positions, taupart, tau_alpha, Qhi, Qlo, Khi, Vhi);
    flash_hmma_kernel<<<dim3(T_ / 128, NH, 2), 256, FLASH2_SMEM>>>(
        Qhi, Qlo, Khi, Vhi, Opart, mpart, lpart);
    combine_kernel<<<T_, 256>>>(Opart, mpart, lpart, Ahi, Alo);
    decomp1_kernel<<<(DIM_ * DIM_ / 4 + 255) / 256, 256>>>(Wout, Whi, DIM_ * DIM_ / 4);
    gemm_hmma_kernel<<<dim3(DIM_ / 128, T_ / 128), 256, GSMEM>>>(
        Ahi, Alo, Whi, bout, out, nullptr, nullptr, DIM_, DIM_, DIM_);
}

// round 17
// speedup vs baseline: 1.8388x; 1.0936x over previous
#include <cuda_runtime.h>
#include <cuda_fp16.h>
#include <math.h>
#include <stdint.h>

#define T_ 2048
#define DIM_ 2048
#define NH 32
#define HD 64
#define QKVD 6144

// ---------------- scratch ----------------
__device__ float g_qkv[T_ * QKVD];
__device__ float g_taupart[8 * T_ * 64];
__device__ float g_Opart[2 * T_ * DIM_];
__device__ float g_mpart[2 * NH * T_];
__device__ float g_lpart[2 * NH * T_];
__device__ __half g_Ahi[T_ * DIM_];
__device__ __half g_Alo[T_ * DIM_];
__device__ __half g_Whi[QKVD * DIM_];
__device__ __half g_Ghi[T_ * QKVD];
__device__ __half g_Glo[T_ * QKVD];
__device__ __half g_Twhi[64 * QKVD];
__device__ __half g_Qhi[NH * T_ * HD];
__device__ __half g_Qlo[NH * T_ * HD];
__device__ __half g_Khi[NH * T_ * HD];
__device__ __half g_Vhi[NH * T_ * HD];

// ================= helpers =================
__device__ __forceinline__ uint32_t smem_u32(const void* p) {
    uint32_t a;
    asm("{ .reg .u64 t; cvta.to.shared.u64 t, %1; cvt.u32.u64 %0, t; }" : "=r"(a) : "l"(p));
    return a;
}
__device__ __forceinline__ void ldsm4(uint32_t* r, uint32_t addr) {
    asm volatile("ldmatrix.sync.aligned.m8n8.x4.shared.b16 {%0,%1,%2,%3}, [%4];"
        : "=r"(r[0]), "=r"(r[1]), "=r"(r[2]), "=r"(r[3]) : "r"(addr));
}
__device__ __forceinline__ void ldsm4t(uint32_t* r, uint32_t addr) {
    asm volatile("ldmatrix.sync.aligned.m8n8.x4.trans.shared.b16 {%0,%1,%2,%3}, [%4];"
        : "=r"(r[0]), "=r"(r[1]), "=r"(r[2]), "=r"(r[3]) : "r"(addr));
}
__device__ __forceinline__ void mma16816(float* d, const uint32_t* a, const uint32_t* b) {
    asm volatile("mma.sync.aligned.m16n8k16.row.col.f32.f16.f16.f32 "
        "{%0,%1,%2,%3}, {%4,%5,%6,%7}, {%8,%9}, {%0,%1,%2,%3};"
        : "+f"(d[0]), "+f"(d[1]), "+f"(d[2]), "+f"(d[3])
        : "r"(a[0]), "r"(a[1]), "r"(a[2]), "r"(a[3]), "r"(b[0]), "r"(b[1]));
}
__device__ __forceinline__ void cp_async16(uint32_t dst, const void* src) {
    asm volatile("cp.async.cg.shared.global [%0], [%1], 16;" :: "r"(dst), "l"(src) : "memory");
}
#define CP_COMMIT() asm volatile("cp.async.commit_group;" ::: "memory")
#define CP_WAIT(n)  asm volatile("cp.async.wait_group %0;" :: "n"(n) : "memory")

__device__ __forceinline__ uint32_t pack_h2(float lo, float hi) {
    __half2 t = __floats2half2_rn(lo, hi);
    return *reinterpret_cast<uint32_t*>(&t);
}
__device__ __forceinline__ float ex2(float x) {
    float y;
    asm("ex2.approx.f32 %0, %1;" : "=f"(y) : "f"(x));
    return y;
}

// ================= split-fp16 decomposition =================
__global__ __launch_bounds__(256)
void decomp_kernel(const float* __restrict__ in, __half* __restrict__ hi,
                   __half* __restrict__ lo, int n4) {
    int i = blockIdx.x * 256 + threadIdx.x;
    if (i >= n4) return;
    float4 v = ((const float4*)in)[i];
    __half h0 = __float2half_rn(v.x);
    __half h1 = __float2half_rn(v.y);
    __half h2 = __float2half_rn(v.z);
    __half h3 = __float2half_rn(v.w);
    ((__half2*)hi)[i * 2 + 0] = __halves2half2(h0, h1);
    ((__half2*)hi)[i * 2 + 1] = __halves2half2(h2, h3);
    ((__half2*)lo)[i * 2 + 0] = __floats2half2_rn(v.x - __half2float(h0), v.y - __half2float(h1));
    ((__half2*)lo)[i * 2 + 1] = __floats2half2_rn(v.z - __half2float(h2), v.w - __half2float(h3));
}

__global__ __launch_bounds__(256)
void decomp1_kernel(const float* __restrict__ in, __half* __restrict__ hi, int n4) {
    int i = blockIdx.x * 256 + threadIdx.x;
    if (i >= n4) return;
    float4 v = ((const float4*)in)[i];
    ((__half2*)hi)[i * 2 + 0] = __floats2half2_rn(v.x, v.y);
    ((__half2*)hi)[i * 2 + 1] = __floats2half2_rn(v.z, v.w);
}

// ================= HMMA fp16 GEMM, column-dependent term count =================
#define MAT_BYTES  (128 * 80)
#define STAGE_BYTES (3 * MAT_BYTES)
#define GSMEM (3 * STAGE_BYTES)

__global__ __launch_bounds__(256, 2)
void gemm_hmma_kernel(const __half* __restrict__ Ahi, const __half* __restrict__ Alo,
                      const __half* __restrict__ Bhi,
                      const float* __restrict__ bias, float* __restrict__ C,
                      __half* __restrict__ Ghi, __half* __restrict__ Glo,
                      int N, int K, int n_2term) {
    extern __shared__ char smem[];
    const uint32_t sbase = smem_u32(smem);
    const int tid = threadIdx.x;
    const int wid = tid >> 5;
    const int lane = tid & 31;
    const int wm = wid >> 2;
    const int wn = wid & 3;
    const int bx = blockIdx.x, by = blockIdx.y;
    const int nch = K / 32;
    const bool two_term = (bx * 128) < n_2term;

    float acc[4][4][4];
#pragma unroll
    for (int mt = 0; mt < 4; mt++)
#pragma unroll
        for (int nt = 0; nt < 4; nt++)
#pragma unroll
            for (int r = 0; r < 4; r++) acc[mt][nt][r] = 0.f;

    auto load_stage = [&](int ci) {
        if (ci < nch) {
            uint32_t st = sbase + (ci % 3) * STAGE_BYTES;
            int k0 = ci * 32;
#pragma unroll
            for (int i = 0; i < 6; i++) {
                int c = tid + i * 256;
                int pl = c / 512;
                int idx = c & 511;
                int row = idx >> 2, k4 = idx & 3;
                uint32_t so = (uint32_t)row * 80 + k4 * 16;
                if (pl == 0)
                    cp_async16(st + so, Ahi + (size_t)(by * 128 + row) * K + k0 + k4 * 8);
                else if (pl == 1) {
                    if (two_term)
                        cp_async16(st + MAT_BYTES + so, Alo + (size_t)(by * 128 + row) * K + k0 + k4 * 8);
                } else
                    cp_async16(st + 2 * MAT_BYTES + so, Bhi + (size_t)(bx * 128 + row) * K + k0 + k4 * 8);
            }
        }
        CP_COMMIT();
    };

    load_stage(0); load_stage(1);

    for (int ci = 0; ci < nch; ci++) {
        CP_WAIT(1);
        __syncthreads();

        uint32_t st = sbase + (ci % 3) * STAGE_BYTES;
        uint32_t aHi = st, aLo = st + MAT_BYTES, bHi = st + 2 * MAT_BYTES;
        const int g = lane >> 3;

#pragma unroll
        for (int ks = 0; ks < 2; ks++) {
            uint32_t ah[4][4], al[4][4];
#pragma unroll
            for (int mt = 0; mt < 4; mt++) {
                uint32_t aoff = (uint32_t)(wm * 64 + mt * 16 + (lane & 15)) * 80
                                + ks * 32 + (lane >> 4) * 16;
                ldsm4(ah[mt], aHi + aoff);
                if (two_term) ldsm4(al[mt], aLo + aoff);
            }
            uint32_t bh[2][4];
#pragma unroll
            for (int p = 0; p < 2; p++) {
                int row = wn * 32 + p * 16 + (g >> 1) * 8 + (lane & 7);
                uint32_t boff = (uint32_t)row * 80 + ks * 32 + (g & 1) * 16;
                ldsm4(bh[p], bHi + boff);
            }
#pragma unroll
            for (int mt = 0; mt < 4; mt++)
#pragma unroll
                for (int p = 0; p < 2; p++)
#pragma unroll
                    for (int pt = 0; pt < 2; pt++)
                        mma16816(acc[mt][p * 2 + pt], ah[mt], &bh[p][pt * 2]);
            if (two_term) {
#pragma unroll
                for (int mt = 0; mt < 4; mt++)
#pragma unroll
                    for (int p = 0; p < 2; p++)
#pragma unroll
                        for (int pt = 0; pt < 2; pt++)
                            mma16816(acc[mt][p * 2 + pt], al[mt], &bh[p][pt * 2]);
            }
        }
        __syncthreads();
        load_stage(ci + 2);
    }

    const bool do_gelu = (Ghi != nullptr);
#pragma unroll
    for (int mt = 0; mt < 4; mt++) {
        int r0 = by * 128 + wm * 64 + mt * 16 + (lane >> 2);
#pragma unroll
        for (int nt = 0; nt < 4; nt++) {
            int c0 = bx * 128 + wn * 32 + nt * 8 + (lane & 3) * 2;
            float b0 = bias[c0], b1 = bias[c0 + 1];
#pragma unroll
            for (int rr = 0; rr < 2; rr++) {
                int r = r0 + rr * 8;
                float v0 = acc[mt][nt][rr * 2 + 0] + b0;
                float v1 = acc[mt][nt][rr * 2 + 1] + b1;
                *(float2*)&C[(size_t)r * N + c0] = make_float2(v0, v1);
                if (do_gelu) {
                    float g0 = 0.5f * v0 * (1.0f + erff(v0 * 0.70710678118654752f));
                    float g1 = 0.5f * v1 * (1.0f + erff(v1 * 0.70710678118654752f));
                    float h0 = __half2float(__float2half_rn(g0));
                    float h1 = __half2float(__float2half_rn(g1));
                    *(uint32_t*)&Ghi[(size_t)r * N + c0] = pack_h2(h0, h1);
                    *(uint32_t*)&Glo[(size_t)r * N + c0] = pack_h2(g0 - h0, g1 - h1);
                }
            }
        }
    }
}

// ================= tau: HMMA fp16 2-term split-K GEMM =================
#define TAPL 10240
#define TBPL 5120
#define TSTAGE (2 * TAPL + TBPL)
#define TSMEM (4 * TSTAGE)

__global__ __launch_bounds__(256, 2)
void tau_hmma_kernel(const __half* __restrict__ Ghi, const __half* __restrict__ Glo,
                     const __half* __restrict__ Twhi,
                     float* __restrict__ part) {
    extern __shared__ char smem[];
    const uint32_t sbase = smem_u32(smem);
    const int tid = threadIdx.x;
    const int wid = tid >> 5;
    const int lane = tid & 31;
    const int wm = wid >> 1;
    const int wn = wid & 1;
    const int t0 = blockIdx.x * 128;
    const int kbase = blockIdx.y * 768;

    float acc[2][4][4];
#pragma unroll
    for (int mt = 0; mt < 2; mt++)
#pragma unroll
        for (int nt = 0; nt < 4; nt++)
#pragma unroll
            for (int r = 0; r < 4; r++) acc[mt][nt][r] = 0.f;

    auto load_stage = [&](int ci) {
        if (ci < 24) {
            uint32_t st = sbase + (ci & 3) * TSTAGE;
            int k0 = kbase + ci * 32;
#pragma unroll
            for (int i = 0; i < 5; i++) {
                int c = tid + i * 256;
                if (c < 1024) {
                    int pl = c >> 9, idx = c & 511;
                    int r = idx >> 2, k4 = idx & 3;
                    cp_async16(st + pl * TAPL + (uint32_t)r * 80 + k4 * 16,
                               (pl ? Glo : Ghi) + (size_t)(t0 + r) * QKVD + k0 + k4 * 8);
                } else {
                    int c2 = c - 1024;
                    int r = c2 >> 2, k4 = c2 & 3;
                    cp_async16(st + 2 * TAPL + (uint32_t)r * 80 + k4 * 16,
                               Twhi + (size_t)r * QKVD + k0 + k4 * 8);
                }
            }
        }
        CP_COMMIT();
    };

    load_stage(0); load_stage(1); load_stage(2);

    for (int ci = 0; ci < 24; ci++) {
        CP_WAIT(2);
        __syncthreads();
        load_stage(ci + 3);

        uint32_t st = sbase + (ci & 3) * TSTAGE;
        const int g = lane >> 3;
#pragma unroll
        for (int ks = 0; ks < 2; ks++) {
            uint32_t ah[2][4], al[2][4];
#pragma unroll
            for (int mt = 0; mt < 2; mt++) {
                uint32_t aoff = (uint32_t)(wm * 32 + mt * 16 + (lane & 15)) * 80
                                + ks * 32 + (lane >> 4) * 16;
                ldsm4(ah[mt], st + aoff);
                ldsm4(al[mt], st + TAPL + aoff);
            }
            uint32_t bh[2][4];
#pragma unroll
            for (int p = 0; p < 2; p++) {
                int row = wn * 32 + p * 16 + (g >> 1) * 8 + (lane & 7);
                uint32_t boff = (uint32_t)row * 80 + ks * 32 + (g & 1) * 16;
                ldsm4(bh[p], st + 2 * TAPL + boff);
            }
#pragma unroll
            for (int mt = 0; mt < 2; mt++)
#pragma unroll
                for (int p = 0; p < 2; p++)
#pragma unroll
                    for (int pt = 0; pt < 2; pt++)
                        mma16816(acc[mt][p * 2 + pt], ah[mt], &bh[p][pt * 2]);
#pragma unroll
            for (int mt = 0; mt < 2; mt++)
#pragma unroll
                for (int p = 0; p < 2; p++)
#pragma unroll
                    for (int pt = 0; pt < 2; pt++)
                        mma16816(acc[mt][p * 2 + pt], al[mt], &bh[p][pt * 2]);
        }
    }

    float* pb = part + (size_t)blockIdx.y * T_ * 64;
#pragma unroll
    for (int mt = 0; mt < 2; mt++) {
        int r0 = t0 + wm * 32 + mt * 16 + (lane >> 2);
#pragma unroll
        for (int nt = 0; nt < 4; nt++) {
            int c0 = wn * 32 + nt * 8 + (lane & 3) * 2;
            *(float2*)&pb[(size_t)r0 * 64 + c0]       = make_float2(acc[mt][nt][0], acc[mt][nt][1]);
            *(float2*)&pb[(size_t)(r0 + 8) * 64 + c0] = make_float2(acc[mt][nt][2], acc[mt][nt][3]);
        }
    }
}

// ================= prep (with fused tau finish, fast sincos) =================
#define QSCALE 0.18033688011112042f    // 0.125 * log2(e)

__global__ __launch_bounds__(256)
void prep_kernel(const float* __restrict__ qkv, const int* __restrict__ positions,
                 const float* __restrict__ part, const float* __restrict__ alpha,
                 __half* __restrict__ Qhi, __half* __restrict__ Qlo,
                 __half* __restrict__ Khi, __half* __restrict__ Vhi) {
    const int t = blockIdx.x;
    const float p = (float)positions[t];
    const float* row = qkv + (size_t)t * QKVD;

    __shared__ float stau[64];
    if (threadIdx.x < 64) {
        int o = threadIdx.x;
        float s = 0.f;
#pragma unroll
        for (int ks = 0; ks < 8; ks++) s += part[(size_t)ks * T_ * 64 + t * 64 + o];
        int hh = o & 31;
        float pl = logf(fmaxf(p + 1.0f, 1e-6f));
        float tp = 0.5f + 1.0f / (1.0f + expf(-alpha[hh] * pl));
        stau[o] = tanhf(s) + tp;
    }
    __syncthreads();

    for (int e = threadIdx.x; e < DIM_; e += 256) {
        int h = e >> 6;
        int d = e & 63;
        float tq = stau[h];
        float tv = stau[32 + h];

        float qo = row[e] * tq;
        float ko = row[DIM_ + e];
        float vo = row[2 * DIM_ + e] * tv;

        if (d < 32) {
            int i = (d < 16) ? d : (d - 16);
            float ang = p * exp2f(-(float)i * 1.2457230355827609f);
            float s, c;
            __sincosf(ang, &s, &c);
            if (d < 16) {
                float q2 = row[e + 16] * tq;
                float k2 = row[DIM_ + e + 16];
                qo = qo * c - q2 * s;
                ko = ko * c - k2 * s;
            } else {
                float q1 = row[e - 16] * tq;
                float k1 = row[DIM_ + e - 16];
                qo = qo * c + q1 * s;
                ko = ko * c + k1 * s;
            }
        }
        qo *= QSCALE;
        size_t o = (size_t)h * T_ * HD + (size_t)t * HD + d;
        __half qh = __float2half_rn(qo);
        Qhi[o] = qh;
        Qlo[o] = __float2half_rn(qo - __half2float(qh));
        Khi[o] = __float2half_rn(ko);
        Vhi[o] = __float2half_rn(vo);
    }
}

// ================= HMMA fp16 flash attention, split-KV =================
#define FROW 144
#define FQL_OFF (128 * FROW)
#define FSTG0   (2 * 128 * FROW)
#define FSTG_BYTES (2 * 64 * FROW)
#define FKH 0
#define FVH (64 * FROW)
#define FLASH2_SMEM (FSTG0 + 4 * FSTG_BYTES)

__global__ __launch_bounds__(256, 2)
void flash_hmma_kernel(const __half* __restrict__ Qhi, const __half* __restrict__ Qlo,
                       const __half* __restrict__ Khi, const __half* __restrict__ Vhi,
                       float* __restrict__ Opart, float* __restrict__ mpart,
                       float* __restrict__ lpart) {
    extern __shared__ char smem[];
    const uint32_t sb = smem_u32(smem);
    const int tid = threadIdx.x;
    const int wid = tid >> 5;
    const int lane = tid & 31;
    const int h = blockIdx.y;
    const int z = blockIdx.z;
    const int qt = (int)gridDim.x - 1 - (int)blockIdx.x;
    const int q0 = qt * 128;
    const size_t hb = (size_t)h * T_ * HD;
    const int kbeg = z ? (qt + 1) : 0;
    const int kend = z ? (2 * qt + 2) : (qt + 1);

#pragma unroll
    for (int i = 0; i < 8; i++) {
        int c = tid + i * 256;
        int pl = c >> 10;
        int r = (c >> 3) & 127;
        int k8 = c & 7;
        const __half* src = (pl ? Qlo : Qhi) + hb + (size_t)(q0 + r) * HD + k8 * 8;
        cp_async16(sb + pl * FQL_OFF + (uint32_t)r * FROW + k8 * 16, src);
    }
    CP_COMMIT();

    auto load_kv = [&](int kt) {
        if (kt < kend) {
            uint32_t stg = sb + FSTG0 + (kt & 3) * FSTG_BYTES;
#pragma unroll
            for (int i = 0; i < 4; i++) {
                int c = tid + i * 256;
                int pl = c >> 9;
                int r = (c >> 3) & 63;
                int k8 = c & 7;
                const __half* base = pl ? Vhi : Khi;
                cp_async16(stg + pl * (64 * FROW) + (uint32_t)r * FROW + k8 * 16,
                           base + hb + (size_t)(kt * 64 + r) * HD + k8 * 8);
            }
        }
        CP_COMMIT();
    };
    load_kv(kbeg); load_kv(kbeg + 1); load_kv(kbeg + 2);

    CP_WAIT(3);
    __syncthreads();

    const uint32_t qbase = sb + (uint32_t)(wid * 16 + (lane & 15)) * FROW + (lane >> 4) * 16;

    float m0 = -1e30f, m1 = -1e30f, l0 = 0.f, l1 = 0.f;
    float O[8][4];
#pragma unroll
    for (int nf = 0; nf < 8; nf++)
#pragma unroll
        for (int c = 0; c < 4; c++) O[nf][c] = 0.f;

    for (int kt = kbeg; kt < kend; kt++) {
        CP_WAIT(2);
        __syncthreads();
        load_kv(kt + 3);

        const bool active = (kt * 64 <= q0 + wid * 16 + 15);
        const uint32_t stg = sb + FSTG0 + (kt & 3) * FSTG_BYTES;

        if (active) {
            float S[8][4];
#pragma unroll
            for (int nf = 0; nf < 8; nf++)
#pragma unroll
                for (int c = 0; c < 4; c++) S[nf][c] = 0.f;

#pragma unroll
            for (int ks = 0; ks < 4; ks++) {
                uint32_t aqh[4], aql[4];
                ldsm4(aqh, qbase + ks * 32);
                ldsm4(aql, qbase + ks * 32 + FQL_OFF);
#pragma unroll
                for (int kg = 0; kg < 2; kg++) {
                    uint32_t bh[2][4];
#pragma unroll
                    for (int kp = 0; kp < 2; kp++) {
                        uint32_t ka = stg
                                      + (uint32_t)((kg * 2 + kp) * 16 + ((lane >> 4) << 3) + (lane & 7)) * FROW
                                      + ks * 32 + ((lane >> 3) & 1) * 16;
                        ldsm4(bh[kp], ka + FKH);
                    }
#pragma unroll
                    for (int kp = 0; kp < 2; kp++)
#pragma unroll
                        for (int half = 0; half < 2; half++)
                            mma16816(S[(kg * 2 + kp) * 2 + half], aqh, &bh[kp][half * 2]);
#pragma unroll
                    for (int kp = 0; kp < 2; kp++)
#pragma unroll
                        for (int half = 0; half < 2; half++)
                            mma16816(S[(kg * 2 + kp) * 2 + half], aql, &bh[kp][half * 2]);
                }
            }

            if (kt >= 2 * qt) {
                int rbase = q0 + wid * 16 + (lane >> 2);
                int cbase = kt * 64 + (lane & 3) * 2;
#pragma unroll
                for (int nf = 0; nf < 8; nf++)
#pragma unroll
                    for (int c = 0; c < 4; c++) {
                        int row = rbase + ((c >> 1) & 1) * 8;
                        int col = cbase + nf * 8 + (c & 1);
                        if (col > row) S[nf][c] = -1e30f;
                    }
            }

#pragma unroll
            for (int j = 0; j < 2; j++) {
                float& mj = j ? m1 : m0;
                float& lj = j ? l1 : l0;
                float rm = -1e30f;
#pragma unroll
                for (int nf = 0; nf < 8; nf++) {
                    rm = fmaxf(rm, S[nf][2 * j]);
                    rm = fmaxf(rm, S[nf][2 * j + 1]);
                }
                rm = fmaxf(rm, __shfl_xor_sync(0xffffffffu, rm, 1));
                rm = fmaxf(rm, __shfl_xor_sync(0xffffffffu, rm, 2));
                float mn = fmaxf(mj, rm);
                float alpha = ex2(mj - mn);
                float rs = 0.f;
#pragma unroll
                for (int nf = 0; nf < 8; nf++) {
                    float p0 = ex2(S[nf][2 * j] - mn);
                    float p1 = ex2(S[nf][2 * j + 1] - mn);
                    S[nf][2 * j] = p0; S[nf][2 * j + 1] = p1;
                    rs += p0 + p1;
                }
                lj = lj * alpha + rs;
                mj = mn;
#pragma unroll
                for (int nf = 0; nf < 8; nf++) {
                    O[nf][2 * j] *= alpha;
                    O[nf][2 * j + 1] *= alpha;
                }
            }

#pragma unroll
            for (int ks = 0; ks < 4; ks++) {
                uint32_t ah[4], al[4];
#pragma unroll
                for (int q = 0; q < 4; q++) {
                    int sf = 2 * ks + (q >> 1);
                    int c0 = (q & 1) * 2;
                    float p0 = S[sf][c0], p1 = S[sf][c0 + 1];
                    float h0 = __half2float(__float2half_rn(p0));
                    float h1 = __half2float(__float2half_rn(p1));
                    ah[q] = pack_h2(h0, h1);
                    al[q] = pack_h2(p0 - h0, p1 - h1);
                }
#pragma unroll
                for (int dg = 0; dg < 2; dg++) {
                    uint32_t vh[2][4];
#pragma unroll
                    for (int dp = 0; dp < 2; dp++) {
                        uint32_t va = stg + (uint32_t)(ks * 16 + ((lane >> 3) & 1) * 8 + (lane & 7)) * FROW
                                      + (dg * 2 + dp) * 32 + (lane >> 4) * 16;
                        ldsm4t(vh[dp], va + FVH);
                    }
#pragma unroll
                    for (int dp = 0; dp < 2; dp++) {
                        int od = (dg * 2 + dp) * 2;
                        mma16816(O[od],     ah, &vh[dp][0]);
                        mma16816(O[od + 1], ah, &vh[dp][2]);
                    }
#pragma unroll
                    for (int dp = 0; dp < 2; dp++) {
                        int od = (dg * 2 + dp) * 2;
                        mma16816(O[od],     al, &vh[dp][0]);
                        mma16816(O[od + 1], al, &vh[dp][2]);
                    }
                }
            }
        }
    }

    l0 += __shfl_xor_sync(0xffffffffu, l0, 1);
    l0 += __shfl_xor_sync(0xffffffffu, l0, 2);
    l1 += __shfl_xor_sync(0xffffffffu, l1, 1);
    l1 += __shfl_xor_sync(0xffffffffu, l1, 2);

    float* Oz = Opart + (size_t)z * T_ * DIM_;
    int r0 = q0 + wid * 16 + (lane >> 2);
#pragma unroll
    for (int nf = 0; nf < 8; nf++)
#pragma unroll
        for (int j = 0; j < 2; j++) {
            int t = r0 + j * 8;
            int col = h * 64 + nf * 8 + (lane & 3) * 2;
            *(float2*)&Oz[(size_t)t * DIM_ + col] =
                make_float2(O[nf][2 * j], O[nf][2 * j + 1]);
        }
    if ((lane & 3) == 0) {
        size_t mb = (size_t)z * NH * T_ + (size_t)h * T_;
        mpart[mb + r0]     = m0;
        lpart[mb + r0]     = l0;
        mpart[mb + r0 + 8] = m1;
        lpart[mb + r0 + 8] = l1;
    }
}

// ================= combine: merge splits (hi plane only — gemm2 is 1-term) =================
__global__ __launch_bounds__(256)
void combine_kernel(const float* __restrict__ Opart, const float* __restrict__ mpart,
                    const float* __restrict__ lpart,
                    __half* __restrict__ Ahi) {
    const int t = blockIdx.x;
    const int tid = threadIdx.x;
    const int h = tid >> 3;
    const int c0 = tid * 8;

    size_t mb0 = (size_t)h * T_ + t;
    size_t mb1 = (size_t)NH * T_ + mb0;
    float m0 = mpart[mb0], l0 = lpart[mb0];
    float m1 = mpart[mb1], l1 = lpart[mb1];
    float m = fmaxf(m0, m1);
    float e0 = ex2(m0 - m), e1 = ex2(m1 - m);
    float L = l0 * e0 + l1 * e1;
    float w0 = e0 / L, w1 = e1 / L;

    const float* O0 = Opart + (size_t)t * DIM_ + c0;
    const float* O1 = Opart + (size_t)T_ * DIM_ + (size_t)t * DIM_ + c0;
#pragma unroll
    for (int i = 0; i < 8; i += 2) {
        float v0 = O0[i]     * w0 + O1[i]     * w1;
        float v1 = O0[i + 1] * w0 + O1[i + 1] * w1;
        *(uint32_t*)&Ahi[(size_t)t * DIM_ + c0 + i] = pack_h2(v0, v1);
    }
}

// ================= host launch =================
extern "C" void kernel_launch(void* const* d_in, const int* in_sizes, int n_in,
                              void* d_out, int out_size) {
    const int*   positions = (const int*)d_in[0];
    const float* hidden    = (const float*)d_in[1];
    const float* Wqkv      = (const float*)d_in[2];
    const float* bqkv      = (const float*)d_in[3];
    const float* Wout      = (const float*)d_in[4];
    const float* bout      = (const float*)d_in[5];
    const float* tau_alpha = (const float*)d_in[6];
    const float* tau_wq    = (const float*)d_in[7];
    const float* tau_wv    = (const float*)d_in[8];
    float* out = (float*)d_out;

    float *qkv, *taupart, *Opart, *mpart, *lpart;
    __half *Ahi, *Alo, *Whi, *Ghi, *Glo, *Twhi, *Qhi, *Qlo, *Khi, *Vhi;
    cudaGetSymbolAddress((void**)&qkv,     g_qkv);
    cudaGetSymbolAddress((void**)&taupart, g_taupart);
    cudaGetSymbolAddress((void**)&Opart,   g_Opart);
    cudaGetSymbolAddress((void**)&mpart,   g_mpart);
    cudaGetSymbolAddress((void**)&lpart,   g_lpart);
    cudaGetSymbolAddress((void**)&Ahi,     g_Ahi);
    cudaGetSymbolAddress((void**)&Alo,     g_Alo);
    cudaGetSymbolAddress((void**)&Whi,     g_Whi);
    cudaGetSymbolAddress((void**)&Ghi,     g_Ghi);
    cudaGetSymbolAddress((void**)&Glo,     g_Glo);
    cudaGetSymbolAddress((void**)&Twhi,    g_Twhi);
    cudaGetSymbolAddress((void**)&Qhi,     g_Qhi);
    cudaGetSymbolAddress((void**)&Qlo,     g_Qlo);
    cudaGetSymbolAddress((void**)&Khi,     g_Khi);
    cudaGetSymbolAddress((void**)&Vhi,     g_Vhi);

    cudaFuncSetAttribute(gemm_hmma_kernel, cudaFuncAttributeMaxDynamicSharedMemorySize, GSMEM);
    cudaFuncSetAttribute(tau_hmma_kernel, cudaFuncAttributeMaxDynamicSharedMemorySize, TSMEM);
    cudaFuncSetAttribute(flash_hmma_kernel, cudaFuncAttributeMaxDynamicSharedMemorySize, FLASH2_SMEM);

    decomp_kernel<<<(T_ * DIM_ / 4 + 255) / 256, 256>>>(hidden, Ahi, Alo, T_ * DIM_ / 4);
    decomp1_kernel<<<(QKVD * DIM_ / 4 + 255) / 256, 256>>>(Wqkv, Whi, QKVD * DIM_ / 4);
    decomp1_kernel<<<(32 * QKVD / 4 + 255) / 256, 256>>>(tau_wq, Twhi, 32 * QKVD / 4);
    decomp1_kernel<<<(32 * QKVD / 4 + 255) / 256, 256>>>(tau_wv, Twhi + 32 * QKVD, 32 * QKVD / 4);
    // gemm1: q columns 2-term, k/v columns 1-term
    gemm_hmma_kernel<<<dim3(QKVD / 128, T_ / 128), 256, GSMEM>>>(
        Ahi, Alo, Whi, bqkv, qkv, Ghi, Glo, QKVD, DIM_, DIM_);
    tau_hmma_kernel<<<dim3(T_ / 128, 8), 256, TSMEM>>>(Ghi, Glo, Twhi, taupart);
    prep_kernel<<<T_, 256>>>(qkv, positions, taupart, tau_alpha, Qhi, Qlo, Khi, Vhi);
    flash_hmma_kernel<<<dim3(T_ / 128, NH, 2), 256, FLASH2_SMEM>>>(
        Qhi, Qlo, Khi, Vhi, Opart, mpart, lpart);
    combine_kernel<<<T_, 256>>>(Opart, mpart, lpart, Ahi);
    decomp1_kernel<<<(DIM_ * DIM_ / 4 + 255) / 256, 256>>>(Wout, Whi, DIM_ * DIM_ / 4);
    // gemm2: 1-term (attn_hi only)
    gemm_hmma_kernel<<<dim3(DIM_ / 128, T_ / 128), 256, GSMEM>>>(
        Ahi, Alo, Whi, bout, out, nullptr, nullptr, DIM_, DIM_, 0);
}